// round 2
// baseline (speedup 1.0000x reference)
#include <cuda_runtime.h>
#include <math.h>

#define N_ENTC 20000
#define NRELC  460
#define HC     128
#define NEC    400000
#define NBC    1024
#define NTC    8
#define H3C    384
#define SLOPE  0.22916666666666666f

// ---------------- scratch layout (single __device__ blob) ----------------
constexpr size_t SEH = (size_t)N_ENTC * HC;
constexpr size_t O_AGG   = 0;
constexpr size_t O_TMP   = O_AGG + SEH;
constexpr size_t O_PRE   = O_TMP + SEH;
constexpr size_t O_ALN   = O_PRE + SEH;
constexpr size_t O_MAP1  = O_ALN + SEH;
constexpr size_t O_MREL  = O_MAP1 + (size_t)NRELC * 256;
constexpr size_t O_QREL  = O_MREL + (size_t)NRELC * HC;
constexpr size_t O_QA    = O_QREL + (size_t)NBC * HC;
constexpr size_t O_AMAT  = O_QA + (size_t)NBC * HC;
constexpr size_t O_ATTN  = O_AMAT + (size_t)NBC * NRELC;
constexpr size_t O_RPATH = O_ATTN + (size_t)NTC * NBC * NRELC;
constexpr size_t O_GIALL = O_RPATH + (size_t)NTC * NBC * HC;
constexpr size_t O_GHB   = O_GIALL + (size_t)NTC * NBC * H3C;
constexpr size_t O_GRUH  = O_GHB + (size_t)NBC * H3C;
constexpr size_t O_P1    = O_GRUH + (size_t)NBC * HC;
constexpr size_t O_PRED  = O_P1 + (size_t)NBC * HC;
constexpr size_t O_GH2   = O_PRED + (size_t)NBC * HC;
constexpr size_t O_SUB   = O_GH2 + (size_t)NBC * HC;
constexpr size_t O_SUBA  = O_SUB + (size_t)NBC * HC;
constexpr size_t O_SVEC  = O_SUBA + (size_t)NBC * HC;
constexpr size_t O_ACC_  = O_SVEC + (size_t)NBC * HC;
constexpr size_t O_ACC   = (O_ACC_ + 1) & ~(size_t)1;   // 8-byte aligned
constexpr size_t O_INT   = O_ACC + 8;                    // 3 doubles + pad
constexpr size_t N_INTS  = (size_t)N_ENTC + (N_ENTC + 1) + N_ENTC + NEC + N_ENTC + 8;
constexpr size_t TOTALF  = O_INT + N_INTS;

__device__ __align__(16) float d_buf[TOTALF];

// ---------------- reductions ----------------
__device__ __forceinline__ float blockReduceSum(float v) {
    __shared__ float sh[32];
    int tid = threadIdx.x;
    __syncthreads();
    #pragma unroll
    for (int o = 16; o > 0; o >>= 1) v += __shfl_xor_sync(0xffffffffu, v, o);
    if ((tid & 31) == 0) sh[tid >> 5] = v;
    __syncthreads();
    float r = 0.f;
    if (tid < 32) {
        int nw = (blockDim.x + 31) >> 5;
        r = (tid < nw) ? sh[tid] : 0.f;
        #pragma unroll
        for (int o = 16; o > 0; o >>= 1) r += __shfl_xor_sync(0xffffffffu, r, o);
    }
    return r;
}
__device__ __forceinline__ float blockReduceMax(float v) {
    __shared__ float sh[32];
    int tid = threadIdx.x;
    __syncthreads();
    #pragma unroll
    for (int o = 16; o > 0; o >>= 1) v = fmaxf(v, __shfl_xor_sync(0xffffffffu, v, o));
    if ((tid & 31) == 0) sh[tid >> 5] = v;
    __syncthreads();
    float r = -3.402823e38f;
    if (tid < 32) {
        int nw = (blockDim.x + 31) >> 5;
        r = (tid < nw) ? sh[tid] : -3.402823e38f;
        #pragma unroll
        for (int o = 16; o > 0; o >>= 1) r = fmaxf(r, __shfl_xor_sync(0xffffffffu, r, o));
    }
    return r;
}

// ---------------- small kernels ----------------
__global__ void k_init(int* deg, int* cursor, int* nzero, double* acc, float* gruh) {
    int i = blockIdx.x * blockDim.x + threadIdx.x;
    if (i < N_ENTC) { deg[i] = 0; cursor[i] = 0; }
    if (i < NBC * HC) gruh[i] = 0.f;
    if (i == 0) { nzero[0] = 0; acc[0] = 0.0; acc[1] = 0.0; acc[2] = 0.0; }
}

__global__ void k_count(const int* __restrict__ dst, int* deg) {
    int e = blockIdx.x * blockDim.x + threadIdx.x;
    if (e < NEC) atomicAdd(&deg[dst[e]], 1);
}

__global__ void k_scan(const int* __restrict__ deg, int* rowptr) {
    __shared__ int s[1024];
    __shared__ int carry;
    int tid = threadIdx.x;
    if (tid == 0) carry = 0;
    __syncthreads();
    for (int base = 0; base < N_ENTC; base += 1024) {
        int i = base + tid;
        int v = (i < N_ENTC) ? deg[i] : 0;
        s[tid] = v;
        __syncthreads();
        for (int off = 1; off < 1024; off <<= 1) {
            int t = (tid >= off) ? s[tid - off] : 0;
            __syncthreads();
            s[tid] += t;
            __syncthreads();
        }
        int incl = s[tid];
        if (i < N_ENTC) rowptr[i] = carry + incl - v;
        __syncthreads();
        if (tid == 1023) carry += incl;
        __syncthreads();
    }
    if (tid == 0) rowptr[N_ENTC] = carry;
}

__global__ void k_fill(const int* __restrict__ dst, const int* __restrict__ rowptr,
                       int* cursor, int* csr) {
    int e = blockIdx.x * blockDim.x + threadIdx.x;
    if (e < NEC) {
        int d = dst[e];
        int p = atomicAdd(&cursor[d], 1);
        csr[rowptr[d] + p] = e;
    }
}

__global__ void k_aggregate(const float* __restrict__ ent, const float* __restrict__ rel,
                            const int* __restrict__ src, const int* __restrict__ typ,
                            const int* __restrict__ rowptr, const int* __restrict__ csr,
                            float* __restrict__ agg, int* zerolist, int* nzero) {
    int node = blockIdx.x;
    int c = threadIdx.x;  // 128
    __shared__ int s_src[512];
    __shared__ int s_typ[512];
    int beg = rowptr[node], end = rowptr[node + 1];
    int deg = end - beg;
    float acc = 0.f;
    for (int base = beg; base < end; base += 512) {
        int cnt = min(512, end - base);
        for (int i = c; i < cnt; i += 128) {
            int e = csr[base + i];
            s_src[i] = src[e] * HC;
            s_typ[i] = typ[e] * HC;
        }
        __syncthreads();
        #pragma unroll 4
        for (int i = 0; i < cnt; i++)
            acc += ent[s_src[i] + c] + rel[s_typ[i] + c];
        __syncthreads();
    }
    agg[node * HC + c] = (deg > 0) ? acc * (1.0f / (float)deg) : 0.f;
    if (c == 0 && deg == 0) {
        int p = atomicAdd(nzero, 1);
        zerolist[p] = node;
    }
}

// ---------------- generic tiled GEMM: C = act(alpha*(A*B + bias) + beta*D) ----------------
template <bool TRANSB, int ACT>
__global__ __launch_bounds__(256)
void k_gemm(const float* __restrict__ A, const float* __restrict__ Bm,
            const float* __restrict__ bias, const float* __restrict__ Dres,
            float* __restrict__ C, int M, int N, int K, float alpha, float beta) {
    const int BM = 64, BN = 128, BK = 16, TM = 8, TN = 4;
    __shared__ float As[BK][BM + 1];
    __shared__ float Bs[BK][BN + 1];
    int brow = blockIdx.y * BM, bcol = blockIdx.x * BN;
    int tid = threadIdx.x, lane = tid & 31, wrow = (tid >> 5) * TM;
    float acc[TM][TN] = {};
    for (int k0 = 0; k0 < K; k0 += BK) {
        for (int i = tid; i < BM * BK; i += 256) {
            int r = i >> 4, cc = i & 15;
            int gr = brow + r, gc = k0 + cc;
            As[cc][r] = (gr < M && gc < K) ? A[(size_t)gr * K + gc] : 0.f;
        }
        if (TRANSB) {
            for (int i = tid; i < BN * BK; i += 256) {
                int n = i >> 4, kk = i & 15;
                int gn = bcol + n, gk = k0 + kk;
                Bs[kk][n] = (gn < N && gk < K) ? Bm[(size_t)gn * K + gk] : 0.f;
            }
        } else {
            for (int i = tid; i < BK * BN; i += 256) {
                int kk = i >> 7, n = i & 127;
                int gk = k0 + kk, gn = bcol + n;
                Bs[kk][n] = (gk < K && gn < N) ? Bm[(size_t)gk * N + gn] : 0.f;
            }
        }
        __syncthreads();
        #pragma unroll
        for (int k = 0; k < BK; k++) {
            float ra[TM], rb[TN];
            #pragma unroll
            for (int i = 0; i < TM; i++) ra[i] = As[k][wrow + i];
            #pragma unroll
            for (int j = 0; j < TN; j++) rb[j] = Bs[k][lane + 32 * j];
            #pragma unroll
            for (int i = 0; i < TM; i++)
                #pragma unroll
                for (int j = 0; j < TN; j++) acc[i][j] = fmaf(ra[i], rb[j], acc[i][j]);
        }
        __syncthreads();
    }
    #pragma unroll
    for (int i = 0; i < TM; i++) {
        int row = brow + wrow + i;
        if (row >= M) continue;
        #pragma unroll
        for (int j = 0; j < TN; j++) {
            int col = bcol + lane + 32 * j;
            if (col >= N) continue;
            float v = acc[i][j];
            if (bias) v += bias[col];
            v *= alpha;
            if (Dres) v += beta * Dres[(size_t)row * N + col];
            if (ACT == 1) v = (v >= 0.f) ? v : v * SLOPE;
            C[(size_t)row * N + col] = v;
        }
    }
}

__global__ void k_fixzero(const float* __restrict__ ent, const float* __restrict__ Wev,
                          float* __restrict__ pre, const int* __restrict__ zerolist,
                          const int* __restrict__ nzero) {
    __shared__ float hrow[HC];
    int nz = nzero[0];
    int j = threadIdx.x;
    for (int zi = blockIdx.x; zi < nz; zi += gridDim.x) {
        int node = zerolist[zi];
        hrow[j] = ent[node * HC + j];
        __syncthreads();
        float s = 0.f;
        #pragma unroll 8
        for (int k = 0; k < HC; k++) s = fmaf(hrow[k], Wev[k * HC + j], s);
        s = (s >= 0.f) ? s : s * SLOPE;
        pre[node * HC + j] = s;
        __syncthreads();
    }
}

__global__ void k_gather(const float* __restrict__ mat, const int* __restrict__ trip,
                         int col, float* __restrict__ out) {
    int b = blockIdx.x, j = threadIdx.x;
    out[b * HC + j] = mat[(size_t)trip[b * 3 + col] * HC + j];
}

// masked softmax for all (t,b) rows at once
__global__ void k_attn(const float* __restrict__ part, const float* __restrict__ Amat,
                       float* __restrict__ attn_all) {
    int tb = blockIdx.x;
    int t = tb >> 10, b = tb & 1023;
    int tid = threadIdx.x;  // 512
    float x = -3.402823e38f;
    if (tid < NRELC) {
        float cur = part[(size_t)b * (NTC * NRELC) + t * NRELC + tid];
        float a = Amat[b * NRELC + tid];
        float val = cur * a;
        x = (val == 0.f) ? -1e9f : val;
    }
    float m = blockReduceMax(x);
    __shared__ float sm_m, sm_s;
    if (tid == 0) sm_m = m;
    __syncthreads();
    m = sm_m;
    float e = (tid < NRELC) ? __expf(x - m) : 0.f;
    float s = blockReduceSum(e);
    if (tid == 0) sm_s = s;
    __syncthreads();
    s = sm_s;
    if (tid < NRELC) attn_all[(size_t)tb * NRELC + tid] = e / s;
}

__global__ void k_gru(const float* __restrict__ gi, const float* __restrict__ gh,
                      const float* __restrict__ hin, float* __restrict__ hout) {
    int idx = blockIdx.x * blockDim.x + threadIdx.x;
    if (idx >= NBC * HC) return;
    int b = idx >> 7, j = idx & 127;
    float ir = gi[b * H3C + j], iz = gi[b * H3C + HC + j], inn = gi[b * H3C + 2 * HC + j];
    float hr = gh[b * H3C + j], hz = gh[b * H3C + HC + j], hn = gh[b * H3C + 2 * HC + j];
    float r = 1.f / (1.f + expf(-(ir + hr)));
    float z = 1.f / (1.f + expf(-(iz + hz)));
    float n = tanhf(inn + r * hn);
    hout[idx] = (1.f - z) * n + z * hin[idx];
}

__global__ void k_mul(const float* __restrict__ a, const float* __restrict__ b,
                      float* __restrict__ c, int n) {
    int i = blockIdx.x * blockDim.x + threadIdx.x;
    if (i < n) c[i] = a[i] * b[i];
}

__global__ void k_match(const float* __restrict__ pred, const float* __restrict__ gruh,
                        double* acc) {
    float s = 0.f;
    for (int i = blockIdx.x * blockDim.x + threadIdx.x; i < NBC * HC;
         i += gridDim.x * blockDim.x) {
        float d = pred[i] - gruh[i];
        s += d * d;
    }
    float b = blockReduceSum(s);
    if (threadIdx.x == 0) atomicAdd(&acc[2], (double)b);
}

// score = sigmoid(svec @ aligned^T); fused softplus/loss accumulation
__global__ __launch_bounds__(256)
void k_score(const float* __restrict__ A, const float* __restrict__ Bm,
             const int* __restrict__ trip, float* __restrict__ out, double* acc) {
    const int BM = 64, BN = 128, BK = 16, TM = 8, TN = 4;
    __shared__ float As[BK][BM + 1];
    __shared__ float Bs[BK][BN + 1];
    int brow = blockIdx.y * BM, bcol = blockIdx.x * BN;
    int tid = threadIdx.x, lane = tid & 31, wrow = (tid >> 5) * TM;
    float c[TM][TN] = {};
    for (int k0 = 0; k0 < HC; k0 += BK) {
        for (int i = tid; i < BM * BK; i += 256) {
            int r = i >> 4, cc = i & 15;
            As[cc][r] = A[(size_t)(brow + r) * HC + k0 + cc];
        }
        for (int i = tid; i < BN * BK; i += 256) {
            int n = i >> 4, kk = i & 15;
            int gn = bcol + n;
            Bs[kk][n] = (gn < N_ENTC) ? Bm[(size_t)gn * HC + k0 + kk] : 0.f;
        }
        __syncthreads();
        #pragma unroll
        for (int k = 0; k < BK; k++) {
            float ra[TM], rb[TN];
            #pragma unroll
            for (int i = 0; i < TM; i++) ra[i] = As[k][wrow + i];
            #pragma unroll
            for (int j = 0; j < TN; j++) rb[j] = Bs[k][lane + 32 * j];
            #pragma unroll
            for (int i = 0; i < TM; i++)
                #pragma unroll
                for (int j = 0; j < TN; j++) c[i][j] = fmaf(ra[i], rb[j], c[i][j]);
        }
        __syncthreads();
    }
    float lsp = 0.f, lxo = 0.f;
    #pragma unroll
    for (int i = 0; i < TM; i++) {
        int row = brow + wrow + i;
        int ob = trip[row * 3 + 2];
        #pragma unroll
        for (int j = 0; j < TN; j++) {
            int col = bcol + lane + 32 * j;
            if (col < N_ENTC) {
                float x = c[i][j];
                float e = __expf(-fabsf(x));
                float sig = (x >= 0.f) ? 1.f / (1.f + e) : e / (1.f + e);
                out[(size_t)row * N_ENTC + col] = sig;
                lsp += fmaxf(x, 0.f) + __logf(1.f + e);
                if (col == ob) lxo += x;
            }
        }
    }
    float bs = blockReduceSum(lsp);
    float bx = blockReduceSum(lxo);
    if (tid == 0) {
        atomicAdd(&acc[0], (double)bs);
        atomicAdd(&acc[1], (double)bx);
    }
}

__global__ void k_final(const double* __restrict__ acc, float* __restrict__ out) {
    if (threadIdx.x == 0) {
        out[(size_t)NBC * N_ENTC]     = (float)(acc[2] / (double)(NBC * HC));
        out[(size_t)NBC * N_ENTC + 1] = (float)((acc[0] - acc[1]) /
                                                ((double)NBC * (double)N_ENTC));
    }
}

// ---------------- host ----------------
static void launch_gemm(bool transB, int act, const float* A, const float* B,
                        const float* bias, const float* D, float* C, int M, int N, int K,
                        float alpha, float beta) {
    dim3 g((N + 127) / 128, (M + 63) / 64);
    if (transB) {
        if (act == 1) k_gemm<true, 1><<<g, 256>>>(A, B, bias, D, C, M, N, K, alpha, beta);
        else          k_gemm<true, 0><<<g, 256>>>(A, B, bias, D, C, M, N, K, alpha, beta);
    } else {
        if (act == 1) k_gemm<false, 1><<<g, 256>>>(A, B, bias, D, C, M, N, K, alpha, beta);
        else          k_gemm<false, 0><<<g, 256>>>(A, B, bias, D, C, M, N, K, alpha, beta);
    }
}

extern "C" void kernel_launch(void* const* d_in, const int* in_sizes, int n_in,
                              void* d_out, int out_size) {
    const float* ent  = (const float*)d_in[0];
    const float* rel  = (const float*)d_in[1];
    const float* Wn   = (const float*)d_in[2];
    const float* Wl   = (const float*)d_in[3];
    const float* Wev  = (const float*)d_in[4];
    const float* wih  = (const float*)d_in[5];
    const float* whh  = (const float*)d_in[6];
    const float* bih  = (const float*)d_in[7];
    const float* bhh  = (const float*)d_in[8];
    const float* Wm1  = (const float*)d_in[9];
    const float* bm1  = (const float*)d_in[10];
    const float* Wm2  = (const float*)d_in[11];
    const float* bm2  = (const float*)d_in[12];
    const float* Wh1  = (const float*)d_in[13];
    const float* bh1  = (const float*)d_in[14];
    const float* Wh2  = (const float*)d_in[15];
    const float* bh2  = (const float*)d_in[16];
    const float* Wal  = (const float*)d_in[17];
    const float* bal  = (const float*)d_in[18];
    const float* Wat  = (const float*)d_in[19];
    const float* bat  = (const float*)d_in[20];
    const float* part = (const float*)d_in[21];
    const int* esrc = (const int*)d_in[22];
    const int* edst = (const int*)d_in[23];
    const int* etyp = (const int*)d_in[24];
    const int* trip = (const int*)d_in[25];
    float* out = (float*)d_out;

    void* basep = nullptr;
    cudaGetSymbolAddress(&basep, d_buf);
    float* F = (float*)basep;

    float* agg    = F + O_AGG;
    float* tmp    = F + O_TMP;
    float* pre    = F + O_PRE;
    float* aln    = F + O_ALN;
    float* map1   = F + O_MAP1;
    float* mrel   = F + O_MREL;
    float* qrel   = F + O_QREL;
    float* qa     = F + O_QA;
    float* Amat   = F + O_AMAT;
    float* attn   = F + O_ATTN;
    float* rpath  = F + O_RPATH;
    float* giall  = F + O_GIALL;
    float* ghb    = F + O_GHB;
    float* gruh   = F + O_GRUH;
    float* p1     = F + O_P1;
    float* pred   = F + O_PRED;
    float* gh2    = F + O_GH2;
    float* sub    = F + O_SUB;
    float* suba   = F + O_SUBA;
    float* svec   = F + O_SVEC;
    double* acc   = (double*)(F + O_ACC);
    int* ip       = (int*)(F + O_INT);
    int* deg      = ip;
    int* rowptr   = deg + N_ENTC;
    int* cursor   = rowptr + N_ENTC + 1;
    int* csr      = cursor + N_ENTC;
    int* zerolist = csr + NEC;
    int* nzero    = zerolist + N_ENTC;

    // ---- graph aggregation (W factored out of the segment-sum) ----
    k_init<<<(NBC * HC + 255) / 256, 256>>>(deg, cursor, nzero, acc, gruh);
    k_count<<<(NEC + 255) / 256, 256>>>(edst, deg);
    k_scan<<<1, 1024>>>(deg, rowptr);
    k_fill<<<(NEC + 255) / 256, 256>>>(edst, rowptr, cursor, csr);
    k_aggregate<<<N_ENTC, 128>>>(ent, rel, esrc, etyp, rowptr, csr, agg, zerolist, nzero);

    // pre_emb = rrelu(aggS @ Wn + h @ loop), deg==0 rows fixed up with evolve
    launch_gemm(false, 0, agg, Wn, nullptr, nullptr, tmp, N_ENTC, HC, HC, 1.f, 0.f);
    launch_gemm(false, 1, ent, Wl, nullptr, tmp, pre, N_ENTC, HC, HC, 1.f, 1.f);
    k_fixzero<<<64, 128>>>(ent, Wev, pre, zerolist, nzero);

    // aligned_all = pre @ W_align^T + b
    launch_gemm(true, 0, pre, Wal, bal, nullptr, aln, N_ENTC, HC, HC, 1.f, 0.f);

    // mapped_rel
    launch_gemm(true, 0, rel, Wm1, bm1, nullptr, map1, NRELC, 256, HC, 1.f, 0.f);
    launch_gemm(true, 0, map1, Wm2, bm2, nullptr, mrel, NRELC, HC, 256, 1.f, 0.f);

    // q_rel, A
    k_gather<<<NBC, 128>>>(mrel, trip, 1, qrel);
    launch_gemm(true, 0, qrel, Wat, bat, nullptr, qa, NBC, HC, HC, 1.f, 0.f);
    launch_gemm(true, 0, qa, mrel, nullptr, nullptr, Amat, NBC, NRELC, HC, 1.f, 0.f);

    // hoisted: softmax + rel_path + gi for all 8 timesteps at once
    k_attn<<<NTC * NBC, 512>>>(part, Amat, attn);
    launch_gemm(false, 0, attn, mrel, nullptr, nullptr, rpath, NTC * NBC, HC, NRELC, 1.f, 0.f);
    launch_gemm(true, 0, rpath, wih, bih, nullptr, giall, NTC * NBC, H3C, HC, 1.f, 0.f);

    // sequential GRU: only the h-dependent part
    for (int t = 0; t < NTC; t++) {
        launch_gemm(true, 0, gruh, whh, bhh, nullptr, ghb, NBC, H3C, HC, 1.f, 0.f);
        k_gru<<<(NBC * HC + 255) / 256, 256>>>(giall + (size_t)t * NBC * H3C, ghb, gruh, gruh);
    }

    // predicted_hist + match_loss + gh2
    launch_gemm(true, 0, qrel, Wh1, bh1, nullptr, p1, NBC, HC, HC, 1.f, 0.f);
    launch_gemm(true, 0, p1, Wh2, bh2, qrel, pred, NBC, HC, HC, 0.1f, 1.f);
    k_match<<<128, 256>>>(pred, gruh, acc);
    launch_gemm(true, 0, qrel, wih, bih, nullptr, giall, NBC, H3C, HC, 1.f, 0.f);
    launch_gemm(true, 0, pred, whh, bhh, nullptr, ghb, NBC, H3C, HC, 1.f, 0.f);
    k_gru<<<(NBC * HC + 255) / 256, 256>>>(giall, ghb, pred, gh2);

    // svec = (sub_emb @ W_align^T + b) * gh2
    k_gather<<<NBC, 128>>>(pre, trip, 0, sub);
    launch_gemm(true, 0, sub, Wal, bal, nullptr, suba, NBC, HC, HC, 1.f, 0.f);
    k_mul<<<(NBC * HC + 255) / 256, 256>>>(suba, gh2, svec, NBC * HC);

    // scoring GEMM + fused sigmoid + loss reduction
    dim3 gs((N_ENTC + 127) / 128, (NBC + 63) / 64);
    k_score<<<gs, 256>>>(svec, aln, trip, out, acc);
    if (out_size >= NBC * N_ENTC + 2) k_final<<<1, 32>>>(acc, out);
}

// round 4
// speedup vs baseline: 1.2921x; 1.2921x over previous
#include <cuda_runtime.h>
#include <cuda_bf16.h>
#include <stdint.h>
#include <math.h>

#define N_ENTC 20000
#define NRELC  460
#define HC     128
#define NEC    400000
#define NBC    1024
#define NTC    8
#define H3C    384
#define SLOPE  0.22916666666666666f

// ---------------- scratch layout (single __device__ blob, fp32) ----------------
constexpr size_t SEH = (size_t)N_ENTC * HC;
constexpr size_t O_PRE   = 0;
constexpr size_t O_MAP1  = O_PRE + SEH;
constexpr size_t O_MREL  = O_MAP1 + (size_t)NRELC * 256;
constexpr size_t O_QREL  = O_MREL + (size_t)NRELC * HC;
constexpr size_t O_QA    = O_QREL + (size_t)NBC * HC;
constexpr size_t O_AMAT  = O_QA + (size_t)NBC * HC;
constexpr size_t O_ATTN  = O_AMAT + (size_t)NBC * NRELC;
constexpr size_t O_RPATH = O_ATTN + (size_t)NTC * NBC * NRELC;
constexpr size_t O_GIALL = O_RPATH + (size_t)NTC * NBC * HC;
constexpr size_t O_GHB   = O_GIALL + (size_t)NTC * NBC * H3C;
constexpr size_t O_GRUH  = O_GHB + (size_t)NBC * H3C;
constexpr size_t O_P1    = O_GRUH + (size_t)NBC * HC;
constexpr size_t O_PRED  = O_P1 + (size_t)NBC * HC;
constexpr size_t O_GH2   = O_PRED + (size_t)NBC * HC;
constexpr size_t O_SUB   = O_GH2 + (size_t)NBC * HC;
constexpr size_t O_SUBA  = O_SUB + (size_t)NBC * HC;
constexpr size_t O_SVEC  = O_SUBA + (size_t)NBC * HC;
constexpr size_t O_ACC_  = O_SVEC + (size_t)NBC * HC;
constexpr size_t O_ACC   = (O_ACC_ + 1) & ~(size_t)1;
constexpr size_t O_INT   = O_ACC + 8;
constexpr size_t N_INTS  = (size_t)N_ENTC + (N_ENTC + 1) + N_ENTC + NEC + N_ENTC + 8;
constexpr size_t TOTALF  = O_INT + N_INTS;

__device__ __align__(16) float d_buf[TOTALF];

// bf16 scratch
__device__ __align__(16) __nv_bfloat16 g_A2[(size_t)N_ENTC * 256];   // [agg | ent]
__device__ __align__(16) __nv_bfloat16 g_B2[128 * 256];              // [Wn^T | Wl^T]
__device__ __align__(16) __nv_bfloat16 g_prebf[(size_t)N_ENTC * HC];
__device__ __align__(16) __nv_bfloat16 g_alnbf[(size_t)N_ENTC * HC];
__device__ __align__(16) __nv_bfloat16 g_walb[HC * HC];
__device__ __align__(16) __nv_bfloat16 g_svecb[(size_t)NBC * HC];

// ---------------- reductions ----------------
__device__ __forceinline__ float blockReduceSum(float v) {
    __shared__ float sh[32];
    int tid = threadIdx.x;
    __syncthreads();
    #pragma unroll
    for (int o = 16; o > 0; o >>= 1) v += __shfl_xor_sync(0xffffffffu, v, o);
    if ((tid & 31) == 0) sh[tid >> 5] = v;
    __syncthreads();
    float r = 0.f;
    if (tid < 32) {
        int nw = (blockDim.x + 31) >> 5;
        r = (tid < nw) ? sh[tid] : 0.f;
        #pragma unroll
        for (int o = 16; o > 0; o >>= 1) r += __shfl_xor_sync(0xffffffffu, r, o);
    }
    return r;
}
__device__ __forceinline__ float blockReduceMax(float v) {
    __shared__ float sh[32];
    int tid = threadIdx.x;
    __syncthreads();
    #pragma unroll
    for (int o = 16; o > 0; o >>= 1) v = fmaxf(v, __shfl_xor_sync(0xffffffffu, v, o));
    if ((tid & 31) == 0) sh[tid >> 5] = v;
    __syncthreads();
    float r = -3.402823e38f;
    if (tid < 32) {
        int nw = (blockDim.x + 31) >> 5;
        r = (tid < nw) ? sh[tid] : -3.402823e38f;
        #pragma unroll
        for (int o = 16; o > 0; o >>= 1) r = fmaxf(r, __shfl_xor_sync(0xffffffffu, r, o));
    }
    return r;
}

// ---------------- CSR build ----------------
__global__ void k_init(int* deg, int* cursor, int* nzero, double* acc, float* gruh) {
    int i = blockIdx.x * blockDim.x + threadIdx.x;
    if (i < N_ENTC) { deg[i] = 0; cursor[i] = 0; }
    if (i < NBC * HC) gruh[i] = 0.f;
    if (i == 0) { nzero[0] = 0; acc[0] = 0.0; acc[1] = 0.0; acc[2] = 0.0; }
}

__global__ void k_count(const int* __restrict__ dst, int* deg) {
    int e = blockIdx.x * blockDim.x + threadIdx.x;
    if (e < NEC) atomicAdd(&deg[dst[e]], 1);
}

__global__ void k_scan(const int* __restrict__ deg, int* rowptr) {
    __shared__ int s[1024];
    __shared__ int carry;
    int tid = threadIdx.x;
    if (tid == 0) carry = 0;
    __syncthreads();
    for (int base = 0; base < N_ENTC; base += 1024) {
        int i = base + tid;
        int v = (i < N_ENTC) ? deg[i] : 0;
        s[tid] = v;
        __syncthreads();
        for (int off = 1; off < 1024; off <<= 1) {
            int t = (tid >= off) ? s[tid - off] : 0;
            __syncthreads();
            s[tid] += t;
            __syncthreads();
        }
        int incl = s[tid];
        if (i < N_ENTC) rowptr[i] = carry + incl - v;
        __syncthreads();
        if (tid == 1023) carry += incl;
        __syncthreads();
    }
    if (tid == 0) rowptr[N_ENTC] = carry;
}

__global__ void k_fill(const int* __restrict__ dst, const int* __restrict__ rowptr,
                       int* cursor, int* csr) {
    int e = blockIdx.x * blockDim.x + threadIdx.x;
    if (e < NEC) {
        int d = dst[e];
        int p = atomicAdd(&cursor[d], 1);
        csr[rowptr[d] + p] = e;
    }
}

// aggregate: writes bf16 agg directly into g_A2 cols [0,128)
__global__ void k_aggregate(const float* __restrict__ ent, const float* __restrict__ rel,
                            const int* __restrict__ src, const int* __restrict__ typ,
                            const int* __restrict__ rowptr, const int* __restrict__ csr,
                            int* zerolist, int* nzero) {
    int node = blockIdx.x;
    int c = threadIdx.x;  // 128
    __shared__ int s_src[512];
    __shared__ int s_typ[512];
    int beg = rowptr[node], end = rowptr[node + 1];
    int deg = end - beg;
    float acc = 0.f;
    for (int base = beg; base < end; base += 512) {
        int cnt = min(512, end - base);
        for (int i = c; i < cnt; i += 128) {
            int e = csr[base + i];
            s_src[i] = src[e] * HC;
            s_typ[i] = typ[e] * HC;
        }
        __syncthreads();
        #pragma unroll 4
        for (int i = 0; i < cnt; i++)
            acc += ent[s_src[i] + c] + rel[s_typ[i] + c];
        __syncthreads();
    }
    float v = (deg > 0) ? acc * (1.0f / (float)deg) : 0.f;
    g_A2[(size_t)node * 256 + c] = __float2bfloat16(v);
    if (c == 0 && deg == 0) {
        int p = atomicAdd(nzero, 1);
        zerolist[p] = node;
    }
}

__global__ void k_entcvt(const float* __restrict__ ent) {
    int i = blockIdx.x * blockDim.x + threadIdx.x;
    if (i < N_ENTC * HC)
        g_A2[(size_t)(i >> 7) * 256 + 128 + (i & 127)] = __float2bfloat16(ent[i]);
}

__global__ void k_b2(const float* __restrict__ Wn, const float* __restrict__ Wl) {
    int i = blockIdx.x * blockDim.x + threadIdx.x;
    if (i < 128 * 256) {
        int n = i >> 8, k = i & 255;
        float v = (k < 128) ? Wn[k * 128 + n] : Wl[(k - 128) * 128 + n];
        g_B2[i] = __float2bfloat16(v);
    }
}

__global__ void k_cvt(const float* __restrict__ src, __nv_bfloat16* __restrict__ dst, int n) {
    int i = blockIdx.x * blockDim.x + threadIdx.x;
    if (i < n) dst[i] = __float2bfloat16(src[i]);
}

// ---------------- bf16 tensor-core GEMM: C = epi(A[M,K] * B[N,K]^T) ----------------
// EPI: 1 = bf16 out (+opt bias), 2 = rrelu dual out (fp32 + bf16), 3 = score
#define BGM 128
#define BGN 128
#define BGK 32
#define SSTR 40

template <int EPI>
__global__ __launch_bounds__(256)
void k_bgemm(const __nv_bfloat16* __restrict__ A, const __nv_bfloat16* __restrict__ B,
             const float* __restrict__ bias, float* __restrict__ Cf,
             __nv_bfloat16* __restrict__ Cb, const int* __restrict__ trip,
             double* acc, int M, int N, int K) {
    __shared__ __nv_bfloat16 As[BGM * SSTR];
    __shared__ __nv_bfloat16 Bs[BGN * SSTR];
    int tid = threadIdx.x;
    int lane = tid & 31, wid = tid >> 5;
    int wm = wid & 3, wn = wid >> 2;      // 4x2 warp grid: 32 rows x 64 cols each
    int rowBase = blockIdx.y * BGM;
    int colBase = blockIdx.x * BGN;
    float c[2][8][4];
    #pragma unroll
    for (int i = 0; i < 2; i++)
        #pragma unroll
        for (int j = 0; j < 8; j++)
            #pragma unroll
            for (int q = 0; q < 4; q++) c[i][j][q] = 0.f;

    for (int k0 = 0; k0 < K; k0 += BGK) {
        #pragma unroll
        for (int i = 0; i < 2; i++) {
            int idx = tid + i * 256;
            int r = idx >> 2, seg = idx & 3;
            uint4 va = make_uint4(0, 0, 0, 0);
            int gr = rowBase + r;
            if (gr < M) va = *(const uint4*)(A + (size_t)gr * K + k0 + seg * 8);
            *(uint4*)(As + r * SSTR + seg * 8) = va;
            uint4 vb = make_uint4(0, 0, 0, 0);
            int gn = colBase + r;
            if (gn < N) vb = *(const uint4*)(B + (size_t)gn * K + k0 + seg * 8);
            *(uint4*)(Bs + r * SSTR + seg * 8) = vb;
        }
        __syncthreads();
        #pragma unroll
        for (int kk = 0; kk < BGK; kk += 16) {
            uint32_t a[2][4], b[8][2];
            #pragma unroll
            for (int mt = 0; mt < 2; mt++) {
                int row = wm * 32 + mt * 16 + (lane & 15);
                int col = kk + ((lane >> 4) << 3);
                uint32_t addr = (uint32_t)__cvta_generic_to_shared(As + row * SSTR + col);
                asm volatile("ldmatrix.sync.aligned.m8n8.x4.shared.b16 {%0,%1,%2,%3},[%4];"
                             : "=r"(a[mt][0]), "=r"(a[mt][1]), "=r"(a[mt][2]), "=r"(a[mt][3])
                             : "r"(addr));
            }
            #pragma unroll
            for (int np = 0; np < 4; np++) {
                int nrow = wn * 64 + np * 16 + ((lane >> 4) << 3) + (lane & 7);
                int ncol = kk + (((lane >> 3) & 1) << 3);
                uint32_t addr = (uint32_t)__cvta_generic_to_shared(Bs + nrow * SSTR + ncol);
                asm volatile("ldmatrix.sync.aligned.m8n8.x4.shared.b16 {%0,%1,%2,%3},[%4];"
                             : "=r"(b[2 * np][0]), "=r"(b[2 * np][1]),
                               "=r"(b[2 * np + 1][0]), "=r"(b[2 * np + 1][1])
                             : "r"(addr));
            }
            #pragma unroll
            for (int mt = 0; mt < 2; mt++)
                #pragma unroll
                for (int nt = 0; nt < 8; nt++)
                    asm volatile(
                        "mma.sync.aligned.m16n8k16.row.col.f32.bf16.bf16.f32 "
                        "{%0,%1,%2,%3},{%4,%5,%6,%7},{%8,%9},{%0,%1,%2,%3};"
                        : "+f"(c[mt][nt][0]), "+f"(c[mt][nt][1]),
                          "+f"(c[mt][nt][2]), "+f"(c[mt][nt][3])
                        : "r"(a[mt][0]), "r"(a[mt][1]), "r"(a[mt][2]), "r"(a[mt][3]),
                          "r"(b[nt][0]), "r"(b[nt][1]));
        }
        __syncthreads();
    }

    if (EPI == 3) {
        float lsp = 0.f, lxo = 0.f;
        #pragma unroll
        for (int mt = 0; mt < 2; mt++) {
            int r0 = rowBase + wm * 32 + mt * 16 + (lane >> 2);
            int ob0 = trip[r0 * 3 + 2];
            int ob1 = trip[(r0 + 8) * 3 + 2];
            #pragma unroll
            for (int nt = 0; nt < 8; nt++) {
                int col = colBase + wn * 64 + nt * 8 + ((lane & 3) << 1);
                if (col < N) {
                    #pragma unroll
                    for (int half = 0; half < 2; half++) {
                        int row = r0 + half * 8;
                        int ob = half ? ob1 : ob0;
                        float x0 = c[mt][nt][half * 2 + 0];
                        float x1 = c[mt][nt][half * 2 + 1];
                        float e0 = __expf(-fabsf(x0));
                        float e1 = __expf(-fabsf(x1));
                        float s0 = (x0 >= 0.f) ? 1.f / (1.f + e0) : e0 / (1.f + e0);
                        float s1 = (x1 >= 0.f) ? 1.f / (1.f + e1) : e1 / (1.f + e1);
                        *(float2*)(Cf + (size_t)row * N + col) = make_float2(s0, s1);
                        lsp += fmaxf(x0, 0.f) + __logf(1.f + e0)
                             + fmaxf(x1, 0.f) + __logf(1.f + e1);
                        if (col == ob) lxo += x0;
                        if (col + 1 == ob) lxo += x1;
                    }
                }
            }
        }
        float bs = blockReduceSum(lsp);
        float bx = blockReduceSum(lxo);
        if (tid == 0) {
            atomicAdd(&acc[0], (double)bs);
            atomicAdd(&acc[1], (double)bx);
        }
    } else {
        #pragma unroll
        for (int mt = 0; mt < 2; mt++) {
            #pragma unroll
            for (int nt = 0; nt < 8; nt++) {
                int col = colBase + wn * 64 + nt * 8 + ((lane & 3) << 1);
                if (col >= N) continue;
                float b0 = bias ? bias[col] : 0.f;
                float b1 = bias ? bias[col + 1] : 0.f;
                #pragma unroll
                for (int half = 0; half < 2; half++) {
                    int row = rowBase + wm * 32 + mt * 16 + (lane >> 2) + half * 8;
                    if (row >= M) continue;
                    float v0 = c[mt][nt][half * 2 + 0] + b0;
                    float v1 = c[mt][nt][half * 2 + 1] + b1;
                    if (EPI == 2) {
                        v0 = (v0 >= 0.f) ? v0 : v0 * SLOPE;
                        v1 = (v1 >= 0.f) ? v1 : v1 * SLOPE;
                        *(float2*)(Cf + (size_t)row * N + col) = make_float2(v0, v1);
                    }
                    *(__nv_bfloat162*)(Cb + (size_t)row * N + col) =
                        __nv_bfloat162(__float2bfloat16(v0), __float2bfloat16(v1));
                }
            }
        }
    }
}

// ---------------- fp32 tiled GEMM (small/medium ops) ----------------
template <bool TRANSB, int ACT>
__global__ __launch_bounds__(256)
void k_gemm(const float* __restrict__ A, const float* __restrict__ Bm,
            const float* __restrict__ bias, const float* __restrict__ Dres,
            float* __restrict__ C, int M, int N, int K, float alpha, float beta) {
    const int BM = 64, BN = 128, BK = 16, TM = 8, TN = 4;
    __shared__ float As[BK][BM + 1];
    __shared__ float Bs[BK][BN + 1];
    int brow = blockIdx.y * BM, bcol = blockIdx.x * BN;
    int tid = threadIdx.x, lane = tid & 31, wrow = (tid >> 5) * TM;
    float acc[TM][TN] = {};
    for (int k0 = 0; k0 < K; k0 += BK) {
        for (int i = tid; i < BM * BK; i += 256) {
            int r = i >> 4, cc = i & 15;
            int gr = brow + r, gc = k0 + cc;
            As[cc][r] = (gr < M && gc < K) ? A[(size_t)gr * K + gc] : 0.f;
        }
        if (TRANSB) {
            for (int i = tid; i < BN * BK; i += 256) {
                int n = i >> 4, kk = i & 15;
                int gn = bcol + n, gk = k0 + kk;
                Bs[kk][n] = (gn < N && gk < K) ? Bm[(size_t)gn * K + gk] : 0.f;
            }
        } else {
            for (int i = tid; i < BK * BN; i += 256) {
                int kk = i >> 7, n = i & 127;
                int gk = k0 + kk, gn = bcol + n;
                Bs[kk][n] = (gk < K && gn < N) ? Bm[(size_t)gk * N + gn] : 0.f;
            }
        }
        __syncthreads();
        #pragma unroll
        for (int k = 0; k < BK; k++) {
            float ra[TM], rb[TN];
            #pragma unroll
            for (int i = 0; i < TM; i++) ra[i] = As[k][wrow + i];
            #pragma unroll
            for (int j = 0; j < TN; j++) rb[j] = Bs[k][lane + 32 * j];
            #pragma unroll
            for (int i = 0; i < TM; i++)
                #pragma unroll
                for (int j = 0; j < TN; j++) acc[i][j] = fmaf(ra[i], rb[j], acc[i][j]);
        }
        __syncthreads();
    }
    #pragma unroll
    for (int i = 0; i < TM; i++) {
        int row = brow + wrow + i;
        if (row >= M) continue;
        #pragma unroll
        for (int j = 0; j < TN; j++) {
            int col = bcol + lane + 32 * j;
            if (col >= N) continue;
            float v = acc[i][j];
            if (bias) v += bias[col];
            v *= alpha;
            if (Dres) v += beta * Dres[(size_t)row * N + col];
            if (ACT == 1) v = (v >= 0.f) ? v : v * SLOPE;
            C[(size_t)row * N + col] = v;
        }
    }
}

__global__ void k_fixzero(const float* __restrict__ ent, const float* __restrict__ Wev,
                          float* __restrict__ pre, const int* __restrict__ zerolist,
                          const int* __restrict__ nzero) {
    __shared__ float hrow[HC];
    int nz = nzero[0];
    int j = threadIdx.x;
    for (int zi = blockIdx.x; zi < nz; zi += gridDim.x) {
        int node = zerolist[zi];
        hrow[j] = ent[node * HC + j];
        __syncthreads();
        float s = 0.f;
        #pragma unroll 8
        for (int k = 0; k < HC; k++) s = fmaf(hrow[k], Wev[k * HC + j], s);
        s = (s >= 0.f) ? s : s * SLOPE;
        pre[node * HC + j] = s;
        g_prebf[(size_t)node * HC + j] = __float2bfloat16(s);
        __syncthreads();
    }
}

__global__ void k_gather(const float* __restrict__ mat, const int* __restrict__ trip,
                         int col, float* __restrict__ out) {
    int b = blockIdx.x, j = threadIdx.x;
    out[b * HC + j] = mat[(size_t)trip[b * 3 + col] * HC + j];
}

__global__ void k_attn(const float* __restrict__ part, const float* __restrict__ Amat,
                       float* __restrict__ attn_all) {
    int tb = blockIdx.x;
    int t = tb >> 10, b = tb & 1023;
    int tid = threadIdx.x;  // 512
    float x = -3.402823e38f;
    if (tid < NRELC) {
        float cur = part[(size_t)b * (NTC * NRELC) + t * NRELC + tid];
        float a = Amat[b * NRELC + tid];
        float val = cur * a;
        x = (val == 0.f) ? -1e9f : val;
    }
    float m = blockReduceMax(x);
    __shared__ float sm_m, sm_s;
    if (tid == 0) sm_m = m;
    __syncthreads();
    m = sm_m;
    float e = (tid < NRELC) ? __expf(x - m) : 0.f;
    float s = blockReduceSum(e);
    if (tid == 0) sm_s = s;
    __syncthreads();
    s = sm_s;
    if (tid < NRELC) attn_all[(size_t)tb * NRELC + tid] = e / s;
}

__global__ void k_gru(const float* __restrict__ gi, const float* __restrict__ gh,
                      const float* __restrict__ hin, float* __restrict__ hout) {
    int idx = blockIdx.x * blockDim.x + threadIdx.x;
    if (idx >= NBC * HC) return;
    int b = idx >> 7, j = idx & 127;
    float ir = gi[b * H3C + j], iz = gi[b * H3C + HC + j], inn = gi[b * H3C + 2 * HC + j];
    float hr = gh[b * H3C + j], hz = gh[b * H3C + HC + j], hn = gh[b * H3C + 2 * HC + j];
    float r = 1.f / (1.f + expf(-(ir + hr)));
    float z = 1.f / (1.f + expf(-(iz + hz)));
    float n = tanhf(inn + r * hn);
    hout[idx] = (1.f - z) * n + z * hin[idx];
}

__global__ void k_mul(const float* __restrict__ a, const float* __restrict__ b,
                      float* __restrict__ c, int n) {
    int i = blockIdx.x * blockDim.x + threadIdx.x;
    if (i < n) {
        float v = a[i] * b[i];
        c[i] = v;
        g_svecb[i] = __float2bfloat16(v);
    }
}

__global__ void k_match(const float* __restrict__ pred, const float* __restrict__ gruh,
                        double* acc) {
    float s = 0.f;
    for (int i = blockIdx.x * blockDim.x + threadIdx.x; i < NBC * HC;
         i += gridDim.x * blockDim.x) {
        float d = pred[i] - gruh[i];
        s += d * d;
    }
    float b = blockReduceSum(s);
    if (threadIdx.x == 0) atomicAdd(&acc[2], (double)b);
}

__global__ void k_final(const double* __restrict__ acc, float* __restrict__ out) {
    if (threadIdx.x == 0) {
        out[(size_t)NBC * N_ENTC]     = (float)(acc[2] / (double)(NBC * HC));
        out[(size_t)NBC * N_ENTC + 1] = (float)((acc[0] - acc[1]) /
                                                ((double)NBC * (double)N_ENTC));
    }
}

// ---------------- host ----------------
static void launch_gemm(bool transB, int act, const float* A, const float* B,
                        const float* bias, const float* D, float* C, int M, int N, int K,
                        float alpha, float beta) {
    dim3 g((N + 127) / 128, (M + 63) / 64);
    if (transB) {
        if (act == 1) k_gemm<true, 1><<<g, 256>>>(A, B, bias, D, C, M, N, K, alpha, beta);
        else          k_gemm<true, 0><<<g, 256>>>(A, B, bias, D, C, M, N, K, alpha, beta);
    } else {
        if (act == 1) k_gemm<false, 1><<<g, 256>>>(A, B, bias, D, C, M, N, K, alpha, beta);
        else          k_gemm<false, 0><<<g, 256>>>(A, B, bias, D, C, M, N, K, alpha, beta);
    }
}

extern "C" void kernel_launch(void* const* d_in, const int* in_sizes, int n_in,
                              void* d_out, int out_size) {
    const float* ent  = (const float*)d_in[0];
    const float* rel  = (const float*)d_in[1];
    const float* Wn   = (const float*)d_in[2];
    const float* Wl   = (const float*)d_in[3];
    const float* Wev  = (const float*)d_in[4];
    const float* wih  = (const float*)d_in[5];
    const float* whh  = (const float*)d_in[6];
    const float* bih  = (const float*)d_in[7];
    const float* bhh  = (const float*)d_in[8];
    const float* Wm1  = (const float*)d_in[9];
    const float* bm1  = (const float*)d_in[10];
    const float* Wm2  = (const float*)d_in[11];
    const float* bm2  = (const float*)d_in[12];
    const float* Wh1  = (const float*)d_in[13];
    const float* bh1  = (const float*)d_in[14];
    const float* Wh2  = (const float*)d_in[15];
    const float* bh2  = (const float*)d_in[16];
    const float* Wal  = (const float*)d_in[17];
    const float* bal  = (const float*)d_in[18];
    const float* Wat  = (const float*)d_in[19];
    const float* bat  = (const float*)d_in[20];
    const float* part = (const float*)d_in[21];
    const int* esrc = (const int*)d_in[22];
    const int* edst = (const int*)d_in[23];
    const int* etyp = (const int*)d_in[24];
    const int* trip = (const int*)d_in[25];
    float* out = (float*)d_out;

    void* basep = nullptr;
    cudaGetSymbolAddress(&basep, d_buf);
    float* F = (float*)basep;
    __nv_bfloat16 *pA2, *pB2, *pPreb, *pAlnb, *pWalb, *pSvecb;
    { void* p; cudaGetSymbolAddress(&p, g_A2);    pA2    = (__nv_bfloat16*)p; }
    { void* p; cudaGetSymbolAddress(&p, g_B2);    pB2    = (__nv_bfloat16*)p; }
    { void* p; cudaGetSymbolAddress(&p, g_prebf); pPreb  = (__nv_bfloat16*)p; }
    { void* p; cudaGetSymbolAddress(&p, g_alnbf); pAlnb  = (__nv_bfloat16*)p; }
    { void* p; cudaGetSymbolAddress(&p, g_walb);  pWalb  = (__nv_bfloat16*)p; }
    { void* p; cudaGetSymbolAddress(&p, g_svecb); pSvecb = (__nv_bfloat16*)p; }

    float* pre    = F + O_PRE;
    float* map1   = F + O_MAP1;
    float* mrel   = F + O_MREL;
    float* qrel   = F + O_QREL;
    float* qa     = F + O_QA;
    float* Amat   = F + O_AMAT;
    float* attn   = F + O_ATTN;
    float* rpath  = F + O_RPATH;
    float* giall  = F + O_GIALL;
    float* ghb    = F + O_GHB;
    float* gruh   = F + O_GRUH;
    float* p1     = F + O_P1;
    float* pred   = F + O_PRED;
    float* gh2    = F + O_GH2;
    float* sub    = F + O_SUB;
    float* suba   = F + O_SUBA;
    float* svec   = F + O_SVEC;
    double* acc   = (double*)(F + O_ACC);
    int* ip       = (int*)(F + O_INT);
    int* deg      = ip;
    int* rowptr   = deg + N_ENTC;
    int* cursor   = rowptr + N_ENTC + 1;
    int* csr      = cursor + N_ENTC;
    int* zerolist = csr + NEC;
    int* nzero    = zerolist + N_ENTC;

    // ---- CSR build + aggregation (writes bf16 agg into A2) ----
    k_init<<<(NBC * HC + 255) / 256, 256>>>(deg, cursor, nzero, acc, gruh);
    k_count<<<(NEC + 255) / 256, 256>>>(edst, deg);
    k_scan<<<1, 1024>>>(deg, rowptr);
    k_fill<<<(NEC + 255) / 256, 256>>>(edst, rowptr, cursor, csr);
    k_aggregate<<<N_ENTC, 128>>>(ent, rel, esrc, etyp, rowptr, csr, zerolist, nzero);
    k_entcvt<<<(N_ENTC * HC + 255) / 256, 256>>>(ent);
    k_b2<<<(128 * 256 + 255) / 256, 256>>>(Wn, Wl);
    k_cvt<<<(HC * HC + 255) / 256, 256>>>(Wal, pWalb, HC * HC);

    // pre = rrelu([agg|ent] @ [Wn;Wl]) — ONE bf16 GEMM, K=256, dual output
    {
        dim3 g(1, (N_ENTC + BGM - 1) / BGM);
        k_bgemm<2><<<g, 256>>>(pA2, pB2, nullptr, pre, pPreb, nullptr, nullptr,
                               N_ENTC, HC, 256);
    }
    k_fixzero<<<64, 128>>>(ent, Wev, pre, zerolist, nzero);

    // aln_bf = pre @ Wal^T + bal (bf16 out, only feeds score)
    {
        dim3 g(1, (N_ENTC + BGM - 1) / BGM);
        k_bgemm<1><<<g, 256>>>(pPreb, pWalb, bal, nullptr, pAlnb, nullptr, nullptr,
                               N_ENTC, HC, HC);
    }

    // mapped_rel (fp32 — feeds the precision-sensitive match_loss path)
    launch_gemm(true, 0, rel, Wm1, bm1, nullptr, map1, NRELC, 256, HC, 1.f, 0.f);
    launch_gemm(true, 0, map1, Wm2, bm2, nullptr, mrel, NRELC, HC, 256, 1.f, 0.f);

    // q_rel, A
    k_gather<<<NBC, 128>>>(mrel, trip, 1, qrel);
    launch_gemm(true, 0, qrel, Wat, bat, nullptr, qa, NBC, HC, HC, 1.f, 0.f);
    launch_gemm(true, 0, qa, mrel, nullptr, nullptr, Amat, NBC, NRELC, HC, 1.f, 0.f);

    // hoisted: softmax + rel_path + gi for all 8 timesteps at once
    k_attn<<<NTC * NBC, 512>>>(part, Amat, attn);
    launch_gemm(false, 0, attn, mrel, nullptr, nullptr, rpath, NTC * NBC, HC, NRELC, 1.f, 0.f);
    launch_gemm(true, 0, rpath, wih, bih, nullptr, giall, NTC * NBC, H3C, HC, 1.f, 0.f);

    // sequential GRU: only the h-dependent part
    for (int t = 0; t < NTC; t++) {
        launch_gemm(true, 0, gruh, whh, bhh, nullptr, ghb, NBC, H3C, HC, 1.f, 0.f);
        k_gru<<<(NBC * HC + 255) / 256, 256>>>(giall + (size_t)t * NBC * H3C, ghb, gruh, gruh);
    }

    // predicted_hist + match_loss + gh2
    launch_gemm(true, 0, qrel, Wh1, bh1, nullptr, p1, NBC, HC, HC, 1.f, 0.f);
    launch_gemm(true, 0, p1, Wh2, bh2, qrel, pred, NBC, HC, HC, 0.1f, 1.f);
    k_match<<<128, 256>>>(pred, gruh, acc);
    launch_gemm(true, 0, qrel, wih, bih, nullptr, giall, NBC, H3C, HC, 1.f, 0.f);
    launch_gemm(true, 0, pred, whh, bhh, nullptr, ghb, NBC, H3C, HC, 1.f, 0.f);
    k_gru<<<(NBC * HC + 255) / 256, 256>>>(giall, ghb, pred, gh2);

    // svec = (sub_emb @ W_align^T + b) * gh2   (also bf16 copy)
    k_gather<<<NBC, 128>>>(pre, trip, 0, sub);
    launch_gemm(true, 0, sub, Wal, bal, nullptr, suba, NBC, HC, HC, 1.f, 0.f);
    k_mul<<<(NBC * HC + 255) / 256, 256>>>(suba, gh2, svec, NBC * HC);

    // score: bf16 tensor-core GEMM + fused sigmoid + loss reduction
    {
        dim3 g((N_ENTC + BGN - 1) / BGN, NBC / BGM);
        k_bgemm<3><<<g, 256>>>(pSvecb, pAlnb, nullptr, out, nullptr, trip, acc,
                               NBC, N_ENTC, HC);
    }
    if (out_size >= NBC * N_ENTC + 2) k_final<<<1, 32>>>(acc, out);
}

// round 5
// speedup vs baseline: 1.2956x; 1.0027x over previous
#include <cuda_runtime.h>
#include <cuda_bf16.h>
#include <stdint.h>
#include <math.h>

#define N_ENTC 20000
#define NRELC  460
#define HC     128
#define NEC    400000
#define NBC    1024
#define NTC    8
#define H3C    384
#define SLOPE  0.22916666666666666f

// ---------------- scratch layout (single __device__ blob, fp32) ----------------
constexpr size_t SEH = (size_t)N_ENTC * HC;
constexpr size_t O_PRE   = 0;
constexpr size_t O_MAP1  = O_PRE + SEH;
constexpr size_t O_MREL  = O_MAP1 + (size_t)NRELC * 256;
constexpr size_t O_QREL  = O_MREL + (size_t)NRELC * HC;
constexpr size_t O_QA    = O_QREL + (size_t)NBC * HC;
constexpr size_t O_AMAT  = O_QA + (size_t)NBC * HC;
constexpr size_t O_ATTN  = O_AMAT + (size_t)NBC * NRELC;
constexpr size_t O_RPATH = O_ATTN + (size_t)NTC * NBC * NRELC;
constexpr size_t O_GIALL = O_RPATH + (size_t)NTC * NBC * HC;
constexpr size_t O_GHB   = O_GIALL + (size_t)NTC * NBC * H3C;
constexpr size_t O_GRUH  = O_GHB + (size_t)NBC * H3C;
constexpr size_t O_P1    = O_GRUH + (size_t)NBC * HC;
constexpr size_t O_PRED  = O_P1 + (size_t)NBC * HC;
constexpr size_t O_GH2   = O_PRED + (size_t)NBC * HC;
constexpr size_t O_SUB   = O_GH2 + (size_t)NBC * HC;
constexpr size_t O_SUBA  = O_SUB + (size_t)NBC * HC;
constexpr size_t O_SVEC  = O_SUBA + (size_t)NBC * HC;
constexpr size_t O_ACC_  = O_SVEC + (size_t)NBC * HC;
constexpr size_t O_ACC   = (O_ACC_ + 1) & ~(size_t)1;
constexpr size_t O_INT   = O_ACC + 8;
constexpr size_t N_INTS  = (size_t)N_ENTC + (N_ENTC + 1) + N_ENTC + NEC + N_ENTC + 8;
constexpr size_t TOTALF  = O_INT + N_INTS;

__device__ __align__(16) float d_buf[TOTALF];

// bf16 scratch
__device__ __align__(16) __nv_bfloat16 g_A2[(size_t)N_ENTC * 256];   // [agg | ent]
__device__ __align__(16) __nv_bfloat16 g_B2[128 * 256];              // [Wn^T | Wl^T]
__device__ __align__(16) __nv_bfloat16 g_prebf[(size_t)N_ENTC * HC];
__device__ __align__(16) __nv_bfloat16 g_alnbf[(size_t)N_ENTC * HC];
__device__ __align__(16) __nv_bfloat16 g_walb[HC * HC];
__device__ __align__(16) __nv_bfloat16 g_svecb[(size_t)NBC * HC];

// ---------------- reductions ----------------
__device__ __forceinline__ float blockReduceSum(float v) {
    __shared__ float sh[32];
    int tid = threadIdx.x;
    __syncthreads();
    #pragma unroll
    for (int o = 16; o > 0; o >>= 1) v += __shfl_xor_sync(0xffffffffu, v, o);
    if ((tid & 31) == 0) sh[tid >> 5] = v;
    __syncthreads();
    float r = 0.f;
    if (tid < 32) {
        int nw = (blockDim.x + 31) >> 5;
        r = (tid < nw) ? sh[tid] : 0.f;
        #pragma unroll
        for (int o = 16; o > 0; o >>= 1) r += __shfl_xor_sync(0xffffffffu, r, o);
    }
    return r;
}
__device__ __forceinline__ float blockReduceMax(float v) {
    __shared__ float sh[32];
    int tid = threadIdx.x;
    __syncthreads();
    #pragma unroll
    for (int o = 16; o > 0; o >>= 1) v = fmaxf(v, __shfl_xor_sync(0xffffffffu, v, o));
    if ((tid & 31) == 0) sh[tid >> 5] = v;
    __syncthreads();
    float r = -3.402823e38f;
    if (tid < 32) {
        int nw = (blockDim.x + 31) >> 5;
        r = (tid < nw) ? sh[tid] : -3.402823e38f;
        #pragma unroll
        for (int o = 16; o > 0; o >>= 1) r = fmaxf(r, __shfl_xor_sync(0xffffffffu, r, o));
    }
    return r;
}

// fast sigmoid + softplus: polynomial for |x|<0.5 (no MUFU), exact fallback
__device__ __forceinline__ void sig_sp(float x, float& sig, float& sp) {
    float ax = fabsf(x);
    if (ax < 0.5f) {
        float x2 = x * x;
        sig = 0.5f + x * (0.25f + x2 * (-0.0208333333f + x2 * 0.0020833333f));
        sp  = 0.69314718f + 0.5f * x
            + x2 * (0.125f + x2 * (-0.0052083333f + x2 * 0.00034722222f));
    } else {
        float e = __expf(-ax);
        sig = (x >= 0.f) ? 1.f / (1.f + e) : e / (1.f + e);
        sp  = fmaxf(x, 0.f) + __logf(1.f + e);
    }
}

// ---------------- CSR build ----------------
__global__ void k_init(int* deg, int* cursor, int* nzero, double* acc, float* gruh) {
    int i = blockIdx.x * blockDim.x + threadIdx.x;
    if (i < N_ENTC) { deg[i] = 0; cursor[i] = 0; }
    if (i < NBC * HC) gruh[i] = 0.f;
    if (i == 0) { nzero[0] = 0; acc[0] = 0.0; acc[1] = 0.0; acc[2] = 0.0; }
}

__global__ void k_count(const int* __restrict__ dst, int* deg) {
    int e = blockIdx.x * blockDim.x + threadIdx.x;
    if (e < NEC) atomicAdd(&deg[dst[e]], 1);
}

__global__ void k_scan(const int* __restrict__ deg, int* rowptr) {
    __shared__ int s[1024];
    __shared__ int carry;
    int tid = threadIdx.x;
    if (tid == 0) carry = 0;
    __syncthreads();
    for (int base = 0; base < N_ENTC; base += 1024) {
        int i = base + tid;
        int v = (i < N_ENTC) ? deg[i] : 0;
        s[tid] = v;
        __syncthreads();
        for (int off = 1; off < 1024; off <<= 1) {
            int t = (tid >= off) ? s[tid - off] : 0;
            __syncthreads();
            s[tid] += t;
            __syncthreads();
        }
        int incl = s[tid];
        if (i < N_ENTC) rowptr[i] = carry + incl - v;
        __syncthreads();
        if (tid == 1023) carry += incl;
        __syncthreads();
    }
    if (tid == 0) rowptr[N_ENTC] = carry;
}

__global__ void k_fill(const int* __restrict__ dst, const int* __restrict__ rowptr,
                       int* cursor, int* csr) {
    int e = blockIdx.x * blockDim.x + threadIdx.x;
    if (e < NEC) {
        int d = dst[e];
        int p = atomicAdd(&cursor[d], 1);
        csr[rowptr[d] + p] = e;
    }
}

// aggregate: writes bf16 agg directly into g_A2 cols [0,128)
__global__ void k_aggregate(const float* __restrict__ ent, const float* __restrict__ rel,
                            const int* __restrict__ src, const int* __restrict__ typ,
                            const int* __restrict__ rowptr, const int* __restrict__ csr,
                            int* zerolist, int* nzero) {
    int node = blockIdx.x;
    int c = threadIdx.x;  // 128
    __shared__ int s_src[512];
    __shared__ int s_typ[512];
    int beg = rowptr[node], end = rowptr[node + 1];
    int deg = end - beg;
    float acc = 0.f;
    for (int base = beg; base < end; base += 512) {
        int cnt = min(512, end - base);
        for (int i = c; i < cnt; i += 128) {
            int e = csr[base + i];
            s_src[i] = src[e] * HC;
            s_typ[i] = typ[e] * HC;
        }
        __syncthreads();
        #pragma unroll 4
        for (int i = 0; i < cnt; i++)
            acc += ent[s_src[i] + c] + rel[s_typ[i] + c];
        __syncthreads();
    }
    float v = (deg > 0) ? acc * (1.0f / (float)deg) : 0.f;
    g_A2[(size_t)node * 256 + c] = __float2bfloat16(v);
    if (c == 0 && deg == 0) {
        int p = atomicAdd(nzero, 1);
        zerolist[p] = node;
    }
}

__global__ void k_entcvt(const float* __restrict__ ent) {
    int i = blockIdx.x * blockDim.x + threadIdx.x;
    if (i < N_ENTC * HC)
        g_A2[(size_t)(i >> 7) * 256 + 128 + (i & 127)] = __float2bfloat16(ent[i]);
}

__global__ void k_b2(const float* __restrict__ Wn, const float* __restrict__ Wl) {
    int i = blockIdx.x * blockDim.x + threadIdx.x;
    if (i < 128 * 256) {
        int n = i >> 8, k = i & 255;
        float v = (k < 128) ? Wn[k * 128 + n] : Wl[(k - 128) * 128 + n];
        g_B2[i] = __float2bfloat16(v);
    }
}

__global__ void k_cvt(const float* __restrict__ src, __nv_bfloat16* __restrict__ dst, int n) {
    int i = blockIdx.x * blockDim.x + threadIdx.x;
    if (i < n) dst[i] = __float2bfloat16(src[i]);
}

// ---------------- bf16 tensor-core GEMM: C = epi(A[M,K] * B[N,K]^T) ----------------
// EPI: 1 = bf16 out (+opt bias), 2 = rrelu dual out (fp32 + bf16), 3 = score
#define BGM 128
#define BGN 128
#define BGK 32
#define SSTR 40

template <int EPI>
__global__ __launch_bounds__(256)
void k_bgemm(const __nv_bfloat16* __restrict__ A, const __nv_bfloat16* __restrict__ B,
             const float* __restrict__ bias, float* __restrict__ Cf,
             __nv_bfloat16* __restrict__ Cb, const int* __restrict__ trip,
             double* acc, int M, int N, int K) {
    __shared__ __nv_bfloat16 As[BGM * SSTR];
    __shared__ __nv_bfloat16 Bs[BGN * SSTR];
    int tid = threadIdx.x;
    int lane = tid & 31, wid = tid >> 5;
    int wm = wid & 3, wn = wid >> 2;      // 4x2 warp grid: 32 rows x 64 cols each
    int rowBase = blockIdx.y * BGM;
    int colBase = blockIdx.x * BGN;
    float c[2][8][4];
    #pragma unroll
    for (int i = 0; i < 2; i++)
        #pragma unroll
        for (int j = 0; j < 8; j++)
            #pragma unroll
            for (int q = 0; q < 4; q++) c[i][j][q] = 0.f;

    for (int k0 = 0; k0 < K; k0 += BGK) {
        #pragma unroll
        for (int i = 0; i < 2; i++) {
            int idx = tid + i * 256;
            int r = idx >> 2, seg = idx & 3;
            uint4 va = make_uint4(0, 0, 0, 0);
            int gr = rowBase + r;
            if (gr < M) va = *(const uint4*)(A + (size_t)gr * K + k0 + seg * 8);
            *(uint4*)(As + r * SSTR + seg * 8) = va;
            uint4 vb = make_uint4(0, 0, 0, 0);
            int gn = colBase + r;
            if (gn < N) vb = *(const uint4*)(B + (size_t)gn * K + k0 + seg * 8);
            *(uint4*)(Bs + r * SSTR + seg * 8) = vb;
        }
        __syncthreads();
        #pragma unroll
        for (int kk = 0; kk < BGK; kk += 16) {
            uint32_t a[2][4], b[8][2];
            #pragma unroll
            for (int mt = 0; mt < 2; mt++) {
                int row = wm * 32 + mt * 16 + (lane & 15);
                int col = kk + ((lane >> 4) << 3);
                uint32_t addr = (uint32_t)__cvta_generic_to_shared(As + row * SSTR + col);
                asm volatile("ldmatrix.sync.aligned.m8n8.x4.shared.b16 {%0,%1,%2,%3},[%4];"
                             : "=r"(a[mt][0]), "=r"(a[mt][1]), "=r"(a[mt][2]), "=r"(a[mt][3])
                             : "r"(addr));
            }
            #pragma unroll
            for (int np = 0; np < 4; np++) {
                int nrow = wn * 64 + np * 16 + ((lane >> 4) << 3) + (lane & 7);
                int ncol = kk + (((lane >> 3) & 1) << 3);
                uint32_t addr = (uint32_t)__cvta_generic_to_shared(Bs + nrow * SSTR + ncol);
                asm volatile("ldmatrix.sync.aligned.m8n8.x4.shared.b16 {%0,%1,%2,%3},[%4];"
                             : "=r"(b[2 * np][0]), "=r"(b[2 * np][1]),
                               "=r"(b[2 * np + 1][0]), "=r"(b[2 * np + 1][1])
                             : "r"(addr));
            }
            #pragma unroll
            for (int mt = 0; mt < 2; mt++)
                #pragma unroll
                for (int nt = 0; nt < 8; nt++)
                    asm volatile(
                        "mma.sync.aligned.m16n8k16.row.col.f32.bf16.bf16.f32 "
                        "{%0,%1,%2,%3},{%4,%5,%6,%7},{%8,%9},{%0,%1,%2,%3};"
                        : "+f"(c[mt][nt][0]), "+f"(c[mt][nt][1]),
                          "+f"(c[mt][nt][2]), "+f"(c[mt][nt][3])
                        : "r"(a[mt][0]), "r"(a[mt][1]), "r"(a[mt][2]), "r"(a[mt][3]),
                          "r"(b[nt][0]), "r"(b[nt][1]));
        }
        __syncthreads();
    }

    if (EPI == 3) {
        float lsp = 0.f, lxo = 0.f;
        #pragma unroll
        for (int mt = 0; mt < 2; mt++) {
            int r0 = rowBase + wm * 32 + mt * 16 + (lane >> 2);
            int ob0 = trip[r0 * 3 + 2];
            int ob1 = trip[(r0 + 8) * 3 + 2];
            #pragma unroll
            for (int nt = 0; nt < 8; nt++) {
                int col = colBase + wn * 64 + nt * 8 + ((lane & 3) << 1);
                if (col < N) {
                    #pragma unroll
                    for (int half = 0; half < 2; half++) {
                        int row = r0 + half * 8;
                        int ob = half ? ob1 : ob0;
                        float x0 = c[mt][nt][half * 2 + 0];
                        float x1 = c[mt][nt][half * 2 + 1];
                        float s0, p0, s1, p1;
                        sig_sp(x0, s0, p0);
                        sig_sp(x1, s1, p1);
                        *(float2*)(Cf + (size_t)row * N + col) = make_float2(s0, s1);
                        lsp += p0 + p1;
                        if (col == ob) lxo += x0;
                        if (col + 1 == ob) lxo += x1;
                    }
                }
            }
        }
        float bs = blockReduceSum(lsp);
        float bx = blockReduceSum(lxo);
        if (tid == 0) {
            atomicAdd(&acc[0], (double)bs);
            atomicAdd(&acc[1], (double)bx);
        }
    } else {
        #pragma unroll
        for (int mt = 0; mt < 2; mt++) {
            #pragma unroll
            for (int nt = 0; nt < 8; nt++) {
                int col = colBase + wn * 64 + nt * 8 + ((lane & 3) << 1);
                if (col >= N) continue;
                float b0 = bias ? bias[col] : 0.f;
                float b1 = bias ? bias[col + 1] : 0.f;
                #pragma unroll
                for (int half = 0; half < 2; half++) {
                    int row = rowBase + wm * 32 + mt * 16 + (lane >> 2) + half * 8;
                    if (row >= M) continue;
                    float v0 = c[mt][nt][half * 2 + 0] + b0;
                    float v1 = c[mt][nt][half * 2 + 1] + b1;
                    if (EPI == 2) {
                        v0 = (v0 >= 0.f) ? v0 : v0 * SLOPE;
                        v1 = (v1 >= 0.f) ? v1 : v1 * SLOPE;
                        *(float2*)(Cf + (size_t)row * N + col) = make_float2(v0, v1);
                    }
                    *(__nv_bfloat162*)(Cb + (size_t)row * N + col) =
                        __nv_bfloat162(__float2bfloat16(v0), __float2bfloat16(v1));
                }
            }
        }
    }
}

// ---------------- fp32 tiled GEMM (small/medium ops) ----------------
template <bool TRANSB, int ACT>
__global__ __launch_bounds__(256)
void k_gemm(const float* __restrict__ A, const float* __restrict__ Bm,
            const float* __restrict__ bias, const float* __restrict__ Dres,
            float* __restrict__ C, int M, int N, int K, float alpha, float beta) {
    const int BM = 64, BN = 128, BK = 16, TM = 8, TN = 4;
    __shared__ float As[BK][BM + 1];
    __shared__ float Bs[BK][BN + 1];
    int brow = blockIdx.y * BM, bcol = blockIdx.x * BN;
    int tid = threadIdx.x, lane = tid & 31, wrow = (tid >> 5) * TM;
    float acc[TM][TN] = {};
    for (int k0 = 0; k0 < K; k0 += BK) {
        for (int i = tid; i < BM * BK; i += 256) {
            int r = i >> 4, cc = i & 15;
            int gr = brow + r, gc = k0 + cc;
            As[cc][r] = (gr < M && gc < K) ? A[(size_t)gr * K + gc] : 0.f;
        }
        if (TRANSB) {
            for (int i = tid; i < BN * BK; i += 256) {
                int n = i >> 4, kk = i & 15;
                int gn = bcol + n, gk = k0 + kk;
                Bs[kk][n] = (gn < N && gk < K) ? Bm[(size_t)gn * K + gk] : 0.f;
            }
        } else {
            for (int i = tid; i < BK * BN; i += 256) {
                int kk = i >> 7, n = i & 127;
                int gk = k0 + kk, gn = bcol + n;
                Bs[kk][n] = (gk < K && gn < N) ? Bm[(size_t)gk * N + gn] : 0.f;
            }
        }
        __syncthreads();
        #pragma unroll
        for (int k = 0; k < BK; k++) {
            float ra[TM], rb[TN];
            #pragma unroll
            for (int i = 0; i < TM; i++) ra[i] = As[k][wrow + i];
            #pragma unroll
            for (int j = 0; j < TN; j++) rb[j] = Bs[k][lane + 32 * j];
            #pragma unroll
            for (int i = 0; i < TM; i++)
                #pragma unroll
                for (int j = 0; j < TN; j++) acc[i][j] = fmaf(ra[i], rb[j], acc[i][j]);
        }
        __syncthreads();
    }
    #pragma unroll
    for (int i = 0; i < TM; i++) {
        int row = brow + wrow + i;
        if (row >= M) continue;
        #pragma unroll
        for (int j = 0; j < TN; j++) {
            int col = bcol + lane + 32 * j;
            if (col >= N) continue;
            float v = acc[i][j];
            if (bias) v += bias[col];
            v *= alpha;
            if (Dres) v += beta * Dres[(size_t)row * N + col];
            if (ACT == 1) v = (v >= 0.f) ? v : v * SLOPE;
            C[(size_t)row * N + col] = v;
        }
    }
}

__global__ void k_fixzero(const float* __restrict__ ent, const float* __restrict__ Wev,
                          float* __restrict__ pre, const int* __restrict__ zerolist,
                          const int* __restrict__ nzero) {
    __shared__ float hrow[HC];
    int nz = nzero[0];
    int j = threadIdx.x;
    for (int zi = blockIdx.x; zi < nz; zi += gridDim.x) {
        int node = zerolist[zi];
        hrow[j] = ent[node * HC + j];
        __syncthreads();
        float s = 0.f;
        #pragma unroll 8
        for (int k = 0; k < HC; k++) s = fmaf(hrow[k], Wev[k * HC + j], s);
        s = (s >= 0.f) ? s : s * SLOPE;
        pre[node * HC + j] = s;
        g_prebf[(size_t)node * HC + j] = __float2bfloat16(s);
        __syncthreads();
    }
}

__global__ void k_gather(const float* __restrict__ mat, const int* __restrict__ trip,
                         int col, float* __restrict__ out) {
    int b = blockIdx.x, j = threadIdx.x;
    out[b * HC + j] = mat[(size_t)trip[b * 3 + col] * HC + j];
}

__global__ void k_attn(const float* __restrict__ part, const float* __restrict__ Amat,
                       float* __restrict__ attn_all) {
    int tb = blockIdx.x;
    int t = tb >> 10, b = tb & 1023;
    int tid = threadIdx.x;  // 512
    float x = -3.402823e38f;
    if (tid < NRELC) {
        float cur = part[(size_t)b * (NTC * NRELC) + t * NRELC + tid];
        float a = Amat[b * NRELC + tid];
        float val = cur * a;
        x = (val == 0.f) ? -1e9f : val;
    }
    float m = blockReduceMax(x);
    __shared__ float sm_m, sm_inv;
    if (tid == 0) sm_m = m;
    __syncthreads();
    m = sm_m;
    float e = (tid < NRELC) ? __expf(x - m) : 0.f;
    float s = blockReduceSum(e);
    if (tid == 0) sm_inv = 1.f / s;   // one rcp per row, broadcast
    __syncthreads();
    float inv = sm_inv;
    if (tid < NRELC) attn_all[(size_t)tb * NRELC + tid] = e * inv;
}

__global__ void k_gru(const float* __restrict__ gi, const float* __restrict__ gh,
                      const float* __restrict__ hin, float* __restrict__ hout) {
    int idx = blockIdx.x * blockDim.x + threadIdx.x;
    if (idx >= NBC * HC) return;
    int b = idx >> 7, j = idx & 127;
    float ir = gi[b * H3C + j], iz = gi[b * H3C + HC + j], inn = gi[b * H3C + 2 * HC + j];
    float hr = gh[b * H3C + j], hz = gh[b * H3C + HC + j], hn = gh[b * H3C + 2 * HC + j];
    float r = 1.f / (1.f + __expf(-(ir + hr)));
    float z = 1.f / (1.f + __expf(-(iz + hz)));
    float n = tanhf(inn + r * hn);
    hout[idx] = (1.f - z) * n + z * hin[idx];
}

__global__ void k_mul(const float* __restrict__ a, const float* __restrict__ b,
                      float* __restrict__ c, int n) {
    int i = blockIdx.x * blockDim.x + threadIdx.x;
    if (i < n) {
        float v = a[i] * b[i];
        c[i] = v;
        g_svecb[i] = __float2bfloat16(v);
    }
}

__global__ void k_match(const float* __restrict__ pred, const float* __restrict__ gruh,
                        double* acc) {
    float s = 0.f;
    for (int i = blockIdx.x * blockDim.x + threadIdx.x; i < NBC * HC;
         i += gridDim.x * blockDim.x) {
        float d = pred[i] - gruh[i];
        s += d * d;
    }
    float b = blockReduceSum(s);
    if (threadIdx.x == 0) atomicAdd(&acc[2], (double)b);
}

__global__ void k_final(const double* __restrict__ acc, float* __restrict__ out) {
    if (threadIdx.x == 0) {
        out[(size_t)NBC * N_ENTC]     = (float)(acc[2] / (double)(NBC * HC));
        out[(size_t)NBC * N_ENTC + 1] = (float)((acc[0] - acc[1]) /
                                                ((double)NBC * (double)N_ENTC));
    }
}

// ---------------- host ----------------
static void launch_gemm(bool transB, int act, const float* A, const float* B,
                        const float* bias, const float* D, float* C, int M, int N, int K,
                        float alpha, float beta) {
    dim3 g((N + 127) / 128, (M + 63) / 64);
    if (transB) {
        if (act == 1) k_gemm<true, 1><<<g, 256>>>(A, B, bias, D, C, M, N, K, alpha, beta);
        else          k_gemm<true, 0><<<g, 256>>>(A, B, bias, D, C, M, N, K, alpha, beta);
    } else {
        if (act == 1) k_gemm<false, 1><<<g, 256>>>(A, B, bias, D, C, M, N, K, alpha, beta);
        else          k_gemm<false, 0><<<g, 256>>>(A, B, bias, D, C, M, N, K, alpha, beta);
    }
}

extern "C" void kernel_launch(void* const* d_in, const int* in_sizes, int n_in,
                              void* d_out, int out_size) {
    const float* ent  = (const float*)d_in[0];
    const float* rel  = (const float*)d_in[1];
    const float* Wn   = (const float*)d_in[2];
    const float* Wl   = (const float*)d_in[3];
    const float* Wev  = (const float*)d_in[4];
    const float* wih  = (const float*)d_in[5];
    const float* whh  = (const float*)d_in[6];
    const float* bih  = (const float*)d_in[7];
    const float* bhh  = (const float*)d_in[8];
    const float* Wm1  = (const float*)d_in[9];
    const float* bm1  = (const float*)d_in[10];
    const float* Wm2  = (const float*)d_in[11];
    const float* bm2  = (const float*)d_in[12];
    const float* Wh1  = (const float*)d_in[13];
    const float* bh1  = (const float*)d_in[14];
    const float* Wh2  = (const float*)d_in[15];
    const float* bh2  = (const float*)d_in[16];
    const float* Wal  = (const float*)d_in[17];
    const float* bal  = (const float*)d_in[18];
    const float* Wat  = (const float*)d_in[19];
    const float* bat  = (const float*)d_in[20];
    const float* part = (const float*)d_in[21];
    const int* esrc = (const int*)d_in[22];
    const int* edst = (const int*)d_in[23];
    const int* etyp = (const int*)d_in[24];
    const int* trip = (const int*)d_in[25];
    float* out = (float*)d_out;

    void* basep = nullptr;
    cudaGetSymbolAddress(&basep, d_buf);
    float* F = (float*)basep;
    __nv_bfloat16 *pA2, *pB2, *pPreb, *pAlnb, *pWalb, *pSvecb;
    { void* p; cudaGetSymbolAddress(&p, g_A2);    pA2    = (__nv_bfloat16*)p; }
    { void* p; cudaGetSymbolAddress(&p, g_B2);    pB2    = (__nv_bfloat16*)p; }
    { void* p; cudaGetSymbolAddress(&p, g_prebf); pPreb  = (__nv_bfloat16*)p; }
    { void* p; cudaGetSymbolAddress(&p, g_alnbf); pAlnb  = (__nv_bfloat16*)p; }
    { void* p; cudaGetSymbolAddress(&p, g_walb);  pWalb  = (__nv_bfloat16*)p; }
    { void* p; cudaGetSymbolAddress(&p, g_svecb); pSvecb = (__nv_bfloat16*)p; }

    float* pre    = F + O_PRE;
    float* map1   = F + O_MAP1;
    float* mrel   = F + O_MREL;
    float* qrel   = F + O_QREL;
    float* qa     = F + O_QA;
    float* Amat   = F + O_AMAT;
    float* attn   = F + O_ATTN;
    float* rpath  = F + O_RPATH;
    float* giall  = F + O_GIALL;
    float* ghb    = F + O_GHB;
    float* gruh   = F + O_GRUH;
    float* p1     = F + O_P1;
    float* pred   = F + O_PRED;
    float* gh2    = F + O_GH2;
    float* sub    = F + O_SUB;
    float* suba   = F + O_SUBA;
    float* svec   = F + O_SVEC;
    double* acc   = (double*)(F + O_ACC);
    int* ip       = (int*)(F + O_INT);
    int* deg      = ip;
    int* rowptr   = deg + N_ENTC;
    int* cursor   = rowptr + N_ENTC + 1;
    int* csr      = cursor + N_ENTC;
    int* zerolist = csr + NEC;
    int* nzero    = zerolist + N_ENTC;

    // ---- CSR build + aggregation (writes bf16 agg into A2) ----
    k_init<<<(NBC * HC + 255) / 256, 256>>>(deg, cursor, nzero, acc, gruh);
    k_count<<<(NEC + 255) / 256, 256>>>(edst, deg);
    k_scan<<<1, 1024>>>(deg, rowptr);
    k_fill<<<(NEC + 255) / 256, 256>>>(edst, rowptr, cursor, csr);
    k_aggregate<<<N_ENTC, 128>>>(ent, rel, esrc, etyp, rowptr, csr, zerolist, nzero);
    k_entcvt<<<(N_ENTC * HC + 255) / 256, 256>>>(ent);
    k_b2<<<(128 * 256 + 255) / 256, 256>>>(Wn, Wl);
    k_cvt<<<(HC * HC + 255) / 256, 256>>>(Wal, pWalb, HC * HC);

    // pre = rrelu([agg|ent] @ [Wn;Wl]) — ONE bf16 GEMM, K=256, dual output
    {
        dim3 g(1, (N_ENTC + BGM - 1) / BGM);
        k_bgemm<2><<<g, 256>>>(pA2, pB2, nullptr, pre, pPreb, nullptr, nullptr,
                               N_ENTC, HC, 256);
    }
    k_fixzero<<<64, 128>>>(ent, Wev, pre, zerolist, nzero);

    // aln_bf = pre @ Wal^T + bal (bf16 out, only feeds score)
    {
        dim3 g(1, (N_ENTC + BGM - 1) / BGM);
        k_bgemm<1><<<g, 256>>>(pPreb, pWalb, bal, nullptr, pAlnb, nullptr, nullptr,
                               N_ENTC, HC, HC);
    }

    // mapped_rel (fp32 — feeds the precision-sensitive match_loss path)
    launch_gemm(true, 0, rel, Wm1, bm1, nullptr, map1, NRELC, 256, HC, 1.f, 0.f);
    launch_gemm(true, 0, map1, Wm2, bm2, nullptr, mrel, NRELC, HC, 256, 1.f, 0.f);

    // q_rel, A
    k_gather<<<NBC, 128>>>(mrel, trip, 1, qrel);
    launch_gemm(true, 0, qrel, Wat, bat, nullptr, qa, NBC, HC, HC, 1.f, 0.f);
    launch_gemm(true, 0, qa, mrel, nullptr, nullptr, Amat, NBC, NRELC, HC, 1.f, 0.f);

    // hoisted: softmax + rel_path + gi for all 8 timesteps at once
    k_attn<<<NTC * NBC, 512>>>(part, Amat, attn);
    launch_gemm(false, 0, attn, mrel, nullptr, nullptr, rpath, NTC * NBC, HC, NRELC, 1.f, 0.f);
    launch_gemm(true, 0, rpath, wih, bih, nullptr, giall, NTC * NBC, H3C, HC, 1.f, 0.f);

    // sequential GRU: only the h-dependent part
    for (int t = 0; t < NTC; t++) {
        launch_gemm(true, 0, gruh, whh, bhh, nullptr, ghb, NBC, H3C, HC, 1.f, 0.f);
        k_gru<<<(NBC * HC + 255) / 256, 256>>>(giall + (size_t)t * NBC * H3C, ghb, gruh, gruh);
    }

    // predicted_hist + match_loss + gh2
    launch_gemm(true, 0, qrel, Wh1, bh1, nullptr, p1, NBC, HC, HC, 1.f, 0.f);
    launch_gemm(true, 0, p1, Wh2, bh2, qrel, pred, NBC, HC, HC, 0.1f, 1.f);
    k_match<<<128, 256>>>(pred, gruh, acc);
    launch_gemm(true, 0, qrel, wih, bih, nullptr, giall, NBC, H3C, HC, 1.f, 0.f);
    launch_gemm(true, 0, pred, whh, bhh, nullptr, ghb, NBC, H3C, HC, 1.f, 0.f);
    k_gru<<<(NBC * HC + 255) / 256, 256>>>(giall, ghb, pred, gh2);

    // svec = (sub_emb @ W_align^T + b) * gh2   (also bf16 copy)
    k_gather<<<NBC, 128>>>(pre, trip, 0, sub);
    launch_gemm(true, 0, sub, Wal, bal, nullptr, suba, NBC, HC, HC, 1.f, 0.f);
    k_mul<<<(NBC * HC + 255) / 256, 256>>>(suba, gh2, svec, NBC * HC);

    // score: bf16 tensor-core GEMM + fused sigmoid(poly) + loss reduction
    {
        dim3 g((N_ENTC + BGN - 1) / BGN, NBC / BGM);
        k_bgemm<3><<<g, 256>>>(pSvecb, pAlnb, nullptr, out, nullptr, trip, acc,
                               NBC, N_ENTC, HC);
    }
    if (out_size >= NBC * N_ENTC + 2) k_final<<<1, 32>>>(acc, out);
}

// round 6
// speedup vs baseline: 1.7546x; 1.3542x over previous
#include <cuda_runtime.h>
#include <cuda_bf16.h>
#include <stdint.h>
#include <math.h>

#define N_ENTC 20000
#define NRELC  460
#define HC     128
#define NEC    400000
#define NBC    1024
#define NTC    8
#define H3C    384
#define SLOPE  0.22916666666666666f
#define KPRE   384
#define KPAD   480   // padded rel dim for bf16 rpath gemm
#define MT_STR 512   // mrelT fp32 stride

// ---------------- fp32 scratch ----------------
constexpr size_t O_MREL  = 0;                                   // 460*128
constexpr size_t O_MRELT = O_MREL + (size_t)NRELC * HC;         // 128*512
constexpr size_t O_QREL  = O_MRELT + (size_t)HC * MT_STR;       // 1024*128
constexpr size_t O_AMAT  = O_QREL + (size_t)NBC * HC;           // 1024*460
constexpr size_t O_GIALL = O_AMAT + (size_t)NBC * NRELC;        // 9216*384
constexpr size_t O_GRUH  = O_GIALL + (size_t)(NTC + 1) * NBC * H3C;
constexpr size_t O_PRED  = O_GRUH + (size_t)NBC * HC;
constexpr size_t O_GH2   = O_PRED + (size_t)NBC * HC;
constexpr size_t O_WHHT  = O_GH2 + (size_t)NBC * HC;            // 128*384
constexpr size_t O_WH1T  = O_WHHT + 49152;                      // 128*128
constexpr size_t O_WH2T  = O_WH1T + 16384;
constexpr size_t O_WATT  = O_WH2T + 16384;
constexpr size_t O_WALT  = O_WATT + 16384;
constexpr size_t O_WM1T  = O_WALT + 16384;                      // 128*256
constexpr size_t O_WM2T  = O_WM1T + 32768;                      // 256*128
constexpr size_t O_ACC_  = O_WM2T + 32768;
constexpr size_t O_ACC   = (O_ACC_ + 1) & ~(size_t)1;
constexpr size_t O_INT   = O_ACC + 8;
constexpr size_t N_INTS  = (size_t)N_ENTC + (N_ENTC + 1) + N_ENTC + NEC + 8;
constexpr size_t TOTALF  = O_INT + N_INTS;
__device__ __align__(16) float d_buf[TOTALF];

// ---------------- bf16 scratch ----------------
__device__ __align__(16) __nv_bfloat16 g_A2[(size_t)N_ENTC * KPRE];
__device__ __align__(16) __nv_bfloat16 g_B3[HC * KPRE];
__device__ __align__(16) __nv_bfloat16 g_prebf[(size_t)N_ENTC * HC];
__device__ __align__(16) __nv_bfloat16 g_alnbf[(size_t)N_ENTC * HC];
__device__ __align__(16) __nv_bfloat16 g_walb[HC * HC];
__device__ __align__(16) __nv_bfloat16 g_wihb[H3C * HC];
__device__ __align__(16) __nv_bfloat16 g_mrelTb[HC * KPAD];
__device__ __align__(16) __nv_bfloat16 g_Xb[(size_t)(NTC + 1) * NBC * HC];
__device__ __align__(16) __nv_bfloat16 g_attnb[(size_t)NTC * NBC * KPAD];
__device__ __align__(16) __nv_bfloat16 g_svecb[(size_t)NBC * HC];

// ---------------- reductions ----------------
__device__ __forceinline__ float blockReduceSum(float v) {
    __shared__ float sh[32];
    int tid = threadIdx.x;
    __syncthreads();
    #pragma unroll
    for (int o = 16; o > 0; o >>= 1) v += __shfl_xor_sync(0xffffffffu, v, o);
    if ((tid & 31) == 0) sh[tid >> 5] = v;
    __syncthreads();
    float r = 0.f;
    if (tid < 32) {
        int nw = (blockDim.x + 31) >> 5;
        r = (tid < nw) ? sh[tid] : 0.f;
        #pragma unroll
        for (int o = 16; o > 0; o >>= 1) r += __shfl_xor_sync(0xffffffffu, r, o);
    }
    return r;
}
__device__ __forceinline__ float blockReduceMax(float v) {
    __shared__ float sh[32];
    int tid = threadIdx.x;
    __syncthreads();
    #pragma unroll
    for (int o = 16; o > 0; o >>= 1) v = fmaxf(v, __shfl_xor_sync(0xffffffffu, v, o));
    if ((tid & 31) == 0) sh[tid >> 5] = v;
    __syncthreads();
    float r = -3.402823e38f;
    if (tid < 32) {
        int nw = (blockDim.x + 31) >> 5;
        r = (tid < nw) ? sh[tid] : -3.402823e38f;
        #pragma unroll
        for (int o = 16; o > 0; o >>= 1) r = fmaxf(r, __shfl_xor_sync(0xffffffffu, r, o));
    }
    return r;
}

__device__ __forceinline__ void sig_sp(float x, float& sig, float& sp) {
    float ax = fabsf(x);
    if (ax < 0.5f) {
        float x2 = x * x;
        sig = 0.5f + x * (0.25f + x2 * (-0.0208333333f + x2 * 0.0020833333f));
        sp  = 0.69314718f + 0.5f * x
            + x2 * (0.125f + x2 * (-0.0052083333f + x2 * 0.00034722222f));
    } else {
        float e = __expf(-ax);
        sig = (x >= 0.f) ? 1.f / (1.f + e) : e / (1.f + e);
        sp  = fmaxf(x, 0.f) + __logf(1.f + e);
    }
}
__device__ __forceinline__ float sigm(float x) { return 1.f / (1.f + __expf(-x)); }

// ---------------- init: zeros + all weight conversions/transposes ----------------
__global__ void k_init(const float* __restrict__ Wn, const float* __restrict__ Wl,
                       const float* __restrict__ Wev, const float* __restrict__ wih,
                       const float* __restrict__ whh, const float* __restrict__ Wal,
                       const float* __restrict__ Wh1, const float* __restrict__ Wh2,
                       const float* __restrict__ Wat, const float* __restrict__ Wm1,
                       const float* __restrict__ Wm2,
                       int* deg, int* cursor, double* acc, float* gruh, float* F) {
    int i = blockIdx.x * blockDim.x + threadIdx.x;  // grid 640*256 = 163840
    if (i < N_ENTC) { deg[i] = 0; cursor[i] = 0; }
    if (i < NBC * HC) gruh[i] = 0.f;
    if (i == 0) { acc[0] = 0.0; acc[1] = 0.0; acc[2] = 0.0; }
    if (i < HC * KPRE) {  // B3[n*384+k]
        int n = i / KPRE, k = i % KPRE;
        float v = (k < 128) ? Wn[k * 128 + n]
                : (k < 256) ? Wl[(k - 128) * 128 + n]
                            : Wev[(k - 256) * 128 + n];
        g_B3[i] = __float2bfloat16(v);
    }
    if (i < H3C * HC) g_wihb[i] = __float2bfloat16(wih[i]);
    if (i < HC * HC)  g_walb[i] = __float2bfloat16(Wal[i]);
    if (i < HC * H3C) {  // whhT[k*384+j] = whh[j*128+k]
        int k = i / H3C, j = i % H3C;
        F[O_WHHT + i] = whh[j * 128 + k];
    }
    if (i < HC * HC) {
        int k = i / HC, j = i % HC;
        F[O_WH1T + i] = Wh1[j * HC + k];
        F[O_WH2T + i] = Wh2[j * HC + k];
        F[O_WATT + i] = Wat[j * HC + k];
        F[O_WALT + i] = Wal[j * HC + k];
    }
    if (i < 128 * 256) {  // Wm1T[k*256+j2] = Wm1[j2*128+k]
        int k = i / 256, j2 = i % 256;
        F[O_WM1T + i] = Wm1[j2 * 128 + k];
    }
    if (i < 256 * 128) {  // Wm2T[k2*128+j] = Wm2[j*256+k2]
        int k2 = i / 128, j = i % 128;
        F[O_WM2T + i] = Wm2[j * 256 + k2];
    }
    if (i < HC * (KPAD - NRELC)) {  // mrelTb pad cols [460,480)
        int j = i / (KPAD - NRELC), c = NRELC + i % (KPAD - NRELC);
        g_mrelTb[j * KPAD + c] = __float2bfloat16(0.f);
    }
    if (i < HC * (MT_STR - NRELC)) {  // mrelT pad cols [460,512)
        int j = i / (MT_STR - NRELC), c = NRELC + i % (MT_STR - NRELC);
        F[O_MRELT + j * MT_STR + c] = 0.f;
    }
    if (i < NTC * NBC * (KPAD - NRELC)) {  // attnb pad
        int row = i / (KPAD - NRELC), c = NRELC + i % (KPAD - NRELC);
        g_attnb[(size_t)row * KPAD + c] = __float2bfloat16(0.f);
    }
}

__global__ void k_count(const int* __restrict__ dst, int* deg) {
    int e = blockIdx.x * blockDim.x + threadIdx.x;
    if (e < NEC) atomicAdd(&deg[dst[e]], 1);
}

// ent → A2 cols [128,256) masked deg>0, [256,384) masked deg==0
__global__ void k_entcvt(const float* __restrict__ ent, const int* __restrict__ deg) {
    int i = blockIdx.x * blockDim.x + threadIdx.x;
    if (i < N_ENTC * HC) {
        int node = i >> 7, c = i & 127;
        float v = ent[i];
        bool m = deg[node] > 0;
        g_A2[(size_t)node * KPRE + 128 + c] = __float2bfloat16(m ? v : 0.f);
        g_A2[(size_t)node * KPRE + 256 + c] = __float2bfloat16(m ? 0.f : v);
    }
}

// shuffle-based exclusive scan (single block, 1024 threads)
__global__ void k_scan(const int* __restrict__ deg, int* rowptr) {
    __shared__ int wsum[32];
    __shared__ int carry_s;
    int tid = threadIdx.x, lane = tid & 31, wid = tid >> 5;
    if (tid == 0) carry_s = 0;
    __syncthreads();
    for (int base = 0; base < N_ENTC; base += 1024) {
        int i = base + tid;
        int v = (i < N_ENTC) ? deg[i] : 0;
        int x = v;
        #pragma unroll
        for (int o = 1; o < 32; o <<= 1) {
            int t = __shfl_up_sync(0xffffffffu, x, o);
            if (lane >= o) x += t;
        }
        if (lane == 31) wsum[wid] = x;
        __syncthreads();
        if (wid == 0) {
            int s = wsum[lane];
            #pragma unroll
            for (int o = 1; o < 32; o <<= 1) {
                int t = __shfl_up_sync(0xffffffffu, s, o);
                if (lane >= o) s += t;
            }
            wsum[lane] = s;
        }
        __syncthreads();
        int woff = (wid > 0) ? wsum[wid - 1] : 0;
        int incl = x + woff;
        int carry = carry_s;
        if (i < N_ENTC) rowptr[i] = carry + incl - v;
        int total = wsum[31];
        __syncthreads();
        if (tid == 0) carry_s = carry + total;
        __syncthreads();
    }
    if (tid == 0) rowptr[N_ENTC] = carry_s;
}

__global__ void k_fill(const int* __restrict__ dst, const int* __restrict__ rowptr,
                       int* cursor, int* csr) {
    int e = blockIdx.x * blockDim.x + threadIdx.x;
    if (e < NEC) {
        int d = dst[e];
        int p = atomicAdd(&cursor[d], 1);
        csr[rowptr[d] + p] = e;
    }
}

__global__ void k_aggregate(const float* __restrict__ ent, const float* __restrict__ rel,
                            const int* __restrict__ src, const int* __restrict__ typ,
                            const int* __restrict__ rowptr, const int* __restrict__ csr) {
    int node = blockIdx.x;
    int c = threadIdx.x;  // 128
    __shared__ int s_src[512];
    __shared__ int s_typ[512];
    int beg = rowptr[node], end = rowptr[node + 1];
    int deg = end - beg;
    float acc = 0.f;
    for (int base = beg; base < end; base += 512) {
        int cnt = min(512, end - base);
        for (int i = c; i < cnt; i += 128) {
            int e = csr[base + i];
            s_src[i] = src[e] * HC;
            s_typ[i] = typ[e] * HC;
        }
        __syncthreads();
        #pragma unroll 4
        for (int i = 0; i < cnt; i++)
            acc += ent[s_src[i] + c] + rel[s_typ[i] + c];
        __syncthreads();
    }
    float v = (deg > 0) ? acc * (1.0f / (float)deg) : 0.f;
    g_A2[(size_t)node * KPRE + c] = __float2bfloat16(v);
}

// ---------------- bf16 tensor-core GEMM ----------------
// EPI: 1 = bf16 out + bias | 2 = rrelu bf16 out | 3 = score | 4 = fp32 out + bias
#define BGM 128
#define BGN 128
#define BGK 32
#define SSTR 40

template <int EPI>
__global__ __launch_bounds__(256)
void k_bgemm(const __nv_bfloat16* __restrict__ A, const __nv_bfloat16* __restrict__ B,
             const float* __restrict__ bias, float* __restrict__ Cf,
             __nv_bfloat16* __restrict__ Cb, const int* __restrict__ trip,
             double* acc, int M, int N, int K) {
    __shared__ __nv_bfloat16 As[BGM * SSTR];
    __shared__ __nv_bfloat16 Bs[BGN * SSTR];
    int tid = threadIdx.x;
    int lane = tid & 31, wid = tid >> 5;
    int wm = wid & 3, wn = wid >> 2;
    int rowBase = blockIdx.y * BGM;
    int colBase = blockIdx.x * BGN;
    float c[2][8][4];
    #pragma unroll
    for (int i = 0; i < 2; i++)
        #pragma unroll
        for (int j = 0; j < 8; j++)
            #pragma unroll
            for (int q = 0; q < 4; q++) c[i][j][q] = 0.f;

    for (int k0 = 0; k0 < K; k0 += BGK) {
        #pragma unroll
        for (int i = 0; i < 2; i++) {
            int idx = tid + i * 256;
            int r = idx >> 2, seg = idx & 3;
            uint4 va = make_uint4(0, 0, 0, 0);
            int gr = rowBase + r;
            if (gr < M) va = *(const uint4*)(A + (size_t)gr * K + k0 + seg * 8);
            *(uint4*)(As + r * SSTR + seg * 8) = va;
            uint4 vb = make_uint4(0, 0, 0, 0);
            int gn = colBase + r;
            if (gn < N) vb = *(const uint4*)(B + (size_t)gn * K + k0 + seg * 8);
            *(uint4*)(Bs + r * SSTR + seg * 8) = vb;
        }
        __syncthreads();
        #pragma unroll
        for (int kk = 0; kk < BGK; kk += 16) {
            uint32_t a[2][4], b[8][2];
            #pragma unroll
            for (int mt = 0; mt < 2; mt++) {
                int row = wm * 32 + mt * 16 + (lane & 15);
                int col = kk + ((lane >> 4) << 3);
                uint32_t addr = (uint32_t)__cvta_generic_to_shared(As + row * SSTR + col);
                asm volatile("ldmatrix.sync.aligned.m8n8.x4.shared.b16 {%0,%1,%2,%3},[%4];"
                             : "=r"(a[mt][0]), "=r"(a[mt][1]), "=r"(a[mt][2]), "=r"(a[mt][3])
                             : "r"(addr));
            }
            #pragma unroll
            for (int np = 0; np < 4; np++) {
                int nrow = wn * 64 + np * 16 + ((lane >> 4) << 3) + (lane & 7);
                int ncol = kk + (((lane >> 3) & 1) << 3);
                uint32_t addr = (uint32_t)__cvta_generic_to_shared(Bs + nrow * SSTR + ncol);
                asm volatile("ldmatrix.sync.aligned.m8n8.x4.shared.b16 {%0,%1,%2,%3},[%4];"
                             : "=r"(b[2 * np][0]), "=r"(b[2 * np][1]),
                               "=r"(b[2 * np + 1][0]), "=r"(b[2 * np + 1][1])
                             : "r"(addr));
            }
            #pragma unroll
            for (int mt = 0; mt < 2; mt++)
                #pragma unroll
                for (int nt = 0; nt < 8; nt++)
                    asm volatile(
                        "mma.sync.aligned.m16n8k16.row.col.f32.bf16.bf16.f32 "
                        "{%0,%1,%2,%3},{%4,%5,%6,%7},{%8,%9},{%0,%1,%2,%3};"
                        : "+f"(c[mt][nt][0]), "+f"(c[mt][nt][1]),
                          "+f"(c[mt][nt][2]), "+f"(c[mt][nt][3])
                        : "r"(a[mt][0]), "r"(a[mt][1]), "r"(a[mt][2]), "r"(a[mt][3]),
                          "r"(b[nt][0]), "r"(b[nt][1]));
        }
        __syncthreads();
    }

    if (EPI == 3) {
        float lsp = 0.f, lxo = 0.f;
        #pragma unroll
        for (int mt = 0; mt < 2; mt++) {
            int r0 = rowBase + wm * 32 + mt * 16 + (lane >> 2);
            int ob0 = trip[r0 * 3 + 2];
            int ob1 = trip[(r0 + 8) * 3 + 2];
            #pragma unroll
            for (int nt = 0; nt < 8; nt++) {
                int col = colBase + wn * 64 + nt * 8 + ((lane & 3) << 1);
                if (col < N) {
                    #pragma unroll
                    for (int half = 0; half < 2; half++) {
                        int row = r0 + half * 8;
                        int ob = half ? ob1 : ob0;
                        float x0 = c[mt][nt][half * 2 + 0];
                        float x1 = c[mt][nt][half * 2 + 1];
                        float s0, p0, s1, p1;
                        sig_sp(x0, s0, p0);
                        sig_sp(x1, s1, p1);
                        *(float2*)(Cf + (size_t)row * N + col) = make_float2(s0, s1);
                        lsp += p0 + p1;
                        if (col == ob) lxo += x0;
                        if (col + 1 == ob) lxo += x1;
                    }
                }
            }
        }
        float bs = blockReduceSum(lsp);
        float bx = blockReduceSum(lxo);
        if (tid == 0) {
            atomicAdd(&acc[0], (double)bs);
            atomicAdd(&acc[1], (double)bx);
        }
    } else {
        #pragma unroll
        for (int mt = 0; mt < 2; mt++) {
            #pragma unroll
            for (int nt = 0; nt < 8; nt++) {
                int col = colBase + wn * 64 + nt * 8 + ((lane & 3) << 1);
                if (col >= N) continue;
                float b0 = (EPI != 2 && bias) ? bias[col] : 0.f;
                float b1 = (EPI != 2 && bias) ? bias[col + 1] : 0.f;
                #pragma unroll
                for (int half = 0; half < 2; half++) {
                    int row = rowBase + wm * 32 + mt * 16 + (lane >> 2) + half * 8;
                    if (row >= M) continue;
                    float v0 = c[mt][nt][half * 2 + 0] + b0;
                    float v1 = c[mt][nt][half * 2 + 1] + b1;
                    if (EPI == 2) {
                        v0 = (v0 >= 0.f) ? v0 : v0 * SLOPE;
                        v1 = (v1 >= 0.f) ? v1 : v1 * SLOPE;
                    }
                    if (EPI == 4) {
                        *(float2*)(Cf + (size_t)row * N + col) = make_float2(v0, v1);
                    } else {
                        *(__nv_bfloat162*)(Cb + (size_t)row * N + col) =
                            __nv_bfloat162(__float2bfloat16(v0), __float2bfloat16(v1));
                    }
                }
            }
        }
    }
}

// ---------------- fused mapped_rel: rel -> map1 -> mrel (+ transposes) ----------------
__global__ __launch_bounds__(256)
void k_mrel(const float* __restrict__ rel, const float* __restrict__ Wm1T,
            const float* __restrict__ Wm2T, const float* __restrict__ bm1,
            const float* __restrict__ bm2, float* __restrict__ mrel,
            float* __restrict__ mrelT) {
    __shared__ float rels[10][128];
    __shared__ float p1s[10][256];
    int tid = threadIdx.x;
    int r0 = blockIdx.x * 10;  // 46 blocks
    for (int i = tid; i < 10 * 128; i += 256)
        rels[i >> 7][i & 127] = rel[(r0 + (i >> 7)) * 128 + (i & 127)];
    __syncthreads();
    // stage1: p1[r][j2] = rel[r]·Wm1T[:,j2] + bm1
    {
        int j2 = tid;  // 0..255
        float a[10];
        #pragma unroll
        for (int r = 0; r < 10; r++) a[r] = 0.f;
        for (int k = 0; k < 128; k++) {
            float w = Wm1T[k * 256 + j2];
            #pragma unroll
            for (int r = 0; r < 10; r++) a[r] = fmaf(rels[r][k], w, a[r]);
        }
        float b = bm1[j2];
        #pragma unroll
        for (int r = 0; r < 10; r++) p1s[r][j2] = a[r] + b;
    }
    __syncthreads();
    // stage2: mrel[r][j] = p1[r]·Wm2T[:,j] + bm2
    {
        int j = tid & 127, half = tid >> 7;
        float a[5];
        #pragma unroll
        for (int r = 0; r < 5; r++) a[r] = 0.f;
        for (int k = 0; k < 256; k++) {
            float w = Wm2T[k * 128 + j];
            #pragma unroll
            for (int r = 0; r < 5; r++) a[r] = fmaf(p1s[half * 5 + r][k], w, a[r]);
        }
        float b = bm2[j];
        #pragma unroll
        for (int r = 0; r < 5; r++) {
            int row = r0 + half * 5 + r;
            float v = a[r] + b;
            mrel[row * 128 + j] = v;
            mrelT[j * MT_STR + row] = v;
            g_mrelTb[j * KPAD + row] = __float2bfloat16(v);
        }
    }
}

// gather q_rel rows (fp32 + bf16 into X slot 8)
__global__ void k_gather(const float* __restrict__ mrel, const int* __restrict__ trip,
                         float* __restrict__ qrel) {
    int b = blockIdx.x, j = threadIdx.x;
    float v = mrel[(size_t)trip[b * 3 + 1] * HC + j];
    qrel[b * HC + j] = v;
    g_Xb[(size_t)(NTC * NBC + b) * HC + j] = __float2bfloat16(v);
}

// fused qa = lin(qrel, Wat) ; Amat = qa @ mrel^T
__global__ __launch_bounds__(128)
void k_qa_amat(const float* __restrict__ qrel, const float* __restrict__ WatT,
               const float* __restrict__ bat, const float* __restrict__ mrelT,
               float* __restrict__ Amat) {
    __shared__ float q[4][128];
    __shared__ float qa[4][128];
    int j = threadIdx.x;
    int r0 = blockIdx.x * 4;  // 256 blocks
    #pragma unroll
    for (int r = 0; r < 4; r++) q[r][j] = qrel[(r0 + r) * 128 + j];
    __syncthreads();
    {
        float a[4] = {0.f, 0.f, 0.f, 0.f};
        for (int k = 0; k < 128; k++) {
            float w = WatT[k * 128 + j];
            #pragma unroll
            for (int r = 0; r < 4; r++) a[r] = fmaf(q[r][k], w, a[r]);
        }
        float b = bat[j];
        #pragma unroll
        for (int r = 0; r < 4; r++) qa[r][j] = a[r] + b;
    }
    __syncthreads();
    #pragma unroll
    for (int r = 0; r < 4; r++) {
        float a[4] = {0.f, 0.f, 0.f, 0.f};
        for (int k = 0; k < 128; k++) {
            float qv = qa[r][k];
            #pragma unroll
            for (int t = 0; t < 4; t++)
                a[t] = fmaf(qv, mrelT[k * MT_STR + j + t * 128], a[t]);
        }
        #pragma unroll
        for (int t = 0; t < 4; t++) {
            int n = j + t * 128;
            if (n < NRELC) Amat[(size_t)(r0 + r) * NRELC + n] = a[t];
        }
    }
}

// masked softmax -> bf16 padded attn
__global__ void k_attn(const float* __restrict__ part, const float* __restrict__ Amat) {
    int tb = blockIdx.x;
    int t = tb >> 10, b = tb & 1023;
    int tid = threadIdx.x;  // 512
    float x = -3.402823e38f;
    if (tid < NRELC) {
        float cur = part[(size_t)b * (NTC * NRELC) + t * NRELC + tid];
        float a = Amat[(size_t)b * NRELC + tid];
        float val = cur * a;
        x = (val == 0.f) ? -1e9f : val;
    }
    float m = blockReduceMax(x);
    __shared__ float sm_m, sm_inv;
    if (tid == 0) sm_m = m;
    __syncthreads();
    m = sm_m;
    float e = (tid < NRELC) ? __expf(x - m) : 0.f;
    float s = blockReduceSum(e);
    if (tid == 0) sm_inv = 1.f / s;
    __syncthreads();
    float inv = sm_inv;
    if (tid < NRELC)
        g_attnb[(size_t)tb * KPAD + tid] = __float2bfloat16(e * inv);
}

// fused GRU step: gh = h@whh^T + bhh, gates, h' ; optional match-loss accumulation
__global__ __launch_bounds__(128)
void k_grustep(const float* __restrict__ gi_t, const float* __restrict__ whhT,
               const float* __restrict__ bhh, const float* __restrict__ hin,
               float* __restrict__ hout, const float* __restrict__ matchB,
               double* acc, int do_match) {
    __shared__ float hs[8][128];
    int j = threadIdx.x;
    int r0 = blockIdx.x * 8;  // 128 blocks
    #pragma unroll
    for (int r = 0; r < 8; r++) hs[r][j] = hin[(r0 + r) * 128 + j];
    __syncthreads();
    float ar[8], az[8], an[8];
    #pragma unroll
    for (int r = 0; r < 8; r++) { ar[r] = 0.f; az[r] = 0.f; an[r] = 0.f; }
    for (int k = 0; k < 128; k++) {
        float wr = whhT[k * H3C + j];
        float wz = whhT[k * H3C + 128 + j];
        float wn = whhT[k * H3C + 256 + j];
        #pragma unroll
        for (int r = 0; r < 8; r++) {
            float h = hs[r][k];
            ar[r] = fmaf(h, wr, ar[r]);
            az[r] = fmaf(h, wz, az[r]);
            an[r] = fmaf(h, wn, an[r]);
        }
    }
    float br = bhh[j], bz = bhh[128 + j], bn = bhh[256 + j];
    float msum = 0.f;
    #pragma unroll
    for (int r = 0; r < 8; r++) {
        size_t gidx = (size_t)(r0 + r) * H3C;
        float ir = gi_t[gidx + j], iz = gi_t[gidx + 128 + j], inn = gi_t[gidx + 256 + j];
        float rr = sigm(ir + ar[r] + br);
        float zz = sigm(iz + az[r] + bz);
        float nn = tanhf(inn + rr * (an[r] + bn));
        float hold = hs[r][j];
        hout[(r0 + r) * 128 + j] = (1.f - zz) * nn + zz * hold;
        if (do_match) {
            float d = hold - matchB[(r0 + r) * 128 + j];
            msum += d * d;
        }
    }
    if (do_match) {
        float bsum = blockReduceSum(msum);
        if (threadIdx.x == 0) atomicAdd(&acc[2], (double)bsum);
    }
}

// fused predicted_hist: pred = 0.1*lin(lin(qrel,Wh1,bh1),Wh2,bh2) + qrel
__global__ __launch_bounds__(128)
void k_predf(const float* __restrict__ qrel, const float* __restrict__ Wh1T,
             const float* __restrict__ Wh2T, const float* __restrict__ bh1,
             const float* __restrict__ bh2, float* __restrict__ pred) {
    __shared__ float q[8][128];
    __shared__ float p1[8][128];
    int j = threadIdx.x;
    int r0 = blockIdx.x * 8;  // 128 blocks
    #pragma unroll
    for (int r = 0; r < 8; r++) q[r][j] = qrel[(r0 + r) * 128 + j];
    __syncthreads();
    {
        float a[8];
        #pragma unroll
        for (int r = 0; r < 8; r++) a[r] = 0.f;
        for (int k = 0; k < 128; k++) {
            float w = Wh1T[k * 128 + j];
            #pragma unroll
            for (int r = 0; r < 8; r++) a[r] = fmaf(q[r][k], w, a[r]);
        }
        float b = bh1[j];
        #pragma unroll
        for (int r = 0; r < 8; r++) p1[r][j] = a[r] + b;
    }
    __syncthreads();
    {
        float a[8];
        #pragma unroll
        for (int r = 0; r < 8; r++) a[r] = 0.f;
        for (int k = 0; k < 128; k++) {
            float w = Wh2T[k * 128 + j];
            #pragma unroll
            for (int r = 0; r < 8; r++) a[r] = fmaf(p1[r][k], w, a[r]);
        }
        float b = bh2[j];
        #pragma unroll
        for (int r = 0; r < 8; r++)
            pred[(r0 + r) * 128 + j] = 0.1f * (a[r] + b) + q[r][j];
    }
}

// fused svec = (pre[trip0] @ Wal^T + bal) * gh2  -> bf16
__global__ __launch_bounds__(128)
void k_svec(const int* __restrict__ trip, const float* __restrict__ WalT,
            const float* __restrict__ bal, const float* __restrict__ gh2) {
    __shared__ float s[8][128];
    int j = threadIdx.x;
    int r0 = blockIdx.x * 8;  // 128 blocks
    #pragma unroll
    for (int r = 0; r < 8; r++) {
        int row = trip[(r0 + r) * 3 + 0];
        s[r][j] = __bfloat162float(g_prebf[(size_t)row * HC + j]);
    }
    __syncthreads();
    float a[8];
    #pragma unroll
    for (int r = 0; r < 8; r++) a[r] = 0.f;
    for (int k = 0; k < 128; k++) {
        float w = WalT[k * 128 + j];
        #pragma unroll
        for (int r = 0; r < 8; r++) a[r] = fmaf(s[r][k], w, a[r]);
    }
    float b = bal[j];
    #pragma unroll
    for (int r = 0; r < 8; r++) {
        float v = (a[r] + b) * gh2[(r0 + r) * 128 + j];
        g_svecb[(r0 + r) * 128 + j] = __float2bfloat16(v);
    }
}

__global__ void k_final(const double* __restrict__ acc, float* __restrict__ out) {
    if (threadIdx.x == 0) {
        out[(size_t)NBC * N_ENTC]     = (float)(acc[2] / (double)(NBC * HC));
        out[(size_t)NBC * N_ENTC + 1] = (float)((acc[0] - acc[1]) /
                                                ((double)NBC * (double)N_ENTC));
    }
}

// ---------------- host ----------------
extern "C" void kernel_launch(void* const* d_in, const int* in_sizes, int n_in,
                              void* d_out, int out_size) {
    const float* ent  = (const float*)d_in[0];
    const float* rel  = (const float*)d_in[1];
    const float* Wn   = (const float*)d_in[2];
    const float* Wl   = (const float*)d_in[3];
    const float* Wev  = (const float*)d_in[4];
    const float* wih  = (const float*)d_in[5];
    const float* whh  = (const float*)d_in[6];
    const float* bih  = (const float*)d_in[7];
    const float* bhh  = (const float*)d_in[8];
    const float* Wm1  = (const float*)d_in[9];
    const float* bm1  = (const float*)d_in[10];
    const float* Wm2  = (const float*)d_in[11];
    const float* bm2  = (const float*)d_in[12];
    const float* Wh1  = (const float*)d_in[13];
    const float* bh1  = (const float*)d_in[14];
    const float* Wh2  = (const float*)d_in[15];
    const float* bh2  = (const float*)d_in[16];
    const float* Wal  = (const float*)d_in[17];
    const float* bal  = (const float*)d_in[18];
    const float* Wat  = (const float*)d_in[19];
    const float* bat  = (const float*)d_in[20];
    const float* part = (const float*)d_in[21];
    const int* esrc = (const int*)d_in[22];
    const int* edst = (const int*)d_in[23];
    const int* etyp = (const int*)d_in[24];
    const int* trip = (const int*)d_in[25];
    float* out = (float*)d_out;

    void* basep = nullptr;
    cudaGetSymbolAddress(&basep, d_buf);
    float* F = (float*)basep;
    __nv_bfloat16 *pA2, *pB3, *pPreb, *pAlnb, *pWalb, *pWihb, *pMrelTb, *pXb, *pAttnb, *pSvecb;
    { void* p; cudaGetSymbolAddress(&p, g_A2);     pA2     = (__nv_bfloat16*)p; }
    { void* p; cudaGetSymbolAddress(&p, g_B3);     pB3     = (__nv_bfloat16*)p; }
    { void* p; cudaGetSymbolAddress(&p, g_prebf);  pPreb   = (__nv_bfloat16*)p; }
    { void* p; cudaGetSymbolAddress(&p, g_alnbf);  pAlnb   = (__nv_bfloat16*)p; }
    { void* p; cudaGetSymbolAddress(&p, g_walb);   pWalb   = (__nv_bfloat16*)p; }
    { void* p; cudaGetSymbolAddress(&p, g_wihb);   pWihb   = (__nv_bfloat16*)p; }
    { void* p; cudaGetSymbolAddress(&p, g_mrelTb); pMrelTb = (__nv_bfloat16*)p; }
    { void* p; cudaGetSymbolAddress(&p, g_Xb);     pXb     = (__nv_bfloat16*)p; }
    { void* p; cudaGetSymbolAddress(&p, g_attnb);  pAttnb  = (__nv_bfloat16*)p; }
    { void* p; cudaGetSymbolAddress(&p, g_svecb);  pSvecb  = (__nv_bfloat16*)p; }

    float* mrel   = F + O_MREL;
    float* mrelT  = F + O_MRELT;
    float* qrel   = F + O_QREL;
    float* Amat   = F + O_AMAT;
    float* giall  = F + O_GIALL;
    float* gruh   = F + O_GRUH;
    float* pred   = F + O_PRED;
    float* gh2    = F + O_GH2;
    float* whhT   = F + O_WHHT;
    float* Wh1T   = F + O_WH1T;
    float* Wh2T   = F + O_WH2T;
    float* WatT   = F + O_WATT;
    float* WalT   = F + O_WALT;
    float* Wm1T   = F + O_WM1T;
    float* Wm2T   = F + O_WM2T;
    double* acc   = (double*)(F + O_ACC);
    int* deg      = (int*)(F + O_INT);
    int* rowptr   = deg + N_ENTC;
    int* cursor   = rowptr + N_ENTC + 1;
    int* csr      = cursor + N_ENTC;

    // 1: init (zeros, conversions, transposes, pads)
    k_init<<<640, 256>>>(Wn, Wl, Wev, wih, whh, Wal, Wh1, Wh2, Wat, Wm1, Wm2,
                         deg, cursor, acc, gruh, F);
    // 2-6: CSR + aggregate
    k_count<<<(NEC + 255) / 256, 256>>>(edst, deg);
    k_entcvt<<<(N_ENTC * HC + 255) / 256, 256>>>(ent, deg);
    k_scan<<<1, 1024>>>(deg, rowptr);
    k_fill<<<(NEC + 255) / 256, 256>>>(edst, rowptr, cursor, csr);
    k_aggregate<<<N_ENTC, 128>>>(ent, rel, esrc, etyp, rowptr, csr);
    // 7: pre = rrelu([aggS|ent·m|ent·(1-m)] @ [Wn;Wl;Wev])  (K=384, bf16 out)
    {
        dim3 g(1, (N_ENTC + BGM - 1) / BGM);
        k_bgemm<2><<<g, 256>>>(pA2, pB3, nullptr, nullptr, pPreb, nullptr, nullptr,
                               N_ENTC, HC, KPRE);
    }
    // 8: aln
    {
        dim3 g(1, (N_ENTC + BGM - 1) / BGM);
        k_bgemm<1><<<g, 256>>>(pPreb, pWalb, bal, nullptr, pAlnb, nullptr, nullptr,
                               N_ENTC, HC, HC);
    }
    // 9-12: mapped_rel chain + attention matrix + softmax
    k_mrel<<<46, 256>>>(rel, Wm1T, Wm2T, bm1, bm2, mrel, mrelT);
    k_gather<<<NBC, 128>>>(mrel, trip, qrel);
    k_qa_amat<<<256, 128>>>(qrel, WatT, bat, mrelT, Amat);
    k_attn<<<NTC * NBC, 512>>>(part, Amat);
    // 13: rpath (bf16) -> X rows [0, 8192)
    {
        dim3 g(1, NTC * NBC / BGM);
        k_bgemm<1><<<g, 256>>>(pAttnb, pMrelTb, nullptr, nullptr, pXb, nullptr, nullptr,
                               NTC * NBC, HC, KPAD);
    }
    // 14: giall = X @ wih^T + bih (fp32 out), M=9216 (8 timesteps + qrel)
    {
        dim3 g(H3C / BGN, (NTC + 1) * NBC / BGM);
        k_bgemm<4><<<g, 256>>>(pXb, pWihb, bih, giall, nullptr, nullptr, nullptr,
                               (NTC + 1) * NBC, H3C, HC);
    }
    // 15-22: sequential fused GRU steps
    for (int t = 0; t < NTC; t++)
        k_grustep<<<128, 128>>>(giall + (size_t)t * NBC * H3C, whhT, bhh,
                                gruh, gruh, nullptr, acc, 0);
    // 23: predicted_hist
    k_predf<<<128, 128>>>(qrel, Wh1T, Wh2T, bh1, bh2, pred);
    // 24: gh2 = GRU(qrel->gi slot 8, pred) + match_loss(pred, gruh)
    k_grustep<<<128, 128>>>(giall + (size_t)NTC * NBC * H3C, whhT, bhh,
                            pred, gh2, gruh, acc, 1);
    // 25: svec (gather + align + mul, bf16 out)
    k_svec<<<128, 128>>>(trip, WalT, bal, gh2);
    // 26: score + fused loss
    {
        dim3 g((N_ENTC + BGN - 1) / BGN, NBC / BGM);
        k_bgemm<3><<<g, 256>>>(pSvecb, pAlnb, nullptr, out, nullptr, trip, acc,
                               NBC, N_ENTC, HC);
    }
    // 27: finalize
    if (out_size >= NBC * N_ENTC + 2) k_final<<<1, 32>>>(acc, out);
}

// round 7
// speedup vs baseline: 2.1929x; 1.2498x over previous
#include <cuda_runtime.h>
#include <cuda_bf16.h>
#include <stdint.h>
#include <math.h>

#define N_ENTC 20000
#define NRELC  460
#define HC     128
#define NEC    400000
#define NBC    1024
#define NTC    8
#define H3C    384
#define SLOPE  0.22916666666666666f
#define KPRE   384
#define KPAD   480
#define MT_STR 512

// ---------------- fp32 scratch ----------------
constexpr size_t O_MREL  = 0;
constexpr size_t O_MRELT = O_MREL + (size_t)NRELC * HC;
constexpr size_t O_QREL  = O_MRELT + (size_t)HC * MT_STR;
constexpr size_t O_AMAT  = O_QREL + (size_t)NBC * HC;
constexpr size_t O_GIALL = O_AMAT + (size_t)NBC * NRELC;
constexpr size_t O_WHHT  = O_GIALL + (size_t)(NTC + 1) * NBC * H3C;
constexpr size_t O_WH1T  = O_WHHT + 49152;
constexpr size_t O_WH2T  = O_WH1T + 16384;
constexpr size_t O_WATT  = O_WH2T + 16384;
constexpr size_t O_WALT  = O_WATT + 16384;
constexpr size_t O_WM1T  = O_WALT + 16384;
constexpr size_t O_WM2T  = O_WM1T + 32768;
constexpr size_t O_ACC_  = O_WM2T + 32768;
constexpr size_t O_ACC   = (O_ACC_ + 1) & ~(size_t)1;
constexpr size_t O_INT   = O_ACC + 8;
constexpr size_t N_INTS  = (size_t)N_ENTC + (N_ENTC + 1) + N_ENTC + NEC + 64;
constexpr size_t TOTALF  = O_INT + N_INTS;
__device__ __align__(16) float d_buf[TOTALF];

// ---------------- bf16 scratch ----------------
__device__ __align__(16) __nv_bfloat16 g_A2[(size_t)N_ENTC * KPRE];
__device__ __align__(16) __nv_bfloat16 g_B3[HC * KPRE];
__device__ __align__(16) __nv_bfloat16 g_prebf[(size_t)N_ENTC * HC];
__device__ __align__(16) __nv_bfloat16 g_alnbf[(size_t)N_ENTC * HC];
__device__ __align__(16) __nv_bfloat16 g_walb[HC * HC];
__device__ __align__(16) __nv_bfloat16 g_wihb[H3C * HC];
__device__ __align__(16) __nv_bfloat16 g_mrelTb[HC * KPAD];
__device__ __align__(16) __nv_bfloat16 g_Xb[(size_t)(NTC + 1) * NBC * HC];
__device__ __align__(16) __nv_bfloat16 g_attnb[(size_t)NTC * NBC * KPAD];
__device__ __align__(16) __nv_bfloat16 g_svecb[(size_t)NBC * HC];

// ---------------- reductions ----------------
__device__ __forceinline__ float blockReduceSum(float v) {
    __shared__ float sh[32];
    int tid = threadIdx.x;
    __syncthreads();
    #pragma unroll
    for (int o = 16; o > 0; o >>= 1) v += __shfl_xor_sync(0xffffffffu, v, o);
    if ((tid & 31) == 0) sh[tid >> 5] = v;
    __syncthreads();
    float r = 0.f;
    if (tid < 32) {
        int nw = (blockDim.x + 31) >> 5;
        r = (tid < nw) ? sh[tid] : 0.f;
        #pragma unroll
        for (int o = 16; o > 0; o >>= 1) r += __shfl_xor_sync(0xffffffffu, r, o);
    }
    return r;
}
__device__ __forceinline__ float blockReduceMax(float v) {
    __shared__ float sh[32];
    int tid = threadIdx.x;
    __syncthreads();
    #pragma unroll
    for (int o = 16; o > 0; o >>= 1) v = fmaxf(v, __shfl_xor_sync(0xffffffffu, v, o));
    if ((tid & 31) == 0) sh[tid >> 5] = v;
    __syncthreads();
    float r = -3.402823e38f;
    if (tid < 32) {
        int nw = (blockDim.x + 31) >> 5;
        r = (tid < nw) ? sh[tid] : -3.402823e38f;
        #pragma unroll
        for (int o = 16; o > 0; o >>= 1) r = fmaxf(r, __shfl_xor_sync(0xffffffffu, r, o));
    }
    return r;
}

__device__ __forceinline__ void sig_sp(float x, float& sig, float& sp) {
    float ax = fabsf(x);
    if (ax < 0.5f) {
        float x2 = x * x;
        sig = 0.5f + x * (0.25f + x2 * (-0.0208333333f + x2 * 0.0020833333f));
        sp  = 0.69314718f + 0.5f * x
            + x2 * (0.125f + x2 * (-0.0052083333f + x2 * 0.00034722222f));
    } else {
        float e = __expf(-ax);
        sig = (x >= 0.f) ? 1.f / (1.f + e) : e / (1.f + e);
        sp  = fmaxf(x, 0.f) + __logf(1.f + e);
    }
}
__device__ __forceinline__ float sigm(float x) { return 1.f / (1.f + __expf(-x)); }

// ---------------- init ----------------
__global__ void k_init(const float* __restrict__ Wn, const float* __restrict__ Wl,
                       const float* __restrict__ Wev, const float* __restrict__ wih,
                       const float* __restrict__ whh, const float* __restrict__ Wal,
                       const float* __restrict__ Wh1, const float* __restrict__ Wh2,
                       const float* __restrict__ Wat, const float* __restrict__ Wm1,
                       const float* __restrict__ Wm2,
                       int* deg, int* cursor, double* acc, float* F) {
    int i = blockIdx.x * blockDim.x + threadIdx.x;  // grid 640*256
    if (i < N_ENTC) { deg[i] = 0; cursor[i] = 0; }
    if (i == 0) { acc[0] = 0.0; acc[1] = 0.0; acc[2] = 0.0; }
    if (i < HC * KPRE) {
        int n = i / KPRE, k = i % KPRE;
        float v = (k < 128) ? Wn[k * 128 + n]
                : (k < 256) ? Wl[(k - 128) * 128 + n]
                            : Wev[(k - 256) * 128 + n];
        g_B3[i] = __float2bfloat16(v);
    }
    if (i < H3C * HC) g_wihb[i] = __float2bfloat16(wih[i]);
    if (i < HC * HC)  g_walb[i] = __float2bfloat16(Wal[i]);
    if (i < HC * H3C) {
        int k = i / H3C, j = i % H3C;
        F[O_WHHT + i] = whh[j * 128 + k];
    }
    if (i < HC * HC) {
        int k = i / HC, j = i % HC;
        F[O_WH1T + i] = Wh1[j * HC + k];
        F[O_WH2T + i] = Wh2[j * HC + k];
        F[O_WATT + i] = Wat[j * HC + k];
        F[O_WALT + i] = Wal[j * HC + k];
    }
    if (i < 128 * 256) {
        int k = i / 256, j2 = i % 256;
        F[O_WM1T + i] = Wm1[j2 * 128 + k];
    }
    if (i < 256 * 128) {
        int k2 = i / 128, j = i % 128;
        F[O_WM2T + i] = Wm2[j * 256 + k2];
    }
    if (i < HC * (KPAD - NRELC)) {
        int j = i / (KPAD - NRELC), c = NRELC + i % (KPAD - NRELC);
        g_mrelTb[j * KPAD + c] = __float2bfloat16(0.f);
    }
    if (i < HC * (MT_STR - NRELC)) {
        int j = i / (MT_STR - NRELC), c = NRELC + i % (MT_STR - NRELC);
        F[O_MRELT + j * MT_STR + c] = 0.f;
    }
    if (i < NTC * NBC * (KPAD - NRELC)) {
        int row = i / (KPAD - NRELC), c = NRELC + i % (KPAD - NRELC);
        g_attnb[(size_t)row * KPAD + c] = __float2bfloat16(0.f);
    }
}

__global__ void k_count(const int* __restrict__ dst, int* deg) {
    int e = blockIdx.x * blockDim.x + threadIdx.x;
    if (e < NEC) atomicAdd(&deg[dst[e]], 1);
}

__global__ void k_entcvt(const float* __restrict__ ent, const int* __restrict__ deg) {
    int i = blockIdx.x * blockDim.x + threadIdx.x;
    if (i < N_ENTC * HC) {
        int node = i >> 7, c = i & 127;
        float v = ent[i];
        bool m = deg[node] > 0;
        g_A2[(size_t)node * KPRE + 128 + c] = __float2bfloat16(m ? v : 0.f);
        g_A2[(size_t)node * KPRE + 256 + c] = __float2bfloat16(m ? 0.f : v);
    }
}

// parallel scan: stage A (20 blocks local scan) + stage B (offset fix)
__global__ void k_scanA(const int* __restrict__ deg, int* rowptr, int* bsums) {
    __shared__ int wsum[32];
    int tid = threadIdx.x, lane = tid & 31, wid = tid >> 5;
    int i = blockIdx.x * 1024 + tid;
    int v = (i < N_ENTC) ? deg[i] : 0;
    int x = v;
    #pragma unroll
    for (int o = 1; o < 32; o <<= 1) {
        int t = __shfl_up_sync(0xffffffffu, x, o);
        if (lane >= o) x += t;
    }
    if (lane == 31) wsum[wid] = x;
    __syncthreads();
    if (wid == 0) {
        int s = wsum[lane];
        #pragma unroll
        for (int o = 1; o < 32; o <<= 1) {
            int t = __shfl_up_sync(0xffffffffu, s, o);
            if (lane >= o) s += t;
        }
        wsum[lane] = s;
    }
    __syncthreads();
    int woff = (wid > 0) ? wsum[wid - 1] : 0;
    int incl = x + woff;
    if (i < N_ENTC) rowptr[i] = incl - v;   // local exclusive
    if (tid == 1023) bsums[blockIdx.x] = incl;
}

__global__ void k_scanB(int* rowptr, const int* __restrict__ bsums, int nblk) {
    __shared__ int offs[32];
    __shared__ int total_s;
    int tid = threadIdx.x;
    if (tid < 32) {
        int v = (tid < nblk) ? bsums[tid] : 0;
        int x = v;
        #pragma unroll
        for (int o = 1; o < 32; o <<= 1) {
            int t = __shfl_up_sync(0xffffffffu, x, o);
            if (tid >= o) x += t;
        }
        offs[tid] = x - v;  // exclusive
        if (tid == 31) total_s = x;
    }
    __syncthreads();
    for (int i = tid; i < N_ENTC; i += blockDim.x)
        rowptr[i] += offs[i >> 10];
    if (tid == 0) rowptr[N_ENTC] = total_s;
}

__global__ void k_fill(const int* __restrict__ dst, const int* __restrict__ rowptr,
                       int* cursor, int* csr) {
    int e = blockIdx.x * blockDim.x + threadIdx.x;
    if (e < NEC) {
        int d = dst[e];
        int p = atomicAdd(&cursor[d], 1);
        csr[rowptr[d] + p] = e;
    }
}

__global__ void k_aggregate(const float* __restrict__ ent, const float* __restrict__ rel,
                            const int* __restrict__ src, const int* __restrict__ typ,
                            const int* __restrict__ rowptr, const int* __restrict__ csr) {
    int node = blockIdx.x;
    int c = threadIdx.x;  // 128
    __shared__ int s_src[512];
    __shared__ int s_typ[512];
    int beg = rowptr[node], end = rowptr[node + 1];
    int deg = end - beg;
    float acc = 0.f;
    for (int base = beg; base < end; base += 512) {
        int cnt = min(512, end - base);
        for (int i = c; i < cnt; i += 128) {
            int e = csr[base + i];
            s_src[i] = src[e] * HC;
            s_typ[i] = typ[e] * HC;
        }
        __syncthreads();
        #pragma unroll 4
        for (int i = 0; i < cnt; i++)
            acc += ent[s_src[i] + c] + rel[s_typ[i] + c];
        __syncthreads();
    }
    float v = (deg > 0) ? acc * (1.0f / (float)deg) : 0.f;
    g_A2[(size_t)node * KPRE + c] = __float2bfloat16(v);
}

// ---------------- bf16 tensor-core GEMM ----------------
#define BGM 128
#define BGN 128
#define BGK 32
#define SSTR 40

template <int EPI>
__global__ __launch_bounds__(256)
void k_bgemm(const __nv_bfloat16* __restrict__ A, const __nv_bfloat16* __restrict__ B,
             const float* __restrict__ bias, float* __restrict__ Cf,
             __nv_bfloat16* __restrict__ Cb, const int* __restrict__ trip,
             double* acc, int M, int N, int K) {
    __shared__ __nv_bfloat16 As[BGM * SSTR];
    __shared__ __nv_bfloat16 Bs[BGN * SSTR];
    int tid = threadIdx.x;
    int lane = tid & 31, wid = tid >> 5;
    int wm = wid & 3, wn = wid >> 2;
    int rowBase = blockIdx.y * BGM;
    int colBase = blockIdx.x * BGN;
    float c[2][8][4];
    #pragma unroll
    for (int i = 0; i < 2; i++)
        #pragma unroll
        for (int j = 0; j < 8; j++)
            #pragma unroll
            for (int q = 0; q < 4; q++) c[i][j][q] = 0.f;

    for (int k0 = 0; k0 < K; k0 += BGK) {
        #pragma unroll
        for (int i = 0; i < 2; i++) {
            int idx = tid + i * 256;
            int r = idx >> 2, seg = idx & 3;
            uint4 va = make_uint4(0, 0, 0, 0);
            int gr = rowBase + r;
            if (gr < M) va = *(const uint4*)(A + (size_t)gr * K + k0 + seg * 8);
            *(uint4*)(As + r * SSTR + seg * 8) = va;
            uint4 vb = make_uint4(0, 0, 0, 0);
            int gn = colBase + r;
            if (gn < N) vb = *(const uint4*)(B + (size_t)gn * K + k0 + seg * 8);
            *(uint4*)(Bs + r * SSTR + seg * 8) = vb;
        }
        __syncthreads();
        #pragma unroll
        for (int kk = 0; kk < BGK; kk += 16) {
            uint32_t a[2][4], b[8][2];
            #pragma unroll
            for (int mt = 0; mt < 2; mt++) {
                int row = wm * 32 + mt * 16 + (lane & 15);
                int col = kk + ((lane >> 4) << 3);
                uint32_t addr = (uint32_t)__cvta_generic_to_shared(As + row * SSTR + col);
                asm volatile("ldmatrix.sync.aligned.m8n8.x4.shared.b16 {%0,%1,%2,%3},[%4];"
                             : "=r"(a[mt][0]), "=r"(a[mt][1]), "=r"(a[mt][2]), "=r"(a[mt][3])
                             : "r"(addr));
            }
            #pragma unroll
            for (int np = 0; np < 4; np++) {
                int nrow = wn * 64 + np * 16 + ((lane >> 4) << 3) + (lane & 7);
                int ncol = kk + (((lane >> 3) & 1) << 3);
                uint32_t addr = (uint32_t)__cvta_generic_to_shared(Bs + nrow * SSTR + ncol);
                asm volatile("ldmatrix.sync.aligned.m8n8.x4.shared.b16 {%0,%1,%2,%3},[%4];"
                             : "=r"(b[2 * np][0]), "=r"(b[2 * np][1]),
                               "=r"(b[2 * np + 1][0]), "=r"(b[2 * np + 1][1])
                             : "r"(addr));
            }
            #pragma unroll
            for (int mt = 0; mt < 2; mt++)
                #pragma unroll
                for (int nt = 0; nt < 8; nt++)
                    asm volatile(
                        "mma.sync.aligned.m16n8k16.row.col.f32.bf16.bf16.f32 "
                        "{%0,%1,%2,%3},{%4,%5,%6,%7},{%8,%9},{%0,%1,%2,%3};"
                        : "+f"(c[mt][nt][0]), "+f"(c[mt][nt][1]),
                          "+f"(c[mt][nt][2]), "+f"(c[mt][nt][3])
                        : "r"(a[mt][0]), "r"(a[mt][1]), "r"(a[mt][2]), "r"(a[mt][3]),
                          "r"(b[nt][0]), "r"(b[nt][1]));
        }
        __syncthreads();
    }

    if (EPI == 3) {
        float lsp = 0.f, lxo = 0.f;
        #pragma unroll
        for (int mt = 0; mt < 2; mt++) {
            int r0 = rowBase + wm * 32 + mt * 16 + (lane >> 2);
            int ob0 = trip[r0 * 3 + 2];
            int ob1 = trip[(r0 + 8) * 3 + 2];
            #pragma unroll
            for (int nt = 0; nt < 8; nt++) {
                int col = colBase + wn * 64 + nt * 8 + ((lane & 3) << 1);
                if (col < N) {
                    #pragma unroll
                    for (int half = 0; half < 2; half++) {
                        int row = r0 + half * 8;
                        int ob = half ? ob1 : ob0;
                        float x0 = c[mt][nt][half * 2 + 0];
                        float x1 = c[mt][nt][half * 2 + 1];
                        float s0, p0, s1, p1;
                        sig_sp(x0, s0, p0);
                        sig_sp(x1, s1, p1);
                        *(float2*)(Cf + (size_t)row * N + col) = make_float2(s0, s1);
                        lsp += p0 + p1;
                        if (col == ob) lxo += x0;
                        if (col + 1 == ob) lxo += x1;
                    }
                }
            }
        }
        float bs = blockReduceSum(lsp);
        float bx = blockReduceSum(lxo);
        if (tid == 0) {
            atomicAdd(&acc[0], (double)bs);
            atomicAdd(&acc[1], (double)bx);
        }
    } else {
        #pragma unroll
        for (int mt = 0; mt < 2; mt++) {
            #pragma unroll
            for (int nt = 0; nt < 8; nt++) {
                int col = colBase + wn * 64 + nt * 8 + ((lane & 3) << 1);
                if (col >= N) continue;
                float b0 = (EPI != 2 && bias) ? bias[col] : 0.f;
                float b1 = (EPI != 2 && bias) ? bias[col + 1] : 0.f;
                #pragma unroll
                for (int half = 0; half < 2; half++) {
                    int row = rowBase + wm * 32 + mt * 16 + (lane >> 2) + half * 8;
                    if (row >= M) continue;
                    float v0 = c[mt][nt][half * 2 + 0] + b0;
                    float v1 = c[mt][nt][half * 2 + 1] + b1;
                    if (EPI == 2) {
                        v0 = (v0 >= 0.f) ? v0 : v0 * SLOPE;
                        v1 = (v1 >= 0.f) ? v1 : v1 * SLOPE;
                    }
                    if (EPI == 4) {
                        *(float2*)(Cf + (size_t)row * N + col) = make_float2(v0, v1);
                    } else {
                        *(__nv_bfloat162*)(Cb + (size_t)row * N + col) =
                            __nv_bfloat162(__float2bfloat16(v0), __float2bfloat16(v1));
                    }
                }
            }
        }
    }
}

// ---------------- fused mapped_rel ----------------
__global__ __launch_bounds__(256)
void k_mrel(const float* __restrict__ rel, const float* __restrict__ Wm1T,
            const float* __restrict__ Wm2T, const float* __restrict__ bm1,
            const float* __restrict__ bm2, float* __restrict__ mrel,
            float* __restrict__ mrelT) {
    __shared__ float rels[10][128];
    __shared__ float p1s[10][256];
    int tid = threadIdx.x;
    int r0 = blockIdx.x * 10;  // 46 blocks
    for (int i = tid; i < 10 * 128; i += 256)
        rels[i >> 7][i & 127] = rel[(r0 + (i >> 7)) * 128 + (i & 127)];
    __syncthreads();
    {
        int j2 = tid;
        float a[10];
        #pragma unroll
        for (int r = 0; r < 10; r++) a[r] = 0.f;
        for (int k = 0; k < 128; k++) {
            float w = Wm1T[k * 256 + j2];
            #pragma unroll
            for (int r = 0; r < 10; r++) a[r] = fmaf(rels[r][k], w, a[r]);
        }
        float b = bm1[j2];
        #pragma unroll
        for (int r = 0; r < 10; r++) p1s[r][j2] = a[r] + b;
    }
    __syncthreads();
    {
        int j = tid & 127, half = tid >> 7;
        float a[5];
        #pragma unroll
        for (int r = 0; r < 5; r++) a[r] = 0.f;
        for (int k = 0; k < 256; k++) {
            float w = Wm2T[k * 128 + j];
            #pragma unroll
            for (int r = 0; r < 5; r++) a[r] = fmaf(p1s[half * 5 + r][k], w, a[r]);
        }
        float b = bm2[j];
        #pragma unroll
        for (int r = 0; r < 5; r++) {
            int row = r0 + half * 5 + r;
            float v = a[r] + b;
            mrel[row * 128 + j] = v;
            mrelT[j * MT_STR + row] = v;
            g_mrelTb[j * KPAD + row] = __float2bfloat16(v);
        }
    }
}

// fused: gather q_rel (fp32 + bf16 slot8) + qa + Amat
__global__ __launch_bounds__(128)
void k_qa_amat(const float* __restrict__ mrel, const int* __restrict__ trip,
               const float* __restrict__ WatT, const float* __restrict__ bat,
               const float* __restrict__ mrelT, float* __restrict__ qrel,
               float* __restrict__ Amat) {
    __shared__ float q[4][128];
    __shared__ float qa[4][128];
    int j = threadIdx.x;
    int r0 = blockIdx.x * 4;  // 256 blocks
    #pragma unroll
    for (int r = 0; r < 4; r++) {
        float v = mrel[(size_t)trip[(r0 + r) * 3 + 1] * HC + j];
        q[r][j] = v;
        qrel[(r0 + r) * 128 + j] = v;
        g_Xb[(size_t)(NTC * NBC + r0 + r) * HC + j] = __float2bfloat16(v);
    }
    __syncthreads();
    {
        float a[4] = {0.f, 0.f, 0.f, 0.f};
        for (int k = 0; k < 128; k++) {
            float w = WatT[k * 128 + j];
            #pragma unroll
            for (int r = 0; r < 4; r++) a[r] = fmaf(q[r][k], w, a[r]);
        }
        float b = bat[j];
        #pragma unroll
        for (int r = 0; r < 4; r++) qa[r][j] = a[r] + b;
    }
    __syncthreads();
    #pragma unroll
    for (int r = 0; r < 4; r++) {
        float a[4] = {0.f, 0.f, 0.f, 0.f};
        for (int k = 0; k < 128; k++) {
            float qv = qa[r][k];
            #pragma unroll
            for (int t = 0; t < 4; t++)
                a[t] = fmaf(qv, mrelT[k * MT_STR + j + t * 128], a[t]);
        }
        #pragma unroll
        for (int t = 0; t < 4; t++) {
            int n = j + t * 128;
            if (n < NRELC) Amat[(size_t)(r0 + r) * NRELC + n] = a[t];
        }
    }
}

__global__ void k_attn(const float* __restrict__ part, const float* __restrict__ Amat) {
    int tb = blockIdx.x;
    int t = tb >> 10, b = tb & 1023;
    int tid = threadIdx.x;  // 512
    float x = -3.402823e38f;
    if (tid < NRELC) {
        float cur = part[(size_t)b * (NTC * NRELC) + t * NRELC + tid];
        float a = Amat[(size_t)b * NRELC + tid];
        float val = cur * a;
        x = (val == 0.f) ? -1e9f : val;
    }
    float m = blockReduceMax(x);
    __shared__ float sm_m, sm_inv;
    if (tid == 0) sm_m = m;
    __syncthreads();
    m = sm_m;
    float e = (tid < NRELC) ? __expf(x - m) : 0.f;
    float s = blockReduceSum(e);
    if (tid == 0) sm_inv = 1.f / s;
    __syncthreads();
    float inv = sm_inv;
    if (tid < NRELC)
        g_attnb[(size_t)tb * KPAD + tid] = __float2bfloat16(e * inv);
}

// ---------------- mega GRU kernel: 8 steps + pred + gh2 + match + svec ----------------
// 128 blocks x 384 threads; block owns batch rows [blockIdx*8, blockIdx*8+8)
__global__ __launch_bounds__(384)
void k_gru_all(const float* __restrict__ giall, const float* __restrict__ whhT,
               const float* __restrict__ bhh, const float* __restrict__ qrel,
               const float* __restrict__ Wh1T, const float* __restrict__ Wh2T,
               const float* __restrict__ bh1, const float* __restrict__ bh2,
               const int* __restrict__ trip, const float* __restrict__ WalT,
               const float* __restrict__ bal, double* acc) {
    __shared__ float hs[8][128];    // GRU state, later gh2
    __shared__ float asg[8][384];   // gate pre-activations
    __shared__ float qs[8][128];    // qrel rows, later pre[sub] rows
    __shared__ float ps[8][128];    // p1, then pred
    int tid = threadIdx.x;
    int j = tid & 127;              // column (for combine stages)
    int g = tid >> 7;               // group 0..2
    int r0 = blockIdx.x * 8;

    for (int i = tid; i < 8 * 128; i += 384) hs[i >> 7][i & 127] = 0.f;
    __syncthreads();

    // ---- 8 GRU steps ----
    for (int t = 0; t < NTC; t++) {
        {
            float a[8];
            #pragma unroll
            for (int r = 0; r < 8; r++) a[r] = 0.f;
            for (int k = 0; k < 128; k++) {
                float w = whhT[k * H3C + tid];
                #pragma unroll
                for (int r = 0; r < 8; r++) a[r] = fmaf(hs[r][k], w, a[r]);
            }
            #pragma unroll
            for (int r = 0; r < 8; r++) asg[r][tid] = a[r];
        }
        __syncthreads();
        if (tid < 128) {
            float br = bhh[j], bz = bhh[128 + j], bn = bhh[256 + j];
            const float* gi = giall + (size_t)t * NBC * H3C;
            #pragma unroll
            for (int r = 0; r < 8; r++) {
                size_t gx = (size_t)(r0 + r) * H3C;
                float rr = sigm(gi[gx + j] + asg[r][j] + br);
                float zz = sigm(gi[gx + 128 + j] + asg[r][128 + j] + bz);
                float nn = tanhf(gi[gx + 256 + j] + rr * (asg[r][256 + j] + bn));
                hs[r][j] = (1.f - zz) * nn + zz * hs[r][j];
            }
        }
        __syncthreads();
    }

    // ---- load qrel rows ----
    for (int i = tid; i < 8 * 128; i += 384)
        qs[i >> 7][i & 127] = qrel[(r0 + (i >> 7)) * 128 + (i & 127)];
    __syncthreads();

    // ---- pred = 0.1*lin(lin(q,Wh1),Wh2) + q ----
    for (int r = g; r < 8; r += 3) {
        float a = 0.f;
        for (int k = 0; k < 128; k++) a = fmaf(qs[r][k], Wh1T[k * 128 + j], a);
        ps[r][j] = a + bh1[j];
    }
    __syncthreads();
    float predv[3];
    int nmine = 0;
    for (int r = g; r < 8; r += 3) {
        float a = 0.f;
        for (int k = 0; k < 128; k++) a = fmaf(ps[r][k], Wh2T[k * 128 + j], a);
        predv[nmine++] = 0.1f * (a + bh2[j]) + qs[r][j];
    }
    __syncthreads();
    {
        int m = 0;
        for (int r = g; r < 8; r += 3) ps[r][j] = predv[m++];
    }
    // match loss: sum (pred - gruh)^2 over owned (r,j)
    __syncthreads();
    {
        float msum = 0.f;
        for (int r = g; r < 8; r += 3) {
            float d = ps[r][j] - hs[r][j];
            msum += d * d;
        }
        float bsum = blockReduceSum(msum);
        if (tid == 0) atomicAdd(&acc[2], (double)bsum);
    }

    // ---- gh2 = GRUCell(q_rel, pred): gi slot NTC, h = ps ----
    __syncthreads();
    {
        float a[8];
        #pragma unroll
        for (int r = 0; r < 8; r++) a[r] = 0.f;
        for (int k = 0; k < 128; k++) {
            float w = whhT[k * H3C + tid];
            #pragma unroll
            for (int r = 0; r < 8; r++) a[r] = fmaf(ps[r][k], w, a[r]);
        }
        #pragma unroll
        for (int r = 0; r < 8; r++) asg[r][tid] = a[r];
    }
    __syncthreads();
    if (tid < 128) {
        float br = bhh[j], bz = bhh[128 + j], bn = bhh[256 + j];
        const float* gi = giall + (size_t)NTC * NBC * H3C;
        #pragma unroll
        for (int r = 0; r < 8; r++) {
            size_t gx = (size_t)(r0 + r) * H3C;
            float rr = sigm(gi[gx + j] + asg[r][j] + br);
            float zz = sigm(gi[gx + 128 + j] + asg[r][128 + j] + bz);
            float nn = tanhf(gi[gx + 256 + j] + rr * (asg[r][256 + j] + bn));
            hs[r][j] = (1.f - zz) * nn + zz * ps[r][j];   // hs := gh2
        }
    }
    __syncthreads();

    // ---- svec = (pre[sub] @ Wal^T + bal) * gh2 -> bf16 ----
    for (int i = tid; i < 8 * 128; i += 384) {
        int r = i >> 7, c = i & 127;
        int row = trip[(r0 + r) * 3 + 0];
        qs[r][c] = __bfloat162float(g_prebf[(size_t)row * HC + c]);
    }
    __syncthreads();
    for (int r = g; r < 8; r += 3) {
        float a = 0.f;
        for (int k = 0; k < 128; k++) a = fmaf(qs[r][k], WalT[k * 128 + j], a);
        float v = (a + bal[j]) * hs[r][j];
        g_svecb[(r0 + r) * 128 + j] = __float2bfloat16(v);
    }
}

__global__ void k_final(const double* __restrict__ acc, float* __restrict__ out) {
    if (threadIdx.x == 0) {
        out[(size_t)NBC * N_ENTC]     = (float)(acc[2] / (double)(NBC * HC));
        out[(size_t)NBC * N_ENTC + 1] = (float)((acc[0] - acc[1]) /
                                                ((double)NBC * (double)N_ENTC));
    }
}

// ---------------- host ----------------
extern "C" void kernel_launch(void* const* d_in, const int* in_sizes, int n_in,
                              void* d_out, int out_size) {
    const float* ent  = (const float*)d_in[0];
    const float* rel  = (const float*)d_in[1];
    const float* Wn   = (const float*)d_in[2];
    const float* Wl   = (const float*)d_in[3];
    const float* Wev  = (const float*)d_in[4];
    const float* wih  = (const float*)d_in[5];
    const float* whh  = (const float*)d_in[6];
    const float* bih  = (const float*)d_in[7];
    const float* bhh  = (const float*)d_in[8];
    const float* Wm1  = (const float*)d_in[9];
    const float* bm1  = (const float*)d_in[10];
    const float* Wm2  = (const float*)d_in[11];
    const float* bm2  = (const float*)d_in[12];
    const float* Wh1  = (const float*)d_in[13];
    const float* bh1  = (const float*)d_in[14];
    const float* Wh2  = (const float*)d_in[15];
    const float* bh2  = (const float*)d_in[16];
    const float* Wal  = (const float*)d_in[17];
    const float* bal  = (const float*)d_in[18];
    const float* Wat  = (const float*)d_in[19];
    const float* bat  = (const float*)d_in[20];
    const float* part = (const float*)d_in[21];
    const int* esrc = (const int*)d_in[22];
    const int* edst = (const int*)d_in[23];
    const int* etyp = (const int*)d_in[24];
    const int* trip = (const int*)d_in[25];
    float* out = (float*)d_out;

    void* basep = nullptr;
    cudaGetSymbolAddress(&basep, d_buf);
    float* F = (float*)basep;
    __nv_bfloat16 *pA2, *pB3, *pPreb, *pAlnb, *pWalb, *pWihb, *pMrelTb, *pXb, *pAttnb, *pSvecb;
    { void* p; cudaGetSymbolAddress(&p, g_A2);     pA2     = (__nv_bfloat16*)p; }
    { void* p; cudaGetSymbolAddress(&p, g_B3);     pB3     = (__nv_bfloat16*)p; }
    { void* p; cudaGetSymbolAddress(&p, g_prebf);  pPreb   = (__nv_bfloat16*)p; }
    { void* p; cudaGetSymbolAddress(&p, g_alnbf);  pAlnb   = (__nv_bfloat16*)p; }
    { void* p; cudaGetSymbolAddress(&p, g_walb);   pWalb   = (__nv_bfloat16*)p; }
    { void* p; cudaGetSymbolAddress(&p, g_wihb);   pWihb   = (__nv_bfloat16*)p; }
    { void* p; cudaGetSymbolAddress(&p, g_mrelTb); pMrelTb = (__nv_bfloat16*)p; }
    { void* p; cudaGetSymbolAddress(&p, g_Xb);     pXb     = (__nv_bfloat16*)p; }
    { void* p; cudaGetSymbolAddress(&p, g_attnb);  pAttnb  = (__nv_bfloat16*)p; }
    { void* p; cudaGetSymbolAddress(&p, g_svecb);  pSvecb  = (__nv_bfloat16*)p; }

    float* mrel   = F + O_MREL;
    float* mrelT  = F + O_MRELT;
    float* qrel   = F + O_QREL;
    float* Amat   = F + O_AMAT;
    float* giall  = F + O_GIALL;
    float* whhT   = F + O_WHHT;
    float* Wh1T   = F + O_WH1T;
    float* Wh2T   = F + O_WH2T;
    float* WatT   = F + O_WATT;
    float* WalT   = F + O_WALT;
    float* Wm1T   = F + O_WM1T;
    float* Wm2T   = F + O_WM2T;
    double* acc   = (double*)(F + O_ACC);
    int* deg      = (int*)(F + O_INT);
    int* rowptr   = deg + N_ENTC;
    int* cursor   = rowptr + N_ENTC + 1;
    int* csr      = cursor + N_ENTC;
    int* bsums    = csr + NEC;

    k_init<<<640, 256>>>(Wn, Wl, Wev, wih, whh, Wal, Wh1, Wh2, Wat, Wm1, Wm2,
                         deg, cursor, acc, F);
    k_count<<<(NEC + 255) / 256, 256>>>(edst, deg);
    k_entcvt<<<(N_ENTC * HC + 255) / 256, 256>>>(ent, deg);
    k_scanA<<<(N_ENTC + 1023) / 1024, 1024>>>(deg, rowptr, bsums);
    k_scanB<<<1, 1024>>>(rowptr, bsums, (N_ENTC + 1023) / 1024);
    k_fill<<<(NEC + 255) / 256, 256>>>(edst, rowptr, cursor, csr);
    k_aggregate<<<N_ENTC, 128>>>(ent, rel, esrc, etyp, rowptr, csr);
    {
        dim3 g(1, (N_ENTC + BGM - 1) / BGM);
        k_bgemm<2><<<g, 256>>>(pA2, pB3, nullptr, nullptr, pPreb, nullptr, nullptr,
                               N_ENTC, HC, KPRE);
    }
    {
        dim3 g(1, (N_ENTC + BGM - 1) / BGM);
        k_bgemm<1><<<g, 256>>>(pPreb, pWalb, bal, nullptr, pAlnb, nullptr, nullptr,
                               N_ENTC, HC, HC);
    }
    k_mrel<<<46, 256>>>(rel, Wm1T, Wm2T, bm1, bm2, mrel, mrelT);
    k_qa_amat<<<256, 128>>>(mrel, trip, WatT, bat, mrelT, qrel, Amat);
    k_attn<<<NTC * NBC, 512>>>(part, Amat);
    {
        dim3 g(1, NTC * NBC / BGM);
        k_bgemm<1><<<g, 256>>>(pAttnb, pMrelTb, nullptr, nullptr, pXb, nullptr, nullptr,
                               NTC * NBC, HC, KPAD);
    }
    {
        dim3 g(H3C / BGN, (NTC + 1) * NBC / BGM);
        k_bgemm<4><<<g, 256>>>(pXb, pWihb, bih, giall, nullptr, nullptr, nullptr,
                               (NTC + 1) * NBC, H3C, HC);
    }
    k_gru_all<<<128, 384>>>(giall, whhT, bhh, qrel, Wh1T, Wh2T, bh1, bh2,
                            trip, WalT, bal, acc);
    {
        dim3 g((N_ENTC + BGN - 1) / BGN, NBC / BGM);
        k_bgemm<3><<<g, 256>>>(pSvecb, pAlnb, nullptr, out, nullptr, trip, acc,
                               NBC, N_ENTC, HC);
    }
    if (out_size >= NBC * N_ENTC + 2) k_final<<<1, 32>>>(acc, out);
}

// round 8
// speedup vs baseline: 2.2449x; 1.0237x over previous
#include <cuda_runtime.h>
#include <cuda_bf16.h>
#include <stdint.h>
#include <math.h>

#define N_ENTC 20000
#define NRELC  460
#define HC     128
#define NEC    400000
#define NBC    1024
#define NTC    8
#define H3C    384
#define SLOPE  0.22916666666666666f
#define KPRE   384
#define KPAD   480
#define MT_STR 512

// ---------------- fp32 scratch ----------------
constexpr size_t O_MREL  = 0;
constexpr size_t O_MRELT = O_MREL + (size_t)NRELC * HC;
constexpr size_t O_QREL  = O_MRELT + (size_t)HC * MT_STR;
constexpr size_t O_AMAT  = O_QREL + (size_t)NBC * HC;
constexpr size_t O_GIALL = O_AMAT + (size_t)NBC * NRELC;
constexpr size_t O_WHHT  = O_GIALL + (size_t)(NTC + 1) * NBC * H3C;
constexpr size_t O_WH1T  = O_WHHT + 49152;
constexpr size_t O_WH2T  = O_WH1T + 16384;
constexpr size_t O_WATT  = O_WH2T + 16384;
constexpr size_t O_WALT  = O_WATT + 16384;
constexpr size_t O_WM1T  = O_WALT + 16384;
constexpr size_t O_WM2T  = O_WM1T + 32768;
constexpr size_t O_ACC_  = O_WM2T + 32768;
constexpr size_t O_ACC   = (O_ACC_ + 1) & ~(size_t)1;
constexpr size_t O_INT   = O_ACC + 8;
constexpr size_t N_INTS  = (size_t)N_ENTC + (N_ENTC + 1) + N_ENTC + NEC + 64;
constexpr size_t TOTALF  = O_INT + N_INTS;
__device__ __align__(16) float d_buf[TOTALF];

// ---------------- bf16 scratch ----------------
__device__ __align__(16) __nv_bfloat16 g_A2[(size_t)N_ENTC * KPRE];
__device__ __align__(16) __nv_bfloat16 g_B3[HC * KPRE];
__device__ __align__(16) __nv_bfloat16 g_entb[(size_t)N_ENTC * HC];
__device__ __align__(16) __nv_bfloat16 g_relb[NRELC * HC];
__device__ __align__(16) __nv_bfloat16 g_prebf[(size_t)N_ENTC * HC];
__device__ __align__(16) __nv_bfloat16 g_alnbf[(size_t)N_ENTC * HC];
__device__ __align__(16) __nv_bfloat16 g_walb[HC * HC];
__device__ __align__(16) __nv_bfloat16 g_wihb[H3C * HC];
__device__ __align__(16) __nv_bfloat16 g_mrelTb[HC * KPAD];
__device__ __align__(16) __nv_bfloat16 g_Xb[(size_t)(NTC + 1) * NBC * HC];
__device__ __align__(16) __nv_bfloat16 g_attnb[(size_t)NTC * NBC * KPAD];
__device__ __align__(16) __nv_bfloat16 g_svecb[(size_t)NBC * HC];

// ---------------- reductions ----------------
__device__ __forceinline__ float blockReduceSum(float v) {
    __shared__ float sh[32];
    int tid = threadIdx.x;
    __syncthreads();
    #pragma unroll
    for (int o = 16; o > 0; o >>= 1) v += __shfl_xor_sync(0xffffffffu, v, o);
    if ((tid & 31) == 0) sh[tid >> 5] = v;
    __syncthreads();
    float r = 0.f;
    if (tid < 32) {
        int nw = (blockDim.x + 31) >> 5;
        r = (tid < nw) ? sh[tid] : 0.f;
        #pragma unroll
        for (int o = 16; o > 0; o >>= 1) r += __shfl_xor_sync(0xffffffffu, r, o);
    }
    return r;
}
__device__ __forceinline__ float blockReduceMax(float v) {
    __shared__ float sh[32];
    int tid = threadIdx.x;
    __syncthreads();
    #pragma unroll
    for (int o = 16; o > 0; o >>= 1) v = fmaxf(v, __shfl_xor_sync(0xffffffffu, v, o));
    if ((tid & 31) == 0) sh[tid >> 5] = v;
    __syncthreads();
    float r = -3.402823e38f;
    if (tid < 32) {
        int nw = (blockDim.x + 31) >> 5;
        r = (tid < nw) ? sh[tid] : -3.402823e38f;
        #pragma unroll
        for (int o = 16; o > 0; o >>= 1) r = fmaxf(r, __shfl_xor_sync(0xffffffffu, r, o));
    }
    return r;
}

__device__ __forceinline__ void sig_sp(float x, float& sig, float& sp) {
    float ax = fabsf(x);
    if (ax < 0.5f) {
        float x2 = x * x;
        sig = 0.5f + x * (0.25f + x2 * (-0.0208333333f + x2 * 0.0020833333f));
        sp  = 0.69314718f + 0.5f * x
            + x2 * (0.125f + x2 * (-0.0052083333f + x2 * 0.00034722222f));
    } else {
        float e = __expf(-ax);
        sig = (x >= 0.f) ? 1.f / (1.f + e) : e / (1.f + e);
        sp  = fmaxf(x, 0.f) + __logf(1.f + e);
    }
}
__device__ __forceinline__ float sigm(float x) { return 1.f / (1.f + __expf(-x)); }

// ---------------- init ----------------
__global__ void k_init(const float* __restrict__ Wn, const float* __restrict__ Wl,
                       const float* __restrict__ Wev, const float* __restrict__ wih,
                       const float* __restrict__ whh, const float* __restrict__ Wal,
                       const float* __restrict__ Wh1, const float* __restrict__ Wh2,
                       const float* __restrict__ Wat, const float* __restrict__ Wm1,
                       const float* __restrict__ Wm2, const float* __restrict__ rel,
                       int* deg, int* cursor, double* acc, float* F) {
    int i = blockIdx.x * blockDim.x + threadIdx.x;  // grid 640*256
    if (i < N_ENTC) { deg[i] = 0; cursor[i] = 0; }
    if (i == 0) { acc[0] = 0.0; acc[1] = 0.0; acc[2] = 0.0; }
    if (i < HC * KPRE) {
        int n = i / KPRE, k = i % KPRE;
        float v = (k < 128) ? Wn[k * 128 + n]
                : (k < 256) ? Wl[(k - 128) * 128 + n]
                            : Wev[(k - 256) * 128 + n];
        g_B3[i] = __float2bfloat16(v);
    }
    if (i < H3C * HC) g_wihb[i] = __float2bfloat16(wih[i]);
    if (i < HC * HC)  g_walb[i] = __float2bfloat16(Wal[i]);
    if (i < NRELC * HC) g_relb[i] = __float2bfloat16(rel[i]);
    if (i < HC * H3C) {
        int k = i / H3C, j = i % H3C;
        F[O_WHHT + i] = whh[j * 128 + k];
    }
    if (i < HC * HC) {
        int k = i / HC, j = i % HC;
        F[O_WH1T + i] = Wh1[j * HC + k];
        F[O_WH2T + i] = Wh2[j * HC + k];
        F[O_WATT + i] = Wat[j * HC + k];
        F[O_WALT + i] = Wal[j * HC + k];
    }
    if (i < 128 * 256) {
        int k = i / 256, j2 = i % 256;
        F[O_WM1T + i] = Wm1[j2 * 128 + k];
    }
    if (i < 256 * 128) {
        int k2 = i / 128, j = i % 128;
        F[O_WM2T + i] = Wm2[j * 256 + k2];
    }
    if (i < HC * (KPAD - NRELC)) {
        int j = i / (KPAD - NRELC), c = NRELC + i % (KPAD - NRELC);
        g_mrelTb[j * KPAD + c] = __float2bfloat16(0.f);
    }
    if (i < HC * (MT_STR - NRELC)) {
        int j = i / (MT_STR - NRELC), c = NRELC + i % (MT_STR - NRELC);
        F[O_MRELT + j * MT_STR + c] = 0.f;
    }
    if (i < NTC * NBC * (KPAD - NRELC)) {
        int row = i / (KPAD - NRELC), c = NRELC + i % (KPAD - NRELC);
        g_attnb[(size_t)row * KPAD + c] = __float2bfloat16(0.f);
    }
}

__global__ void k_count(const int* __restrict__ dst, int* deg) {
    int e = blockIdx.x * blockDim.x + threadIdx.x;
    if (e < NEC) atomicAdd(&deg[dst[e]], 1);
}

// ent -> bf16 copy + masked A2 columns
__global__ void k_entcvt(const float* __restrict__ ent, const int* __restrict__ deg) {
    int i = blockIdx.x * blockDim.x + threadIdx.x;
    if (i < N_ENTC * HC) {
        int node = i >> 7, c = i & 127;
        float v = ent[i];
        bool m = deg[node] > 0;
        g_entb[i] = __float2bfloat16(v);
        g_A2[(size_t)node * KPRE + 128 + c] = __float2bfloat16(m ? v : 0.f);
        g_A2[(size_t)node * KPRE + 256 + c] = __float2bfloat16(m ? 0.f : v);
    }
}

__global__ void k_scanA(const int* __restrict__ deg, int* rowptr, int* bsums) {
    __shared__ int wsum[32];
    int tid = threadIdx.x, lane = tid & 31, wid = tid >> 5;
    int i = blockIdx.x * 1024 + tid;
    int v = (i < N_ENTC) ? deg[i] : 0;
    int x = v;
    #pragma unroll
    for (int o = 1; o < 32; o <<= 1) {
        int t = __shfl_up_sync(0xffffffffu, x, o);
        if (lane >= o) x += t;
    }
    if (lane == 31) wsum[wid] = x;
    __syncthreads();
    if (wid == 0) {
        int s = wsum[lane];
        #pragma unroll
        for (int o = 1; o < 32; o <<= 1) {
            int t = __shfl_up_sync(0xffffffffu, s, o);
            if (lane >= o) s += t;
        }
        wsum[lane] = s;
    }
    __syncthreads();
    int woff = (wid > 0) ? wsum[wid - 1] : 0;
    int incl = x + woff;
    if (i < N_ENTC) rowptr[i] = incl - v;
    if (tid == 1023) bsums[blockIdx.x] = incl;
}

__global__ void k_scanB(int* rowptr, const int* __restrict__ bsums, int nblk) {
    __shared__ int offs[32];
    __shared__ int total_s;
    int tid = threadIdx.x;
    if (tid < 32) {
        int v = (tid < nblk) ? bsums[tid] : 0;
        int x = v;
        #pragma unroll
        for (int o = 1; o < 32; o <<= 1) {
            int t = __shfl_up_sync(0xffffffffu, x, o);
            if (tid >= o) x += t;
        }
        offs[tid] = x - v;
        if (tid == 31) total_s = x;
    }
    __syncthreads();
    for (int i = tid; i < N_ENTC; i += blockDim.x)
        rowptr[i] += offs[i >> 10];
    if (tid == 0) rowptr[N_ENTC] = total_s;
}

__global__ void k_fill(const int* __restrict__ dst, const int* __restrict__ rowptr,
                       int* cursor, int* csr) {
    int e = blockIdx.x * blockDim.x + threadIdx.x;
    if (e < NEC) {
        int d = dst[e];
        int p = atomicAdd(&cursor[d], 1);
        csr[rowptr[d] + p] = e;
    }
}

// bf16 aggregate: 64 threads/node, bf16x2 loads (half the bytes + half the loads)
__global__ void k_aggregate(const int* __restrict__ src, const int* __restrict__ typ,
                            const int* __restrict__ rowptr, const int* __restrict__ csr) {
    int node = blockIdx.x;
    int c = threadIdx.x;  // 64
    __shared__ int s_src[256];
    __shared__ int s_typ[256];
    const __nv_bfloat162* entb = (const __nv_bfloat162*)g_entb;
    const __nv_bfloat162* relb = (const __nv_bfloat162*)g_relb;
    int beg = rowptr[node], end = rowptr[node + 1];
    int deg = end - beg;
    float ax = 0.f, ay = 0.f;
    for (int base = beg; base < end; base += 256) {
        int cnt = min(256, end - base);
        for (int i = c; i < cnt; i += 64) {
            int e = csr[base + i];
            s_src[i] = src[e] << 6;   // row stride in bf16x2 units
            s_typ[i] = typ[e] << 6;
        }
        __syncthreads();
        #pragma unroll 4
        for (int i = 0; i < cnt; i++) {
            __nv_bfloat162 ev = entb[s_src[i] + c];
            __nv_bfloat162 rv = relb[s_typ[i] + c];
            ax += __bfloat162float(ev.x) + __bfloat162float(rv.x);
            ay += __bfloat162float(ev.y) + __bfloat162float(rv.y);
        }
        __syncthreads();
    }
    float inv = (deg > 0) ? 1.f / (float)deg : 0.f;
    __nv_bfloat162 o;
    o.x = __float2bfloat16(ax * inv);
    o.y = __float2bfloat16(ay * inv);
    *(__nv_bfloat162*)(g_A2 + (size_t)node * KPRE + 2 * c) = o;
}

// ---------------- GEMM fragment helpers ----------------
#define BGM 128
#define BGN 128
#define BGK 32
#define SSTR 40
#define XSTR 136

#define MMA_STEP(As_, Bs_, STRA, kbaseA, kk, cacc)                                   \
    {                                                                                 \
        uint32_t a[2][4], b[8][2];                                                    \
        _Pragma("unroll")                                                             \
        for (int mt = 0; mt < 2; mt++) {                                              \
            int row = wm * 32 + mt * 16 + (lane & 15);                                \
            int col = (kbaseA) + (kk) + ((lane >> 4) << 3);                           \
            uint32_t addr = (uint32_t)__cvta_generic_to_shared((As_) + row * (STRA) + col); \
            asm volatile("ldmatrix.sync.aligned.m8n8.x4.shared.b16 {%0,%1,%2,%3},[%4];" \
                         : "=r"(a[mt][0]), "=r"(a[mt][1]), "=r"(a[mt][2]), "=r"(a[mt][3]) \
                         : "r"(addr));                                                \
        }                                                                             \
        _Pragma("unroll")                                                             \
        for (int np = 0; np < 4; np++) {                                              \
            int nrow = wn * 64 + np * 16 + ((lane >> 4) << 3) + (lane & 7);           \
            int ncol = (kk) + (((lane >> 3) & 1) << 3);                               \
            uint32_t addr = (uint32_t)__cvta_generic_to_shared((Bs_) + nrow * SSTR + ncol); \
            asm volatile("ldmatrix.sync.aligned.m8n8.x4.shared.b16 {%0,%1,%2,%3},[%4];" \
                         : "=r"(b[2 * np][0]), "=r"(b[2 * np][1]),                    \
                           "=r"(b[2 * np + 1][0]), "=r"(b[2 * np + 1][1])             \
                         : "r"(addr));                                                \
        }                                                                             \
        _Pragma("unroll")                                                             \
        for (int mt = 0; mt < 2; mt++)                                                \
            _Pragma("unroll")                                                         \
            for (int nt = 0; nt < 8; nt++)                                            \
                asm volatile(                                                         \
                    "mma.sync.aligned.m16n8k16.row.col.f32.bf16.bf16.f32 "            \
                    "{%0,%1,%2,%3},{%4,%5,%6,%7},{%8,%9},{%0,%1,%2,%3};"              \
                    : "+f"(cacc[mt][nt][0]), "+f"(cacc[mt][nt][1]),                   \
                      "+f"(cacc[mt][nt][2]), "+f"(cacc[mt][nt][3])                    \
                    : "r"(a[mt][0]), "r"(a[mt][1]), "r"(a[mt][2]), "r"(a[mt][3]),     \
                      "r"(b[nt][0]), "r"(b[nt][1]));                                  \
    }

// ---------------- score GEMM (unchanged core) ----------------
__global__ __launch_bounds__(256)
void k_score(const __nv_bfloat16* __restrict__ A, const __nv_bfloat16* __restrict__ B,
             float* __restrict__ Cf, const int* __restrict__ trip, double* acc,
             int M, int N) {
    __shared__ __nv_bfloat16 As[BGM * SSTR];
    __shared__ __nv_bfloat16 Bs[BGN * SSTR];
    int tid = threadIdx.x;
    int lane = tid & 31, wid = tid >> 5;
    int wm = wid & 3, wn = wid >> 2;
    int rowBase = blockIdx.y * BGM;
    int colBase = blockIdx.x * BGN;
    float c[2][8][4];
    #pragma unroll
    for (int i = 0; i < 2; i++)
        #pragma unroll
        for (int j = 0; j < 8; j++)
            #pragma unroll
            for (int q = 0; q < 4; q++) c[i][j][q] = 0.f;
    for (int k0 = 0; k0 < HC; k0 += BGK) {
        #pragma unroll
        for (int i = 0; i < 2; i++) {
            int idx = tid + i * 256;
            int r = idx >> 2, seg = idx & 3;
            *(uint4*)(As + r * SSTR + seg * 8) =
                *(const uint4*)(A + (size_t)(rowBase + r) * HC + k0 + seg * 8);
            uint4 vb = make_uint4(0, 0, 0, 0);
            int gn = colBase + r;
            if (gn < N) vb = *(const uint4*)(B + (size_t)gn * HC + k0 + seg * 8);
            *(uint4*)(Bs + r * SSTR + seg * 8) = vb;
        }
        __syncthreads();
        MMA_STEP(As, Bs, SSTR, 0, 0, c)
        MMA_STEP(As, Bs, SSTR, 0, 16, c)
        __syncthreads();
    }
    float lsp = 0.f, lxo = 0.f;
    #pragma unroll
    for (int mt = 0; mt < 2; mt++) {
        int r0 = rowBase + wm * 32 + mt * 16 + (lane >> 2);
        int ob0 = trip[r0 * 3 + 2];
        int ob1 = trip[(r0 + 8) * 3 + 2];
        #pragma unroll
        for (int nt = 0; nt < 8; nt++) {
            int col = colBase + wn * 64 + nt * 8 + ((lane & 3) << 1);
            if (col < N) {
                #pragma unroll
                for (int half = 0; half < 2; half++) {
                    int row = r0 + half * 8;
                    int ob = half ? ob1 : ob0;
                    float x0 = c[mt][nt][half * 2 + 0];
                    float x1 = c[mt][nt][half * 2 + 1];
                    float s0, p0, s1, p1;
                    sig_sp(x0, s0, p0);
                    sig_sp(x1, s1, p1);
                    *(float2*)(Cf + (size_t)row * N + col) = make_float2(s0, s1);
                    lsp += p0 + p1;
                    if (col == ob) lxo += x0;
                    if (col + 1 == ob) lxo += x1;
                }
            }
        }
    }
    float bs = blockReduceSum(lsp);
    float bx = blockReduceSum(lxo);
    if (tid == 0) {
        atomicAdd(&acc[0], (double)bs);
        atomicAdd(&acc[1], (double)bx);
    }
}

// ---------------- fused pre+aln: stage1 rrelu GEMM K=384, stage2 @Wal^T ----------------
__global__ __launch_bounds__(256)
void k_prealn(const float* __restrict__ bal, int M) {
    extern __shared__ __nv_bfloat16 sm[];
    __nv_bfloat16* As = sm;
    __nv_bfloat16* Bs = sm + BGM * SSTR;
    __nv_bfloat16* Xs = sm + 2 * BGM * SSTR;
    int tid = threadIdx.x, lane = tid & 31, wid = tid >> 5;
    int wm = wid & 3, wn = wid >> 2;
    int rowBase = blockIdx.x * BGM;
    float c[2][8][4];
    #pragma unroll
    for (int i = 0; i < 2; i++)
        #pragma unroll
        for (int j = 0; j < 8; j++)
            #pragma unroll
            for (int q = 0; q < 4; q++) c[i][j][q] = 0.f;
    for (int k0 = 0; k0 < KPRE; k0 += BGK) {
        #pragma unroll
        for (int i = 0; i < 2; i++) {
            int idx = tid + i * 256;
            int r = idx >> 2, seg = idx & 3;
            uint4 va = make_uint4(0, 0, 0, 0);
            int gr = rowBase + r;
            if (gr < M) va = *(const uint4*)(g_A2 + (size_t)gr * KPRE + k0 + seg * 8);
            *(uint4*)(As + r * SSTR + seg * 8) = va;
            *(uint4*)(Bs + r * SSTR + seg * 8) =
                *(const uint4*)(g_B3 + (size_t)r * KPRE + k0 + seg * 8);
        }
        __syncthreads();
        MMA_STEP(As, Bs, SSTR, 0, 0, c)
        MMA_STEP(As, Bs, SSTR, 0, 16, c)
        __syncthreads();
    }
    // stage-1 epilogue: rrelu -> Xs + prebf
    #pragma unroll
    for (int mt = 0; mt < 2; mt++) {
        #pragma unroll
        for (int nt = 0; nt < 8; nt++) {
            int colL = wn * 64 + nt * 8 + ((lane & 3) << 1);
            #pragma unroll
            for (int half = 0; half < 2; half++) {
                int rowL = wm * 32 + mt * 16 + (lane >> 2) + half * 8;
                float v0 = c[mt][nt][half * 2 + 0];
                float v1 = c[mt][nt][half * 2 + 1];
                v0 = (v0 >= 0.f) ? v0 : v0 * SLOPE;
                v1 = (v1 >= 0.f) ? v1 : v1 * SLOPE;
                __nv_bfloat162 bv(__float2bfloat16(v0), __float2bfloat16(v1));
                *(__nv_bfloat162*)(Xs + rowL * XSTR + colL) = bv;
                int grow = rowBase + rowL;
                if (grow < M)
                    *(__nv_bfloat162*)(g_prebf + (size_t)grow * HC + colL) = bv;
            }
        }
    }
    __syncthreads();
    // stage 2: aln = Xs @ Wal^T + bal
    float c2[2][8][4];
    #pragma unroll
    for (int i = 0; i < 2; i++)
        #pragma unroll
        for (int j = 0; j < 8; j++)
            #pragma unroll
            for (int q = 0; q < 4; q++) c2[i][j][q] = 0.f;
    for (int k0 = 0; k0 < HC; k0 += BGK) {
        #pragma unroll
        for (int i = 0; i < 2; i++) {
            int idx = tid + i * 256;
            int r = idx >> 2, seg = idx & 3;
            *(uint4*)(Bs + r * SSTR + seg * 8) =
                *(const uint4*)(g_walb + (size_t)r * HC + k0 + seg * 8);
        }
        __syncthreads();
        MMA_STEP(Xs, Bs, XSTR, k0, 0, c2)
        MMA_STEP(Xs, Bs, XSTR, k0, 16, c2)
        __syncthreads();
    }
    #pragma unroll
    for (int mt = 0; mt < 2; mt++) {
        #pragma unroll
        for (int nt = 0; nt < 8; nt++) {
            int colL = wn * 64 + nt * 8 + ((lane & 3) << 1);
            float b0 = bal[colL], b1 = bal[colL + 1];
            #pragma unroll
            for (int half = 0; half < 2; half++) {
                int grow = rowBase + wm * 32 + mt * 16 + (lane >> 2) + half * 8;
                if (grow < M) {
                    __nv_bfloat162 bv(__float2bfloat16(c2[mt][nt][half * 2 + 0] + b0),
                                      __float2bfloat16(c2[mt][nt][half * 2 + 1] + b1));
                    *(__nv_bfloat162*)(g_alnbf + (size_t)grow * HC + colL) = bv;
                }
            }
        }
    }
}

// ---------------- fused rpath+giall ----------------
// blocks 0..63: X = attn @ mrel (K=480) ; blocks 64..71: X = Xb slot8
// then giall[rows] = X @ wih^T + bih (3 n-blocks of 128)
__global__ __launch_bounds__(256)
void k_rpgi(const float* __restrict__ bih, float* __restrict__ giall) {
    extern __shared__ __nv_bfloat16 sm[];
    __nv_bfloat16* As = sm;
    __nv_bfloat16* Bs = sm + BGM * SSTR;
    __nv_bfloat16* Xs = sm + 2 * BGM * SSTR;
    int tid = threadIdx.x, lane = tid & 31, wid = tid >> 5;
    int wm = wid & 3, wn = wid >> 2;
    int rowBase = blockIdx.x * BGM;   // 72 blocks
    if (blockIdx.x < 64) {
        float c[2][8][4];
        #pragma unroll
        for (int i = 0; i < 2; i++)
            #pragma unroll
            for (int j = 0; j < 8; j++)
                #pragma unroll
                for (int q = 0; q < 4; q++) c[i][j][q] = 0.f;
        for (int k0 = 0; k0 < KPAD; k0 += BGK) {
            #pragma unroll
            for (int i = 0; i < 2; i++) {
                int idx = tid + i * 256;
                int r = idx >> 2, seg = idx & 3;
                *(uint4*)(As + r * SSTR + seg * 8) =
                    *(const uint4*)(g_attnb + (size_t)(rowBase + r) * KPAD + k0 + seg * 8);
                *(uint4*)(Bs + r * SSTR + seg * 8) =
                    *(const uint4*)(g_mrelTb + (size_t)r * KPAD + k0 + seg * 8);
            }
            __syncthreads();
            MMA_STEP(As, Bs, SSTR, 0, 0, c)
            MMA_STEP(As, Bs, SSTR, 0, 16, c)
            __syncthreads();
        }
        #pragma unroll
        for (int mt = 0; mt < 2; mt++)
            #pragma unroll
            for (int nt = 0; nt < 8; nt++) {
                int colL = wn * 64 + nt * 8 + ((lane & 3) << 1);
                #pragma unroll
                for (int half = 0; half < 2; half++) {
                    int rowL = wm * 32 + mt * 16 + (lane >> 2) + half * 8;
                    __nv_bfloat162 bv(__float2bfloat16(c[mt][nt][half * 2 + 0]),
                                      __float2bfloat16(c[mt][nt][half * 2 + 1]));
                    *(__nv_bfloat162*)(Xs + rowL * XSTR + colL) = bv;
                }
            }
    } else {
        // load slot-8 qrel rows (written by k_qa_amat)
        for (int i = tid; i < BGM * (HC / 8); i += 256) {
            int r = i / (HC / 8), seg = i % (HC / 8);
            *(uint4*)(Xs + r * XSTR + seg * 8) =
                *(const uint4*)(g_Xb + (size_t)(rowBase + r) * HC + seg * 8);
        }
    }
    __syncthreads();
    for (int nb = 0; nb < 3; nb++) {
        float c2[2][8][4];
        #pragma unroll
        for (int i = 0; i < 2; i++)
            #pragma unroll
            for (int j = 0; j < 8; j++)
                #pragma unroll
                for (int q = 0; q < 4; q++) c2[i][j][q] = 0.f;
        for (int k0 = 0; k0 < HC; k0 += BGK) {
            #pragma unroll
            for (int i = 0; i < 2; i++) {
                int idx = tid + i * 256;
                int r = idx >> 2, seg = idx & 3;
                *(uint4*)(Bs + r * SSTR + seg * 8) =
                    *(const uint4*)(g_wihb + (size_t)(nb * 128 + r) * HC + k0 + seg * 8);
            }
            __syncthreads();
            MMA_STEP(Xs, Bs, XSTR, k0, 0, c2)
            MMA_STEP(Xs, Bs, XSTR, k0, 16, c2)
            __syncthreads();
        }
        #pragma unroll
        for (int mt = 0; mt < 2; mt++)
            #pragma unroll
            for (int nt = 0; nt < 8; nt++) {
                int colL = wn * 64 + nt * 8 + ((lane & 3) << 1);
                int col = nb * 128 + colL;
                float b0 = bih[col], b1 = bih[col + 1];
                #pragma unroll
                for (int half = 0; half < 2; half++) {
                    int row = rowBase + wm * 32 + mt * 16 + (lane >> 2) + half * 8;
                    *(float2*)(giall + (size_t)row * H3C + col) =
                        make_float2(c2[mt][nt][half * 2 + 0] + b0,
                                    c2[mt][nt][half * 2 + 1] + b1);
                }
            }
    }
}

// ---------------- fused mapped_rel ----------------
__global__ __launch_bounds__(256)
void k_mrel(const float* __restrict__ rel, const float* __restrict__ Wm1T,
            const float* __restrict__ Wm2T, const float* __restrict__ bm1,
            const float* __restrict__ bm2, float* __restrict__ mrel,
            float* __restrict__ mrelT) {
    __shared__ float rels[10][128];
    __shared__ float p1s[10][256];
    int tid = threadIdx.x;
    int r0 = blockIdx.x * 10;  // 46 blocks
    for (int i = tid; i < 10 * 128; i += 256)
        rels[i >> 7][i & 127] = rel[(r0 + (i >> 7)) * 128 + (i & 127)];
    __syncthreads();
    {
        int j2 = tid;
        float a[10];
        #pragma unroll
        for (int r = 0; r < 10; r++) a[r] = 0.f;
        for (int k = 0; k < 128; k++) {
            float w = Wm1T[k * 256 + j2];
            #pragma unroll
            for (int r = 0; r < 10; r++) a[r] = fmaf(rels[r][k], w, a[r]);
        }
        float b = bm1[j2];
        #pragma unroll
        for (int r = 0; r < 10; r++) p1s[r][j2] = a[r] + b;
    }
    __syncthreads();
    {
        int j = tid & 127, half = tid >> 7;
        float a[5];
        #pragma unroll
        for (int r = 0; r < 5; r++) a[r] = 0.f;
        for (int k = 0; k < 256; k++) {
            float w = Wm2T[k * 128 + j];
            #pragma unroll
            for (int r = 0; r < 5; r++) a[r] = fmaf(p1s[half * 5 + r][k], w, a[r]);
        }
        float b = bm2[j];
        #pragma unroll
        for (int r = 0; r < 5; r++) {
            int row = r0 + half * 5 + r;
            float v = a[r] + b;
            mrel[row * 128 + j] = v;
            mrelT[j * MT_STR + row] = v;
            g_mrelTb[j * KPAD + row] = __float2bfloat16(v);
        }
    }
}

__global__ __launch_bounds__(128)
void k_qa_amat(const float* __restrict__ mrel, const int* __restrict__ trip,
               const float* __restrict__ WatT, const float* __restrict__ bat,
               const float* __restrict__ mrelT, float* __restrict__ qrel,
               float* __restrict__ Amat) {
    __shared__ float q[4][128];
    __shared__ float qa[4][128];
    int j = threadIdx.x;
    int r0 = blockIdx.x * 4;  // 256 blocks
    #pragma unroll
    for (int r = 0; r < 4; r++) {
        float v = mrel[(size_t)trip[(r0 + r) * 3 + 1] * HC + j];
        q[r][j] = v;
        qrel[(r0 + r) * 128 + j] = v;
        g_Xb[(size_t)(NTC * NBC + r0 + r) * HC + j] = __float2bfloat16(v);
    }
    __syncthreads();
    {
        float a[4] = {0.f, 0.f, 0.f, 0.f};
        for (int k = 0; k < 128; k++) {
            float w = WatT[k * 128 + j];
            #pragma unroll
            for (int r = 0; r < 4; r++) a[r] = fmaf(q[r][k], w, a[r]);
        }
        float b = bat[j];
        #pragma unroll
        for (int r = 0; r < 4; r++) qa[r][j] = a[r] + b;
    }
    __syncthreads();
    #pragma unroll
    for (int r = 0; r < 4; r++) {
        float a[4] = {0.f, 0.f, 0.f, 0.f};
        for (int k = 0; k < 128; k++) {
            float qv = qa[r][k];
            #pragma unroll
            for (int t = 0; t < 4; t++)
                a[t] = fmaf(qv, mrelT[k * MT_STR + j + t * 128], a[t]);
        }
        #pragma unroll
        for (int t = 0; t < 4; t++) {
            int n = j + t * 128;
            if (n < NRELC) Amat[(size_t)(r0 + r) * NRELC + n] = a[t];
        }
    }
}

__global__ void k_attn(const float* __restrict__ part, const float* __restrict__ Amat) {
    int tb = blockIdx.x;
    int t = tb >> 10, b = tb & 1023;
    int tid = threadIdx.x;  // 512
    float x = -3.402823e38f;
    if (tid < NRELC) {
        float cur = part[(size_t)b * (NTC * NRELC) + t * NRELC + tid];
        float a = Amat[(size_t)b * NRELC + tid];
        float val = cur * a;
        x = (val == 0.f) ? -1e9f : val;
    }
    float m = blockReduceMax(x);
    __shared__ float sm_m, sm_inv;
    if (tid == 0) sm_m = m;
    __syncthreads();
    m = sm_m;
    float e = (tid < NRELC) ? __expf(x - m) : 0.f;
    float s = blockReduceSum(e);
    if (tid == 0) sm_inv = 1.f / s;
    __syncthreads();
    float inv = sm_inv;
    if (tid < NRELC)
        g_attnb[(size_t)tb * KPAD + tid] = __float2bfloat16(e * inv);
}

// ---------------- mega GRU kernel ----------------
__global__ __launch_bounds__(384)
void k_gru_all(const float* __restrict__ giall, const float* __restrict__ whhT,
               const float* __restrict__ bhh, const float* __restrict__ qrel,
               const float* __restrict__ Wh1T, const float* __restrict__ Wh2T,
               const float* __restrict__ bh1, const float* __restrict__ bh2,
               const int* __restrict__ trip, const float* __restrict__ WalT,
               const float* __restrict__ bal, double* acc) {
    __shared__ float hs[8][128];
    __shared__ float asg[8][384];
    __shared__ float qs[8][128];
    __shared__ float ps[8][128];
    int tid = threadIdx.x;
    int j = tid & 127;
    int g = tid >> 7;
    int r0 = blockIdx.x * 8;

    for (int i = tid; i < 8 * 128; i += 384) hs[i >> 7][i & 127] = 0.f;
    __syncthreads();

    for (int t = 0; t < NTC; t++) {
        {
            float a[8];
            #pragma unroll
            for (int r = 0; r < 8; r++) a[r] = 0.f;
            for (int k = 0; k < 128; k++) {
                float w = whhT[k * H3C + tid];
                #pragma unroll
                for (int r = 0; r < 8; r++) a[r] = fmaf(hs[r][k], w, a[r]);
            }
            #pragma unroll
            for (int r = 0; r < 8; r++) asg[r][tid] = a[r];
        }
        __syncthreads();
        if (tid < 128) {
            float br = bhh[j], bz = bhh[128 + j], bn = bhh[256 + j];
            const float* gi = giall + (size_t)t * NBC * H3C;
            #pragma unroll
            for (int r = 0; r < 8; r++) {
                size_t gx = (size_t)(r0 + r) * H3C;
                float rr = sigm(gi[gx + j] + asg[r][j] + br);
                float zz = sigm(gi[gx + 128 + j] + asg[r][128 + j] + bz);
                float nn = tanhf(gi[gx + 256 + j] + rr * (asg[r][256 + j] + bn));
                hs[r][j] = (1.f - zz) * nn + zz * hs[r][j];
            }
        }
        __syncthreads();
    }

    for (int i = tid; i < 8 * 128; i += 384)
        qs[i >> 7][i & 127] = qrel[(r0 + (i >> 7)) * 128 + (i & 127)];
    __syncthreads();

    for (int r = g; r < 8; r += 3) {
        float a = 0.f;
        for (int k = 0; k < 128; k++) a = fmaf(qs[r][k], Wh1T[k * 128 + j], a);
        ps[r][j] = a + bh1[j];
    }
    __syncthreads();
    float predv[3];
    int nmine = 0;
    for (int r = g; r < 8; r += 3) {
        float a = 0.f;
        for (int k = 0; k < 128; k++) a = fmaf(ps[r][k], Wh2T[k * 128 + j], a);
        predv[nmine++] = 0.1f * (a + bh2[j]) + qs[r][j];
    }
    __syncthreads();
    {
        int m = 0;
        for (int r = g; r < 8; r += 3) ps[r][j] = predv[m++];
    }
    __syncthreads();
    {
        float msum = 0.f;
        for (int r = g; r < 8; r += 3) {
            float d = ps[r][j] - hs[r][j];
            msum += d * d;
        }
        float bsum = blockReduceSum(msum);
        if (tid == 0) atomicAdd(&acc[2], (double)bsum);
    }
    __syncthreads();
    {
        float a[8];
        #pragma unroll
        for (int r = 0; r < 8; r++) a[r] = 0.f;
        for (int k = 0; k < 128; k++) {
            float w = whhT[k * H3C + tid];
            #pragma unroll
            for (int r = 0; r < 8; r++) a[r] = fmaf(ps[r][k], w, a[r]);
        }
        #pragma unroll
        for (int r = 0; r < 8; r++) asg[r][tid] = a[r];
    }
    __syncthreads();
    if (tid < 128) {
        float br = bhh[j], bz = bhh[128 + j], bn = bhh[256 + j];
        const float* gi = giall + (size_t)NTC * NBC * H3C;
        #pragma unroll
        for (int r = 0; r < 8; r++) {
            size_t gx = (size_t)(r0 + r) * H3C;
            float rr = sigm(gi[gx + j] + asg[r][j] + br);
            float zz = sigm(gi[gx + 128 + j] + asg[r][128 + j] + bz);
            float nn = tanhf(gi[gx + 256 + j] + rr * (asg[r][256 + j] + bn));
            hs[r][j] = (1.f - zz) * nn + zz * ps[r][j];
        }
    }
    __syncthreads();
    for (int i = tid; i < 8 * 128; i += 384) {
        int r = i >> 7, c = i & 127;
        int row = trip[(r0 + r) * 3 + 0];
        qs[r][c] = __bfloat162float(g_prebf[(size_t)row * HC + c]);
    }
    __syncthreads();
    for (int r = g; r < 8; r += 3) {
        float a = 0.f;
        for (int k = 0; k < 128; k++) a = fmaf(qs[r][k], WalT[k * 128 + j], a);
        float v = (a + bal[j]) * hs[r][j];
        g_svecb[(r0 + r) * 128 + j] = __float2bfloat16(v);
    }
}

__global__ void k_final(const double* __restrict__ acc, float* __restrict__ out) {
    if (threadIdx.x == 0) {
        out[(size_t)NBC * N_ENTC]     = (float)(acc[2] / (double)(NBC * HC));
        out[(size_t)NBC * N_ENTC + 1] = (float)((acc[0] - acc[1]) /
                                                ((double)NBC * (double)N_ENTC));
    }
}

// ---------------- host ----------------
extern "C" void kernel_launch(void* const* d_in, const int* in_sizes, int n_in,
                              void* d_out, int out_size) {
    const float* ent  = (const float*)d_in[0];
    const float* rel  = (const float*)d_in[1];
    const float* Wn   = (const float*)d_in[2];
    const float* Wl   = (const float*)d_in[3];
    const float* Wev  = (const float*)d_in[4];
    const float* wih  = (const float*)d_in[5];
    const float* whh  = (const float*)d_in[6];
    const float* bih  = (const float*)d_in[7];
    const float* bhh  = (const float*)d_in[8];
    const float* Wm1  = (const float*)d_in[9];
    const float* bm1  = (const float*)d_in[10];
    const float* Wm2  = (const float*)d_in[11];
    const float* bm2  = (const float*)d_in[12];
    const float* Wh1  = (const float*)d_in[13];
    const float* bh1  = (const float*)d_in[14];
    const float* Wh2  = (const float*)d_in[15];
    const float* bh2  = (const float*)d_in[16];
    const float* Wal  = (const float*)d_in[17];
    const float* bal  = (const float*)d_in[18];
    const float* Wat  = (const float*)d_in[19];
    const float* bat  = (const float*)d_in[20];
    const float* part = (const float*)d_in[21];
    const int* esrc = (const int*)d_in[22];
    const int* edst = (const int*)d_in[23];
    const int* etyp = (const int*)d_in[24];
    const int* trip = (const int*)d_in[25];
    float* out = (float*)d_out;

    void* basep = nullptr;
    cudaGetSymbolAddress(&basep, d_buf);
    float* F = (float*)basep;
    __nv_bfloat16 *pSvecb, *pAlnb;
    { void* p; cudaGetSymbolAddress(&p, g_svecb); pSvecb = (__nv_bfloat16*)p; }
    { void* p; cudaGetSymbolAddress(&p, g_alnbf); pAlnb  = (__nv_bfloat16*)p; }

    float* mrel   = F + O_MREL;
    float* mrelT  = F + O_MRELT;
    float* qrel   = F + O_QREL;
    float* Amat   = F + O_AMAT;
    float* giall  = F + O_GIALL;
    float* whhT   = F + O_WHHT;
    float* Wh1T   = F + O_WH1T;
    float* Wh2T   = F + O_WH2T;
    float* WatT   = F + O_WATT;
    float* WalT   = F + O_WALT;
    float* Wm1T   = F + O_WM1T;
    float* Wm2T   = F + O_WM2T;
    double* acc   = (double*)(F + O_ACC);
    int* deg      = (int*)(F + O_INT);
    int* rowptr   = deg + N_ENTC;
    int* cursor   = rowptr + N_ENTC + 1;
    int* csr      = cursor + N_ENTC;
    int* bsums    = csr + NEC;

    const int FUSED_SMEM = (2 * BGM * SSTR + BGM * XSTR) * 2;  // 55296 B
    cudaFuncSetAttribute(k_prealn, cudaFuncAttributeMaxDynamicSharedMemorySize, FUSED_SMEM);
    cudaFuncSetAttribute(k_rpgi,   cudaFuncAttributeMaxDynamicSharedMemorySize, FUSED_SMEM);

    k_init<<<640, 256>>>(Wn, Wl, Wev, wih, whh, Wal, Wh1, Wh2, Wat, Wm1, Wm2, rel,
                         deg, cursor, acc, F);
    k_count<<<(NEC + 255) / 256, 256>>>(edst, deg);
    k_entcvt<<<(N_ENTC * HC + 255) / 256, 256>>>(ent, deg);
    k_scanA<<<(N_ENTC + 1023) / 1024, 1024>>>(deg, rowptr, bsums);
    k_scanB<<<1, 1024>>>(rowptr, bsums, (N_ENTC + 1023) / 1024);
    k_fill<<<(NEC + 255) / 256, 256>>>(edst, rowptr, cursor, csr);
    k_aggregate<<<N_ENTC, 64>>>(esrc, etyp, rowptr, csr);
    k_prealn<<<(N_ENTC + BGM - 1) / BGM, 256, FUSED_SMEM>>>(bal, N_ENTC);
    k_mrel<<<46, 256>>>(rel, Wm1T, Wm2T, bm1, bm2, mrel, mrelT);
    k_qa_amat<<<256, 128>>>(mrel, trip, WatT, bat, mrelT, qrel, Amat);
    k_attn<<<NTC * NBC, 512>>>(part, Amat);
    k_rpgi<<<(NTC + 1) * NBC / BGM, 256, FUSED_SMEM>>>(bih, giall);
    k_gru_all<<<128, 384>>>(giall, whhT, bhh, qrel, Wh1T, Wh2T, bh1, bh2,
                            trip, WalT, bal, acc);
    {
        dim3 g((N_ENTC + BGN - 1) / BGN, NBC / BGM);
        k_score<<<g, 256>>>(pSvecb, pAlnb, out, trip, acc, NBC, N_ENTC);
    }
    if (out_size >= NBC * N_ENTC + 2) k_final<<<1, 32>>>(acc, out);
}

// round 9
// speedup vs baseline: 2.6757x; 1.1919x over previous
#include <cuda_runtime.h>
#include <cuda_bf16.h>
#include <stdint.h>
#include <math.h>

#define N_ENTC 20000
#define NRELC  460
#define HC     128
#define NEC    400000
#define NBC    1024
#define NTC    8
#define H3C    384
#define SLOPE  0.22916666666666666f
#define KPRE   384
#define KPAD   480
#define MT_STR 512

// ---------------- fp32 scratch ----------------
constexpr size_t O_MREL  = 0;
constexpr size_t O_MRELT = O_MREL + (size_t)NRELC * HC;
constexpr size_t O_QREL  = O_MRELT + (size_t)HC * MT_STR;
constexpr size_t O_AMAT  = O_QREL + (size_t)NBC * HC;
constexpr size_t O_GIALL = O_AMAT + (size_t)NBC * NRELC;
constexpr size_t O_WHHT  = O_GIALL + (size_t)(NTC + 1) * NBC * H3C;
constexpr size_t O_WH1T  = O_WHHT + 49152;
constexpr size_t O_WH2T  = O_WH1T + 16384;
constexpr size_t O_WATT  = O_WH2T + 16384;
constexpr size_t O_WALT  = O_WATT + 16384;
constexpr size_t O_WM1T  = O_WALT + 16384;
constexpr size_t O_WM2T  = O_WM1T + 32768;
constexpr size_t O_ACC_  = O_WM2T + 32768;
constexpr size_t O_ACC   = (O_ACC_ + 1) & ~(size_t)1;
constexpr size_t O_INT   = O_ACC + 8;
constexpr size_t N_INTS  = (size_t)N_ENTC + (N_ENTC + 1) + N_ENTC + NEC + 64;
constexpr size_t TOTALF  = O_INT + N_INTS;
__device__ __align__(16) float d_buf[TOTALF];

// ---------------- bf16 scratch ----------------
__device__ __align__(16) __nv_bfloat16 g_aggb[(size_t)N_ENTC * HC];
__device__ __align__(16) __nv_bfloat16 g_B3[HC * KPRE];
__device__ __align__(16) __nv_bfloat16 g_entb[(size_t)N_ENTC * HC];
__device__ __align__(16) __nv_bfloat16 g_relb[NRELC * HC];
__device__ __align__(16) __nv_bfloat16 g_prebf[(size_t)N_ENTC * HC];
__device__ __align__(16) __nv_bfloat16 g_alnbf[(size_t)N_ENTC * HC];
__device__ __align__(16) __nv_bfloat16 g_walb[HC * HC];
__device__ __align__(16) __nv_bfloat16 g_wihb[H3C * HC];
__device__ __align__(16) __nv_bfloat16 g_mrelTb[HC * KPAD];
__device__ __align__(16) __nv_bfloat16 g_Xb[(size_t)(NTC + 1) * NBC * HC];
__device__ __align__(16) __nv_bfloat16 g_attnb[(size_t)NTC * NBC * KPAD];
__device__ __align__(16) __nv_bfloat16 g_svecb[(size_t)NBC * HC];

// ---------------- reductions ----------------
__device__ __forceinline__ float blockReduceSum(float v) {
    __shared__ float sh[32];
    int tid = threadIdx.x;
    __syncthreads();
    #pragma unroll
    for (int o = 16; o > 0; o >>= 1) v += __shfl_xor_sync(0xffffffffu, v, o);
    if ((tid & 31) == 0) sh[tid >> 5] = v;
    __syncthreads();
    float r = 0.f;
    if (tid < 32) {
        int nw = (blockDim.x + 31) >> 5;
        r = (tid < nw) ? sh[tid] : 0.f;
        #pragma unroll
        for (int o = 16; o > 0; o >>= 1) r += __shfl_xor_sync(0xffffffffu, r, o);
    }
    return r;
}
__device__ __forceinline__ float blockReduceMax(float v) {
    __shared__ float sh[32];
    int tid = threadIdx.x;
    __syncthreads();
    #pragma unroll
    for (int o = 16; o > 0; o >>= 1) v = fmaxf(v, __shfl_xor_sync(0xffffffffu, v, o));
    if ((tid & 31) == 0) sh[tid >> 5] = v;
    __syncthreads();
    float r = -3.402823e38f;
    if (tid < 32) {
        int nw = (blockDim.x + 31) >> 5;
        r = (tid < nw) ? sh[tid] : -3.402823e38f;
        #pragma unroll
        for (int o = 16; o > 0; o >>= 1) r = fmaxf(r, __shfl_xor_sync(0xffffffffu, r, o));
    }
    return r;
}

__device__ __forceinline__ void sig_sp(float x, float& sig, float& sp) {
    float ax = fabsf(x);
    if (ax < 0.5f) {
        float x2 = x * x;
        sig = 0.5f + x * (0.25f + x2 * (-0.0208333333f + x2 * 0.0020833333f));
        sp  = 0.69314718f + 0.5f * x
            + x2 * (0.125f + x2 * (-0.0052083333f + x2 * 0.00034722222f));
    } else {
        float e = __expf(-ax);
        sig = (x >= 0.f) ? 1.f / (1.f + e) : e / (1.f + e);
        sp  = fmaxf(x, 0.f) + __logf(1.f + e);
    }
}
__device__ __forceinline__ float sigm(float x) { return 1.f / (1.f + __expf(-x)); }

// ---------------- init ----------------
__global__ void k_init(const float* __restrict__ Wn, const float* __restrict__ Wl,
                       const float* __restrict__ Wev, const float* __restrict__ wih,
                       const float* __restrict__ whh, const float* __restrict__ Wal,
                       const float* __restrict__ Wh1, const float* __restrict__ Wh2,
                       const float* __restrict__ Wat, const float* __restrict__ Wm1,
                       const float* __restrict__ Wm2, const float* __restrict__ rel,
                       int* deg, int* cursor, double* acc, float* F) {
    int i = blockIdx.x * blockDim.x + threadIdx.x;  // grid 640*256
    if (i < N_ENTC) { deg[i] = 0; cursor[i] = 0; }
    if (i == 0) { acc[0] = 0.0; acc[1] = 0.0; acc[2] = 0.0; }
    if (i < HC * KPRE) {
        int n = i / KPRE, k = i % KPRE;
        float v = (k < 128) ? Wn[k * 128 + n]
                : (k < 256) ? Wl[(k - 128) * 128 + n]
                            : Wev[(k - 256) * 128 + n];
        g_B3[i] = __float2bfloat16(v);
    }
    if (i < H3C * HC) g_wihb[i] = __float2bfloat16(wih[i]);
    if (i < HC * HC)  g_walb[i] = __float2bfloat16(Wal[i]);
    if (i < NRELC * HC) g_relb[i] = __float2bfloat16(rel[i]);
    if (i < HC * H3C) {
        int k = i / H3C, j = i % H3C;
        F[O_WHHT + i] = whh[j * 128 + k];
    }
    if (i < HC * HC) {
        int k = i / HC, j = i % HC;
        F[O_WH1T + i] = Wh1[j * HC + k];
        F[O_WH2T + i] = Wh2[j * HC + k];
        F[O_WATT + i] = Wat[j * HC + k];
        F[O_WALT + i] = Wal[j * HC + k];
    }
    if (i < 128 * 256) {
        int k = i / 256, j2 = i % 256;
        F[O_WM1T + i] = Wm1[j2 * 128 + k];
    }
    if (i < 256 * 128) {
        int k2 = i / 128, j = i % 128;
        F[O_WM2T + i] = Wm2[j * 256 + k2];
    }
    if (i < HC * (KPAD - NRELC)) {
        int j = i / (KPAD - NRELC), c = NRELC + i % (KPAD - NRELC);
        g_mrelTb[j * KPAD + c] = __float2bfloat16(0.f);
    }
    if (i < HC * (MT_STR - NRELC)) {
        int j = i / (MT_STR - NRELC), c = NRELC + i % (MT_STR - NRELC);
        F[O_MRELT + j * MT_STR + c] = 0.f;
    }
    if (i < NTC * NBC * (KPAD - NRELC)) {
        int row = i / (KPAD - NRELC), c = NRELC + i % (KPAD - NRELC);
        g_attnb[(size_t)row * KPAD + c] = __float2bfloat16(0.f);
    }
}

__global__ void k_count(const int* __restrict__ dst, int* deg) {
    int e = blockIdx.x * blockDim.x + threadIdx.x;
    if (e < NEC) atomicAdd(&deg[dst[e]], 1);
}

// ent -> bf16 copy only
__global__ void k_entcvt(const float* __restrict__ ent) {
    int i = blockIdx.x * blockDim.x + threadIdx.x;
    if (i < N_ENTC * HC) g_entb[i] = __float2bfloat16(ent[i]);
}

__global__ void k_scanA(const int* __restrict__ deg, int* rowptr, int* bsums) {
    __shared__ int wsum[32];
    int tid = threadIdx.x, lane = tid & 31, wid = tid >> 5;
    int i = blockIdx.x * 1024 + tid;
    int v = (i < N_ENTC) ? deg[i] : 0;
    int x = v;
    #pragma unroll
    for (int o = 1; o < 32; o <<= 1) {
        int t = __shfl_up_sync(0xffffffffu, x, o);
        if (lane >= o) x += t;
    }
    if (lane == 31) wsum[wid] = x;
    __syncthreads();
    if (wid == 0) {
        int s = wsum[lane];
        #pragma unroll
        for (int o = 1; o < 32; o <<= 1) {
            int t = __shfl_up_sync(0xffffffffu, s, o);
            if (lane >= o) s += t;
        }
        wsum[lane] = s;
    }
    __syncthreads();
    int woff = (wid > 0) ? wsum[wid - 1] : 0;
    int incl = x + woff;
    if (i < N_ENTC) rowptr[i] = incl - v;
    if (tid == 1023) bsums[blockIdx.x] = incl;
}

__global__ void k_scanB(int* rowptr, const int* __restrict__ bsums, int nblk) {
    __shared__ int offs[32];
    __shared__ int total_s;
    int tid = threadIdx.x;
    if (tid < 32) {
        int v = (tid < nblk) ? bsums[tid] : 0;
        int x = v;
        #pragma unroll
        for (int o = 1; o < 32; o <<= 1) {
            int t = __shfl_up_sync(0xffffffffu, x, o);
            if (tid >= o) x += t;
        }
        offs[tid] = x - v;
        if (tid == 31) total_s = x;
    }
    __syncthreads();
    for (int i = tid; i < N_ENTC; i += blockDim.x)
        rowptr[i] += offs[i >> 10];
    if (tid == 0) rowptr[N_ENTC] = total_s;
}

// fill: pack (src | typ<<16) directly into csr
__global__ void k_fill(const int* __restrict__ dst, const int* __restrict__ src,
                       const int* __restrict__ typ, const int* __restrict__ rowptr,
                       int* cursor, int* csr) {
    int e = blockIdx.x * blockDim.x + threadIdx.x;
    if (e < NEC) {
        int d = dst[e];
        int p = atomicAdd(&cursor[d], 1);
        csr[rowptr[d] + p] = src[e] | (typ[e] << 16);
    }
}

// bf16 aggregate with packed csr
__global__ void k_aggregate(const int* __restrict__ rowptr, const int* __restrict__ csr) {
    int node = blockIdx.x;
    int c = threadIdx.x;  // 64
    __shared__ int s_src[256];
    __shared__ int s_typ[256];
    const __nv_bfloat162* entb = (const __nv_bfloat162*)g_entb;
    const __nv_bfloat162* relb = (const __nv_bfloat162*)g_relb;
    int beg = rowptr[node], end = rowptr[node + 1];
    int deg = end - beg;
    float ax = 0.f, ay = 0.f;
    for (int base = beg; base < end; base += 256) {
        int cnt = min(256, end - base);
        for (int i = c; i < cnt; i += 64) {
            int p = csr[base + i];
            s_src[i] = (p & 0xFFFF) << 6;
            s_typ[i] = ((unsigned)p >> 16) << 6;
        }
        __syncthreads();
        #pragma unroll 4
        for (int i = 0; i < cnt; i++) {
            __nv_bfloat162 ev = entb[s_src[i] + c];
            __nv_bfloat162 rv = relb[s_typ[i] + c];
            ax += __bfloat162float(ev.x) + __bfloat162float(rv.x);
            ay += __bfloat162float(ev.y) + __bfloat162float(rv.y);
        }
        __syncthreads();
    }
    float inv = (deg > 0) ? 1.f / (float)deg : 0.f;
    __nv_bfloat162 o;
    o.x = __float2bfloat16(ax * inv);
    o.y = __float2bfloat16(ay * inv);
    *(__nv_bfloat162*)(g_aggb + (size_t)node * HC + 2 * c) = o;
}

// ---------------- GEMM fragment helpers ----------------
#define BGM 128
#define BGN 128
#define BGK 32
#define SSTR 40
#define XSTR 136

#define MMA_STEP(As_, Bs_, STRA, kbaseA, kk, cacc)                                   \
    {                                                                                 \
        uint32_t a[2][4], b[8][2];                                                    \
        _Pragma("unroll")                                                             \
        for (int mt = 0; mt < 2; mt++) {                                              \
            int row = wm * 32 + mt * 16 + (lane & 15);                                \
            int col = (kbaseA) + (kk) + ((lane >> 4) << 3);                           \
            uint32_t addr = (uint32_t)__cvta_generic_to_shared((As_) + row * (STRA) + col); \
            asm volatile("ldmatrix.sync.aligned.m8n8.x4.shared.b16 {%0,%1,%2,%3},[%4];" \
                         : "=r"(a[mt][0]), "=r"(a[mt][1]), "=r"(a[mt][2]), "=r"(a[mt][3]) \
                         : "r"(addr));                                                \
        }                                                                             \
        _Pragma("unroll")                                                             \
        for (int np = 0; np < 4; np++) {                                              \
            int nrow = wn * 64 + np * 16 + ((lane >> 4) << 3) + (lane & 7);           \
            int ncol = (kk) + (((lane >> 3) & 1) << 3);                               \
            uint32_t addr = (uint32_t)__cvta_generic_to_shared((Bs_) + nrow * SSTR + ncol); \
            asm volatile("ldmatrix.sync.aligned.m8n8.x4.shared.b16 {%0,%1,%2,%3},[%4];" \
                         : "=r"(b[2 * np][0]), "=r"(b[2 * np][1]),                    \
                           "=r"(b[2 * np + 1][0]), "=r"(b[2 * np + 1][1])             \
                         : "r"(addr));                                                \
        }                                                                             \
        _Pragma("unroll")                                                             \
        for (int mt = 0; mt < 2; mt++)                                                \
            _Pragma("unroll")                                                         \
            for (int nt = 0; nt < 8; nt++)                                            \
                asm volatile(                                                         \
                    "mma.sync.aligned.m16n8k16.row.col.f32.bf16.bf16.f32 "            \
                    "{%0,%1,%2,%3},{%4,%5,%6,%7},{%8,%9},{%0,%1,%2,%3};"              \
                    : "+f"(cacc[mt][nt][0]), "+f"(cacc[mt][nt][1]),                   \
                      "+f"(cacc[mt][nt][2]), "+f"(cacc[mt][nt][3])                    \
                    : "r"(a[mt][0]), "r"(a[mt][1]), "r"(a[mt][2]), "r"(a[mt][3]),     \
                      "r"(b[nt][0]), "r"(b[nt][1]));                                  \
    }

// ---------------- score GEMM ----------------
__global__ __launch_bounds__(256)
void k_score(const __nv_bfloat16* __restrict__ A, const __nv_bfloat16* __restrict__ B,
             float* __restrict__ Cf, const int* __restrict__ trip, double* acc,
             int M, int N) {
    __shared__ __nv_bfloat16 As[BGM * SSTR];
    __shared__ __nv_bfloat16 Bs[BGN * SSTR];
    int tid = threadIdx.x;
    int lane = tid & 31, wid = tid >> 5;
    int wm = wid & 3, wn = wid >> 2;
    int rowBase = blockIdx.y * BGM;
    int colBase = blockIdx.x * BGN;
    float c[2][8][4];
    #pragma unroll
    for (int i = 0; i < 2; i++)
        #pragma unroll
        for (int j = 0; j < 8; j++)
            #pragma unroll
            for (int q = 0; q < 4; q++) c[i][j][q] = 0.f;
    for (int k0 = 0; k0 < HC; k0 += BGK) {
        #pragma unroll
        for (int i = 0; i < 2; i++) {
            int idx = tid + i * 256;
            int r = idx >> 2, seg = idx & 3;
            *(uint4*)(As + r * SSTR + seg * 8) =
                *(const uint4*)(A + (size_t)(rowBase + r) * HC + k0 + seg * 8);
            uint4 vb = make_uint4(0, 0, 0, 0);
            int gn = colBase + r;
            if (gn < N) vb = *(const uint4*)(B + (size_t)gn * HC + k0 + seg * 8);
            *(uint4*)(Bs + r * SSTR + seg * 8) = vb;
        }
        __syncthreads();
        MMA_STEP(As, Bs, SSTR, 0, 0, c)
        MMA_STEP(As, Bs, SSTR, 0, 16, c)
        __syncthreads();
    }
    float lsp = 0.f, lxo = 0.f;
    #pragma unroll
    for (int mt = 0; mt < 2; mt++) {
        int r0 = rowBase + wm * 32 + mt * 16 + (lane >> 2);
        int ob0 = trip[r0 * 3 + 2];
        int ob1 = trip[(r0 + 8) * 3 + 2];
        #pragma unroll
        for (int nt = 0; nt < 8; nt++) {
            int col = colBase + wn * 64 + nt * 8 + ((lane & 3) << 1);
            if (col < N) {
                #pragma unroll
                for (int half = 0; half < 2; half++) {
                    int row = r0 + half * 8;
                    int ob = half ? ob1 : ob0;
                    float x0 = c[mt][nt][half * 2 + 0];
                    float x1 = c[mt][nt][half * 2 + 1];
                    float s0, p0, s1, p1;
                    sig_sp(x0, s0, p0);
                    sig_sp(x1, s1, p1);
                    *(float2*)(Cf + (size_t)row * N + col) = make_float2(s0, s1);
                    lsp += p0 + p1;
                    if (col == ob) lxo += x0;
                    if (col + 1 == ob) lxo += x1;
                }
            }
        }
    }
    float bs = blockReduceSum(lsp);
    float bx = blockReduceSum(lxo);
    if (tid == 0) {
        atomicAdd(&acc[0], (double)bs);
        atomicAdd(&acc[1], (double)bx);
    }
}

// ---------------- fused pre+aln (reads aggb + masked entb directly) ----------------
__global__ __launch_bounds__(256)
void k_prealn(const float* __restrict__ bal, const int* __restrict__ deg, int M) {
    extern __shared__ __nv_bfloat16 sm[];
    __nv_bfloat16* As = sm;
    __nv_bfloat16* Bs = sm + BGM * SSTR;
    __nv_bfloat16* Xs = sm + 2 * BGM * SSTR;
    int tid = threadIdx.x, lane = tid & 31, wid = tid >> 5;
    int wm = wid & 3, wn = wid >> 2;
    int rowBase = blockIdx.x * BGM;
    // per-thread row info for loader (2 rows per thread)
    int lr[2]; bool lv[2], lm[2];
    #pragma unroll
    for (int i = 0; i < 2; i++) {
        int idx = tid + i * 256;
        lr[i] = idx >> 2;
        int gr = rowBase + lr[i];
        lv[i] = gr < M;
        lm[i] = lv[i] && (deg[lv[i] ? gr : 0] > 0);
    }
    float c[2][8][4];
    #pragma unroll
    for (int i = 0; i < 2; i++)
        #pragma unroll
        for (int j = 0; j < 8; j++)
            #pragma unroll
            for (int q = 0; q < 4; q++) c[i][j][q] = 0.f;
    for (int k0 = 0; k0 < KPRE; k0 += BGK) {
        #pragma unroll
        for (int i = 0; i < 2; i++) {
            int idx = tid + i * 256;
            int r = lr[i], seg = idx & 3;
            int gr = rowBase + r;
            int kc = k0 + seg * 8;
            uint4 va = make_uint4(0, 0, 0, 0);
            if (lv[i]) {
                if (k0 < 128) {
                    va = *(const uint4*)(g_aggb + (size_t)gr * HC + kc);
                } else if (k0 < 256) {
                    if (lm[i]) va = *(const uint4*)(g_entb + (size_t)gr * HC + kc - 128);
                } else {
                    if (!lm[i]) va = *(const uint4*)(g_entb + (size_t)gr * HC + kc - 256);
                }
            }
            *(uint4*)(As + r * SSTR + seg * 8) = va;
            *(uint4*)(Bs + r * SSTR + seg * 8) =
                *(const uint4*)(g_B3 + (size_t)r * KPRE + k0 + seg * 8);
        }
        __syncthreads();
        MMA_STEP(As, Bs, SSTR, 0, 0, c)
        MMA_STEP(As, Bs, SSTR, 0, 16, c)
        __syncthreads();
    }
    #pragma unroll
    for (int mt = 0; mt < 2; mt++) {
        #pragma unroll
        for (int nt = 0; nt < 8; nt++) {
            int colL = wn * 64 + nt * 8 + ((lane & 3) << 1);
            #pragma unroll
            for (int half = 0; half < 2; half++) {
                int rowL = wm * 32 + mt * 16 + (lane >> 2) + half * 8;
                float v0 = c[mt][nt][half * 2 + 0];
                float v1 = c[mt][nt][half * 2 + 1];
                v0 = (v0 >= 0.f) ? v0 : v0 * SLOPE;
                v1 = (v1 >= 0.f) ? v1 : v1 * SLOPE;
                __nv_bfloat162 bv(__float2bfloat16(v0), __float2bfloat16(v1));
                *(__nv_bfloat162*)(Xs + rowL * XSTR + colL) = bv;
                int grow = rowBase + rowL;
                if (grow < M)
                    *(__nv_bfloat162*)(g_prebf + (size_t)grow * HC + colL) = bv;
            }
        }
    }
    __syncthreads();
    float c2[2][8][4];
    #pragma unroll
    for (int i = 0; i < 2; i++)
        #pragma unroll
        for (int j = 0; j < 8; j++)
            #pragma unroll
            for (int q = 0; q < 4; q++) c2[i][j][q] = 0.f;
    for (int k0 = 0; k0 < HC; k0 += BGK) {
        #pragma unroll
        for (int i = 0; i < 2; i++) {
            int idx = tid + i * 256;
            int r = idx >> 2, seg = idx & 3;
            *(uint4*)(Bs + r * SSTR + seg * 8) =
                *(const uint4*)(g_walb + (size_t)r * HC + k0 + seg * 8);
        }
        __syncthreads();
        MMA_STEP(Xs, Bs, XSTR, k0, 0, c2)
        MMA_STEP(Xs, Bs, XSTR, k0, 16, c2)
        __syncthreads();
    }
    #pragma unroll
    for (int mt = 0; mt < 2; mt++) {
        #pragma unroll
        for (int nt = 0; nt < 8; nt++) {
            int colL = wn * 64 + nt * 8 + ((lane & 3) << 1);
            float b0 = bal[colL], b1 = bal[colL + 1];
            #pragma unroll
            for (int half = 0; half < 2; half++) {
                int grow = rowBase + wm * 32 + mt * 16 + (lane >> 2) + half * 8;
                if (grow < M) {
                    __nv_bfloat162 bv(__float2bfloat16(c2[mt][nt][half * 2 + 0] + b0),
                                      __float2bfloat16(c2[mt][nt][half * 2 + 1] + b1));
                    *(__nv_bfloat162*)(g_alnbf + (size_t)grow * HC + colL) = bv;
                }
            }
        }
    }
}

// ---------------- fused rpath+giall ----------------
__global__ __launch_bounds__(256)
void k_rpgi(const float* __restrict__ bih, float* __restrict__ giall) {
    extern __shared__ __nv_bfloat16 sm[];
    __nv_bfloat16* As = sm;
    __nv_bfloat16* Bs = sm + BGM * SSTR;
    __nv_bfloat16* Xs = sm + 2 * BGM * SSTR;
    int tid = threadIdx.x, lane = tid & 31, wid = tid >> 5;
    int wm = wid & 3, wn = wid >> 2;
    int rowBase = blockIdx.x * BGM;
    if (blockIdx.x < 64) {
        float c[2][8][4];
        #pragma unroll
        for (int i = 0; i < 2; i++)
            #pragma unroll
            for (int j = 0; j < 8; j++)
                #pragma unroll
                for (int q = 0; q < 4; q++) c[i][j][q] = 0.f;
        for (int k0 = 0; k0 < KPAD; k0 += BGK) {
            #pragma unroll
            for (int i = 0; i < 2; i++) {
                int idx = tid + i * 256;
                int r = idx >> 2, seg = idx & 3;
                *(uint4*)(As + r * SSTR + seg * 8) =
                    *(const uint4*)(g_attnb + (size_t)(rowBase + r) * KPAD + k0 + seg * 8);
                *(uint4*)(Bs + r * SSTR + seg * 8) =
                    *(const uint4*)(g_mrelTb + (size_t)r * KPAD + k0 + seg * 8);
            }
            __syncthreads();
            MMA_STEP(As, Bs, SSTR, 0, 0, c)
            MMA_STEP(As, Bs, SSTR, 0, 16, c)
            __syncthreads();
        }
        #pragma unroll
        for (int mt = 0; mt < 2; mt++)
            #pragma unroll
            for (int nt = 0; nt < 8; nt++) {
                int colL = wn * 64 + nt * 8 + ((lane & 3) << 1);
                #pragma unroll
                for (int half = 0; half < 2; half++) {
                    int rowL = wm * 32 + mt * 16 + (lane >> 2) + half * 8;
                    __nv_bfloat162 bv(__float2bfloat16(c[mt][nt][half * 2 + 0]),
                                      __float2bfloat16(c[mt][nt][half * 2 + 1]));
                    *(__nv_bfloat162*)(Xs + rowL * XSTR + colL) = bv;
                }
            }
    } else {
        for (int i = tid; i < BGM * (HC / 8); i += 256) {
            int r = i / (HC / 8), seg = i % (HC / 8);
            *(uint4*)(Xs + r * XSTR + seg * 8) =
                *(const uint4*)(g_Xb + (size_t)(rowBase + r) * HC + seg * 8);
        }
    }
    __syncthreads();
    for (int nb = 0; nb < 3; nb++) {
        float c2[2][8][4];
        #pragma unroll
        for (int i = 0; i < 2; i++)
            #pragma unroll
            for (int j = 0; j < 8; j++)
                #pragma unroll
                for (int q = 0; q < 4; q++) c2[i][j][q] = 0.f;
        for (int k0 = 0; k0 < HC; k0 += BGK) {
            #pragma unroll
            for (int i = 0; i < 2; i++) {
                int idx = tid + i * 256;
                int r = idx >> 2, seg = idx & 3;
                *(uint4*)(Bs + r * SSTR + seg * 8) =
                    *(const uint4*)(g_wihb + (size_t)(nb * 128 + r) * HC + k0 + seg * 8);
            }
            __syncthreads();
            MMA_STEP(Xs, Bs, XSTR, k0, 0, c2)
            MMA_STEP(Xs, Bs, XSTR, k0, 16, c2)
            __syncthreads();
        }
        #pragma unroll
        for (int mt = 0; mt < 2; mt++)
            #pragma unroll
            for (int nt = 0; nt < 8; nt++) {
                int colL = wn * 64 + nt * 8 + ((lane & 3) << 1);
                int col = nb * 128 + colL;
                float b0 = bih[col], b1 = bih[col + 1];
                #pragma unroll
                for (int half = 0; half < 2; half++) {
                    int row = rowBase + wm * 32 + mt * 16 + (lane >> 2) + half * 8;
                    *(float2*)(giall + (size_t)row * H3C + col) =
                        make_float2(c2[mt][nt][half * 2 + 0] + b0,
                                    c2[mt][nt][half * 2 + 1] + b1);
                }
            }
    }
}

// ---------------- fused mapped_rel ----------------
__global__ __launch_bounds__(256)
void k_mrel(const float* __restrict__ rel, const float* __restrict__ Wm1T,
            const float* __restrict__ Wm2T, const float* __restrict__ bm1,
            const float* __restrict__ bm2, float* __restrict__ mrel,
            float* __restrict__ mrelT) {
    __shared__ float rels[10][128];
    __shared__ float p1s[10][256];
    int tid = threadIdx.x;
    int r0 = blockIdx.x * 10;
    for (int i = tid; i < 10 * 128; i += 256)
        rels[i >> 7][i & 127] = rel[(r0 + (i >> 7)) * 128 + (i & 127)];
    __syncthreads();
    {
        int j2 = tid;
        float a[10];
        #pragma unroll
        for (int r = 0; r < 10; r++) a[r] = 0.f;
        for (int k = 0; k < 128; k++) {
            float w = Wm1T[k * 256 + j2];
            #pragma unroll
            for (int r = 0; r < 10; r++) a[r] = fmaf(rels[r][k], w, a[r]);
        }
        float b = bm1[j2];
        #pragma unroll
        for (int r = 0; r < 10; r++) p1s[r][j2] = a[r] + b;
    }
    __syncthreads();
    {
        int j = tid & 127, half = tid >> 7;
        float a[5];
        #pragma unroll
        for (int r = 0; r < 5; r++) a[r] = 0.f;
        for (int k = 0; k < 256; k++) {
            float w = Wm2T[k * 128 + j];
            #pragma unroll
            for (int r = 0; r < 5; r++) a[r] = fmaf(p1s[half * 5 + r][k], w, a[r]);
        }
        float b = bm2[j];
        #pragma unroll
        for (int r = 0; r < 5; r++) {
            int row = r0 + half * 5 + r;
            float v = a[r] + b;
            mrel[row * 128 + j] = v;
            mrelT[j * MT_STR + row] = v;
            g_mrelTb[j * KPAD + row] = __float2bfloat16(v);
        }
    }
}

__global__ __launch_bounds__(128)
void k_qa_amat(const float* __restrict__ mrel, const int* __restrict__ trip,
               const float* __restrict__ WatT, const float* __restrict__ bat,
               const float* __restrict__ mrelT, float* __restrict__ qrel,
               float* __restrict__ Amat) {
    __shared__ float q[4][128];
    __shared__ float qa[4][128];
    int j = threadIdx.x;
    int r0 = blockIdx.x * 4;
    #pragma unroll
    for (int r = 0; r < 4; r++) {
        float v = mrel[(size_t)trip[(r0 + r) * 3 + 1] * HC + j];
        q[r][j] = v;
        qrel[(r0 + r) * 128 + j] = v;
        g_Xb[(size_t)(NTC * NBC + r0 + r) * HC + j] = __float2bfloat16(v);
    }
    __syncthreads();
    {
        float a[4] = {0.f, 0.f, 0.f, 0.f};
        for (int k = 0; k < 128; k++) {
            float w = WatT[k * 128 + j];
            #pragma unroll
            for (int r = 0; r < 4; r++) a[r] = fmaf(q[r][k], w, a[r]);
        }
        float b = bat[j];
        #pragma unroll
        for (int r = 0; r < 4; r++) qa[r][j] = a[r] + b;
    }
    __syncthreads();
    #pragma unroll
    for (int r = 0; r < 4; r++) {
        float a[4] = {0.f, 0.f, 0.f, 0.f};
        for (int k = 0; k < 128; k++) {
            float qv = qa[r][k];
            #pragma unroll
            for (int t = 0; t < 4; t++)
                a[t] = fmaf(qv, mrelT[k * MT_STR + j + t * 128], a[t]);
        }
        #pragma unroll
        for (int t = 0; t < 4; t++) {
            int n = j + t * 128;
            if (n < NRELC) Amat[(size_t)(r0 + r) * NRELC + n] = a[t];
        }
    }
}

__global__ void k_attn(const float* __restrict__ part, const float* __restrict__ Amat) {
    int tb = blockIdx.x;
    int t = tb >> 10, b = tb & 1023;
    int tid = threadIdx.x;  // 512
    float x = -3.402823e38f;
    if (tid < NRELC) {
        float cur = part[(size_t)b * (NTC * NRELC) + t * NRELC + tid];
        float a = Amat[(size_t)b * NRELC + tid];
        float val = cur * a;
        x = (val == 0.f) ? -1e9f : val;
    }
    float m = blockReduceMax(x);
    __shared__ float sm_m, sm_inv;
    if (tid == 0) sm_m = m;
    __syncthreads();
    m = sm_m;
    float e = (tid < NRELC) ? __expf(x - m) : 0.f;
    float s = blockReduceSum(e);
    if (tid == 0) sm_inv = 1.f / s;
    __syncthreads();
    float inv = sm_inv;
    if (tid < NRELC)
        g_attnb[(size_t)tb * KPAD + tid] = __float2bfloat16(e * inv);
}

// ---------------- mega GRU kernel ----------------
__global__ __launch_bounds__(384)
void k_gru_all(const float* __restrict__ giall, const float* __restrict__ whhT,
               const float* __restrict__ bhh, const float* __restrict__ qrel,
               const float* __restrict__ Wh1T, const float* __restrict__ Wh2T,
               const float* __restrict__ bh1, const float* __restrict__ bh2,
               const int* __restrict__ trip, const float* __restrict__ WalT,
               const float* __restrict__ bal, double* acc) {
    __shared__ float hs[8][128];
    __shared__ float asg[8][384];
    __shared__ float qs[8][128];
    __shared__ float ps[8][128];
    int tid = threadIdx.x;
    int j = tid & 127;
    int g = tid >> 7;
    int r0 = blockIdx.x * 8;

    for (int i = tid; i < 8 * 128; i += 384) hs[i >> 7][i & 127] = 0.f;
    __syncthreads();

    for (int t = 0; t < NTC; t++) {
        {
            float a[8];
            #pragma unroll
            for (int r = 0; r < 8; r++) a[r] = 0.f;
            for (int k = 0; k < 128; k++) {
                float w = whhT[k * H3C + tid];
                #pragma unroll
                for (int r = 0; r < 8; r++) a[r] = fmaf(hs[r][k], w, a[r]);
            }
            #pragma unroll
            for (int r = 0; r < 8; r++) asg[r][tid] = a[r];
        }
        __syncthreads();
        if (tid < 128) {
            float br = bhh[j], bz = bhh[128 + j], bn = bhh[256 + j];
            const float* gi = giall + (size_t)t * NBC * H3C;
            #pragma unroll
            for (int r = 0; r < 8; r++) {
                size_t gx = (size_t)(r0 + r) * H3C;
                float rr = sigm(gi[gx + j] + asg[r][j] + br);
                float zz = sigm(gi[gx + 128 + j] + asg[r][128 + j] + bz);
                float nn = tanhf(gi[gx + 256 + j] + rr * (asg[r][256 + j] + bn));
                hs[r][j] = (1.f - zz) * nn + zz * hs[r][j];
            }
        }
        __syncthreads();
    }

    for (int i = tid; i < 8 * 128; i += 384)
        qs[i >> 7][i & 127] = qrel[(r0 + (i >> 7)) * 128 + (i & 127)];
    __syncthreads();

    for (int r = g; r < 8; r += 3) {
        float a = 0.f;
        for (int k = 0; k < 128; k++) a = fmaf(qs[r][k], Wh1T[k * 128 + j], a);
        ps[r][j] = a + bh1[j];
    }
    __syncthreads();
    float predv[3];
    int nmine = 0;
    for (int r = g; r < 8; r += 3) {
        float a = 0.f;
        for (int k = 0; k < 128; k++) a = fmaf(ps[r][k], Wh2T[k * 128 + j], a);
        predv[nmine++] = 0.1f * (a + bh2[j]) + qs[r][j];
    }
    __syncthreads();
    {
        int m = 0;
        for (int r = g; r < 8; r += 3) ps[r][j] = predv[m++];
    }
    __syncthreads();
    {
        float msum = 0.f;
        for (int r = g; r < 8; r += 3) {
            float d = ps[r][j] - hs[r][j];
            msum += d * d;
        }
        float bsum = blockReduceSum(msum);
        if (tid == 0) atomicAdd(&acc[2], (double)bsum);
    }
    __syncthreads();
    {
        float a[8];
        #pragma unroll
        for (int r = 0; r < 8; r++) a[r] = 0.f;
        for (int k = 0; k < 128; k++) {
            float w = whhT[k * H3C + tid];
            #pragma unroll
            for (int r = 0; r < 8; r++) a[r] = fmaf(ps[r][k], w, a[r]);
        }
        #pragma unroll
        for (int r = 0; r < 8; r++) asg[r][tid] = a[r];
    }
    __syncthreads();
    if (tid < 128) {
        float br = bhh[j], bz = bhh[128 + j], bn = bhh[256 + j];
        const float* gi = giall + (size_t)NTC * NBC * H3C;
        #pragma unroll
        for (int r = 0; r < 8; r++) {
            size_t gx = (size_t)(r0 + r) * H3C;
            float rr = sigm(gi[gx + j] + asg[r][j] + br);
            float zz = sigm(gi[gx + 128 + j] + asg[r][128 + j] + bz);
            float nn = tanhf(gi[gx + 256 + j] + rr * (asg[r][256 + j] + bn));
            hs[r][j] = (1.f - zz) * nn + zz * ps[r][j];
        }
    }
    __syncthreads();
    for (int i = tid; i < 8 * 128; i += 384) {
        int r = i >> 7, c = i & 127;
        int row = trip[(r0 + r) * 3 + 0];
        qs[r][c] = __bfloat162float(g_prebf[(size_t)row * HC + c]);
    }
    __syncthreads();
    for (int r = g; r < 8; r += 3) {
        float a = 0.f;
        for (int k = 0; k < 128; k++) a = fmaf(qs[r][k], WalT[k * 128 + j], a);
        float v = (a + bal[j]) * hs[r][j];
        g_svecb[(r0 + r) * 128 + j] = __float2bfloat16(v);
    }
}

__global__ void k_final(const double* __restrict__ acc, float* __restrict__ out) {
    if (threadIdx.x == 0) {
        out[(size_t)NBC * N_ENTC]     = (float)(acc[2] / (double)(NBC * HC));
        out[(size_t)NBC * N_ENTC + 1] = (float)((acc[0] - acc[1]) /
                                                ((double)NBC * (double)N_ENTC));
    }
}

// ---------------- host ----------------
extern "C" void kernel_launch(void* const* d_in, const int* in_sizes, int n_in,
                              void* d_out, int out_size) {
    const float* ent  = (const float*)d_in[0];
    const float* rel  = (const float*)d_in[1];
    const float* Wn   = (const float*)d_in[2];
    const float* Wl   = (const float*)d_in[3];
    const float* Wev  = (const float*)d_in[4];
    const float* wih  = (const float*)d_in[5];
    const float* whh  = (const float*)d_in[6];
    const float* bih  = (const float*)d_in[7];
    const float* bhh  = (const float*)d_in[8];
    const float* Wm1  = (const float*)d_in[9];
    const float* bm1  = (const float*)d_in[10];
    const float* Wm2  = (const float*)d_in[11];
    const float* bm2  = (const float*)d_in[12];
    const float* Wh1  = (const float*)d_in[13];
    const float* bh1  = (const float*)d_in[14];
    const float* Wh2  = (const float*)d_in[15];
    const float* bh2  = (const float*)d_in[16];
    const float* Wal  = (const float*)d_in[17];
    const float* bal  = (const float*)d_in[18];
    const float* Wat  = (const float*)d_in[19];
    const float* bat  = (const float*)d_in[20];
    const float* part = (const float*)d_in[21];
    const int* esrc = (const int*)d_in[22];
    const int* edst = (const int*)d_in[23];
    const int* etyp = (const int*)d_in[24];
    const int* trip = (const int*)d_in[25];
    float* out = (float*)d_out;

    void* basep = nullptr;
    cudaGetSymbolAddress(&basep, d_buf);
    float* F = (float*)basep;
    __nv_bfloat16 *pSvecb, *pAlnb;
    { void* p; cudaGetSymbolAddress(&p, g_svecb); pSvecb = (__nv_bfloat16*)p; }
    { void* p; cudaGetSymbolAddress(&p, g_alnbf); pAlnb  = (__nv_bfloat16*)p; }

    float* mrel   = F + O_MREL;
    float* mrelT  = F + O_MRELT;
    float* qrel   = F + O_QREL;
    float* Amat   = F + O_AMAT;
    float* giall  = F + O_GIALL;
    float* whhT   = F + O_WHHT;
    float* Wh1T   = F + O_WH1T;
    float* Wh2T   = F + O_WH2T;
    float* WatT   = F + O_WATT;
    float* WalT   = F + O_WALT;
    float* Wm1T   = F + O_WM1T;
    float* Wm2T   = F + O_WM2T;
    double* acc   = (double*)(F + O_ACC);
    int* deg      = (int*)(F + O_INT);
    int* rowptr   = deg + N_ENTC;
    int* cursor   = rowptr + N_ENTC + 1;
    int* csr      = cursor + N_ENTC;
    int* bsums    = csr + NEC;

    const int FUSED_SMEM = (2 * BGM * SSTR + BGM * XSTR) * 2;  // 55296 B
    static bool s_init = false;
    static cudaStream_t sB = 0;
    static cudaEvent_t evF = 0, evB = 0;
    if (!s_init) {
        cudaFuncSetAttribute(k_prealn, cudaFuncAttributeMaxDynamicSharedMemorySize, FUSED_SMEM);
        cudaFuncSetAttribute(k_rpgi,   cudaFuncAttributeMaxDynamicSharedMemorySize, FUSED_SMEM);
        cudaStreamCreateWithFlags(&sB, cudaStreamNonBlocking);
        cudaEventCreateWithFlags(&evF, cudaEventDisableTiming);
        cudaEventCreateWithFlags(&evB, cudaEventDisableTiming);
        s_init = true;
    }

    k_init<<<640, 256>>>(Wn, Wl, Wev, wih, whh, Wal, Wh1, Wh2, Wat, Wm1, Wm2, rel,
                         deg, cursor, acc, F);
    cudaEventRecord(evF, 0);
    cudaStreamWaitEvent(sB, evF, 0);

    // ---- chain B (relation path) on sB ----
    k_mrel<<<46, 256, 0, sB>>>(rel, Wm1T, Wm2T, bm1, bm2, mrel, mrelT);
    k_qa_amat<<<256, 128, 0, sB>>>(mrel, trip, WatT, bat, mrelT, qrel, Amat);
    k_attn<<<NTC * NBC, 512, 0, sB>>>(part, Amat);
    k_rpgi<<<(NTC + 1) * NBC / BGM, 256, FUSED_SMEM, sB>>>(bih, giall);
    cudaEventRecord(evB, sB);

    // ---- chain A (entity path) on default stream ----
    k_count<<<(NEC + 255) / 256, 256>>>(edst, deg);
    k_entcvt<<<(N_ENTC * HC + 255) / 256, 256>>>(ent);
    k_scanA<<<(N_ENTC + 1023) / 1024, 1024>>>(deg, rowptr, bsums);
    k_scanB<<<1, 1024>>>(rowptr, bsums, (N_ENTC + 1023) / 1024);
    k_fill<<<(NEC + 255) / 256, 256>>>(edst, esrc, etyp, rowptr, cursor, csr);
    k_aggregate<<<N_ENTC, 64>>>(rowptr, csr);
    k_prealn<<<(N_ENTC + BGM - 1) / BGM, 256, FUSED_SMEM>>>(bal, deg, N_ENTC);

    // ---- join ----
    cudaStreamWaitEvent(0, evB, 0);
    k_gru_all<<<128, 384>>>(giall, whhT, bhh, qrel, Wh1T, Wh2T, bh1, bh2,
                            trip, WalT, bal, acc);
    {
        dim3 g((N_ENTC + BGN - 1) / BGN, NBC / BGM);
        k_score<<<g, 256>>>(pSvecb, pAlnb, out, trip, acc, NBC, N_ENTC);
    }
    if (out_size >= NBC * N_ENTC + 2) k_final<<<1, 32>>>(acc, out);
}

// round 10
// speedup vs baseline: 2.8691x; 1.0723x over previous
#include <cuda_runtime.h>
#include <cuda_bf16.h>
#include <stdint.h>
#include <math.h>

#define N_ENTC 20000
#define NRELC  460
#define HC     128
#define NEC    400000
#define NBC    1024
#define NTC    8
#define H3C    384
#define SLOPE  0.22916666666666666f
#define KPRE   384
#define KPAD   480
#define MT_STR 512

// ---------------- fp32 scratch ----------------
constexpr size_t O_MREL  = 0;
constexpr size_t O_MRELT = O_MREL + (size_t)NRELC * HC;
constexpr size_t O_QREL  = O_MRELT + (size_t)HC * MT_STR;
constexpr size_t O_AMAT  = O_QREL + (size_t)NBC * HC;
constexpr size_t O_GIALL = O_AMAT + (size_t)NBC * NRELC;
constexpr size_t O_WHHT  = O_GIALL + (size_t)(NTC + 1) * NBC * H3C;
constexpr size_t O_WH1T  = O_WHHT + 49152;
constexpr size_t O_WH2T  = O_WH1T + 16384;
constexpr size_t O_WATT  = O_WH2T + 16384;
constexpr size_t O_WALT  = O_WATT + 16384;
constexpr size_t O_WM1T  = O_WALT + 16384;
constexpr size_t O_WM2T  = O_WM1T + 32768;
constexpr size_t O_ACC_  = O_WM2T + 32768;
constexpr size_t O_ACC   = (O_ACC_ + 1) & ~(size_t)1;
constexpr size_t O_INT   = O_ACC + 8;
constexpr size_t N_INTS  = (size_t)N_ENTC + (N_ENTC + 1) + N_ENTC + NEC + 64;
constexpr size_t TOTALF  = O_INT + N_INTS;
__device__ __align__(16) float d_buf[TOTALF];

// ---------------- bf16 scratch ----------------
__device__ __align__(16) __nv_bfloat16 g_aggb[(size_t)N_ENTC * HC];
__device__ __align__(16) __nv_bfloat16 g_B3[HC * KPRE];
__device__ __align__(16) __nv_bfloat16 g_entb[(size_t)N_ENTC * HC];
__device__ __align__(16) __nv_bfloat16 g_relb[NRELC * HC];
__device__ __align__(16) __nv_bfloat16 g_prebf[(size_t)N_ENTC * HC];
__device__ __align__(16) __nv_bfloat16 g_alnbf[(size_t)N_ENTC * HC];
__device__ __align__(16) __nv_bfloat16 g_walb[HC * HC];
__device__ __align__(16) __nv_bfloat16 g_wihb[H3C * HC];
__device__ __align__(16) __nv_bfloat16 g_mrelTb[HC * KPAD];
__device__ __align__(16) __nv_bfloat16 g_Xb[(size_t)(NTC + 1) * NBC * HC];
__device__ __align__(16) __nv_bfloat16 g_attnb[(size_t)NTC * NBC * KPAD];
__device__ __align__(16) __nv_bfloat16 g_svecb[(size_t)NBC * HC];

// ---------------- reductions ----------------
__device__ __forceinline__ float blockReduceSum(float v) {
    __shared__ float sh[32];
    int tid = threadIdx.x;
    __syncthreads();
    #pragma unroll
    for (int o = 16; o > 0; o >>= 1) v += __shfl_xor_sync(0xffffffffu, v, o);
    if ((tid & 31) == 0) sh[tid >> 5] = v;
    __syncthreads();
    float r = 0.f;
    if (tid < 32) {
        int nw = (blockDim.x + 31) >> 5;
        r = (tid < nw) ? sh[tid] : 0.f;
        #pragma unroll
        for (int o = 16; o > 0; o >>= 1) r += __shfl_xor_sync(0xffffffffu, r, o);
    }
    return r;
}

__device__ __forceinline__ void sig_sp(float x, float& sig, float& sp) {
    float ax = fabsf(x);
    if (ax < 0.5f) {
        float x2 = x * x;
        sig = 0.5f + x * (0.25f + x2 * (-0.0208333333f + x2 * 0.0020833333f));
        sp  = 0.69314718f + 0.5f * x
            + x2 * (0.125f + x2 * (-0.0052083333f + x2 * 0.00034722222f));
    } else {
        float e = __expf(-ax);
        sig = (x >= 0.f) ? 1.f / (1.f + e) : e / (1.f + e);
        sp  = fmaxf(x, 0.f) + __logf(1.f + e);
    }
}
__device__ __forceinline__ float sigm(float x) { return 1.f / (1.f + __expf(-x)); }

// ---------------- init ----------------
__global__ void k_init(const float* __restrict__ Wn, const float* __restrict__ Wl,
                       const float* __restrict__ Wev, const float* __restrict__ wih,
                       const float* __restrict__ whh, const float* __restrict__ Wal,
                       const float* __restrict__ Wh1, const float* __restrict__ Wh2,
                       const float* __restrict__ Wat, const float* __restrict__ Wm1,
                       const float* __restrict__ Wm2, const float* __restrict__ rel,
                       int* deg, int* cursor, double* acc, float* F) {
    int i = blockIdx.x * blockDim.x + threadIdx.x;  // grid 640*256
    if (i < N_ENTC) { deg[i] = 0; cursor[i] = 0; }
    if (i == 0) { acc[0] = 0.0; acc[1] = 0.0; acc[2] = 0.0; }
    if (i < HC * KPRE) {
        int n = i / KPRE, k = i % KPRE;
        float v = (k < 128) ? Wn[k * 128 + n]
                : (k < 256) ? Wl[(k - 128) * 128 + n]
                            : Wev[(k - 256) * 128 + n];
        g_B3[i] = __float2bfloat16(v);
    }
    if (i < H3C * HC) g_wihb[i] = __float2bfloat16(wih[i]);
    if (i < HC * HC)  g_walb[i] = __float2bfloat16(Wal[i]);
    if (i < NRELC * HC) g_relb[i] = __float2bfloat16(rel[i]);
    if (i < HC * H3C) {
        int k = i / H3C, j = i % H3C;
        F[O_WHHT + i] = whh[j * 128 + k];
    }
    if (i < HC * HC) {
        int k = i / HC, j = i % HC;
        F[O_WH1T + i] = Wh1[j * HC + k];
        F[O_WH2T + i] = Wh2[j * HC + k];
        F[O_WATT + i] = Wat[j * HC + k];
        F[O_WALT + i] = Wal[j * HC + k];
    }
    if (i < 128 * 256) {
        int k = i / 256, j2 = i % 256;
        F[O_WM1T + i] = Wm1[j2 * 128 + k];
    }
    if (i < 256 * 128) {
        int k2 = i / 128, j = i % 128;
        F[O_WM2T + i] = Wm2[j * 256 + k2];
    }
    if (i < HC * (KPAD - NRELC)) {
        int j = i / (KPAD - NRELC), c = NRELC + i % (KPAD - NRELC);
        g_mrelTb[j * KPAD + c] = __float2bfloat16(0.f);
    }
    if (i < HC * (MT_STR - NRELC)) {
        int j = i / (MT_STR - NRELC), c = NRELC + i % (MT_STR - NRELC);
        F[O_MRELT + j * MT_STR + c] = 0.f;
    }
    if (i < NTC * NBC * (KPAD - NRELC)) {
        int row = i / (KPAD - NRELC), c = NRELC + i % (KPAD - NRELC);
        g_attnb[(size_t)row * KPAD + c] = __float2bfloat16(0.f);
    }
}

// merged: degree count + ent bf16 conversion (one graph node)
__global__ void k_count_entcvt(const int* __restrict__ dst, int* deg,
                               const float* __restrict__ ent) {
    int i = blockIdx.x * blockDim.x + threadIdx.x;  // grid covers N_ENTC*HC
    if (i < NEC) atomicAdd(&deg[dst[i]], 1);
    if (i < N_ENTC * HC) g_entb[i] = __float2bfloat16(ent[i]);
}

__global__ void k_scanA(const int* __restrict__ deg, int* rowptr, int* bsums) {
    __shared__ int wsum[32];
    int tid = threadIdx.x, lane = tid & 31, wid = tid >> 5;
    int i = blockIdx.x * 1024 + tid;
    int v = (i < N_ENTC) ? deg[i] : 0;
    int x = v;
    #pragma unroll
    for (int o = 1; o < 32; o <<= 1) {
        int t = __shfl_up_sync(0xffffffffu, x, o);
        if (lane >= o) x += t;
    }
    if (lane == 31) wsum[wid] = x;
    __syncthreads();
    if (wid == 0) {
        int s = wsum[lane];
        #pragma unroll
        for (int o = 1; o < 32; o <<= 1) {
            int t = __shfl_up_sync(0xffffffffu, s, o);
            if (lane >= o) s += t;
        }
        wsum[lane] = s;
    }
    __syncthreads();
    int woff = (wid > 0) ? wsum[wid - 1] : 0;
    int incl = x + woff;
    if (i < N_ENTC) rowptr[i] = incl - v;
    if (tid == 1023) bsums[blockIdx.x] = incl;
}

__global__ void k_scanB(int* rowptr, const int* __restrict__ bsums, int nblk) {
    __shared__ int offs[32];
    __shared__ int total_s;
    int tid = threadIdx.x;
    if (tid < 32) {
        int v = (tid < nblk) ? bsums[tid] : 0;
        int x = v;
        #pragma unroll
        for (int o = 1; o < 32; o <<= 1) {
            int t = __shfl_up_sync(0xffffffffu, x, o);
            if (tid >= o) x += t;
        }
        offs[tid] = x - v;
        if (tid == 31) total_s = x;
    }
    __syncthreads();
    for (int i = tid; i < N_ENTC; i += blockDim.x)
        rowptr[i] += offs[i >> 10];
    if (tid == 0) rowptr[N_ENTC] = total_s;
}

__global__ void k_fill(const int* __restrict__ dst, const int* __restrict__ src,
                       const int* __restrict__ typ, const int* __restrict__ rowptr,
                       int* cursor, int* csr) {
    int e = blockIdx.x * blockDim.x + threadIdx.x;
    if (e < NEC) {
        int d = dst[e];
        int p = atomicAdd(&cursor[d], 1);
        csr[rowptr[d] + p] = src[e] | (typ[e] << 16);
    }
}

__global__ void k_aggregate(const int* __restrict__ rowptr, const int* __restrict__ csr) {
    int node = blockIdx.x;
    int c = threadIdx.x;  // 64
    __shared__ int s_src[256];
    __shared__ int s_typ[256];
    const __nv_bfloat162* entb = (const __nv_bfloat162*)g_entb;
    const __nv_bfloat162* relb = (const __nv_bfloat162*)g_relb;
    int beg = rowptr[node], end = rowptr[node + 1];
    int deg = end - beg;
    float ax = 0.f, ay = 0.f;
    for (int base = beg; base < end; base += 256) {
        int cnt = min(256, end - base);
        for (int i = c; i < cnt; i += 64) {
            int p = csr[base + i];
            s_src[i] = (p & 0xFFFF) << 6;
            s_typ[i] = ((unsigned)p >> 16) << 6;
        }
        __syncthreads();
        #pragma unroll 4
        for (int i = 0; i < cnt; i++) {
            __nv_bfloat162 ev = entb[s_src[i] + c];
            __nv_bfloat162 rv = relb[s_typ[i] + c];
            ax += __bfloat162float(ev.x) + __bfloat162float(rv.x);
            ay += __bfloat162float(ev.y) + __bfloat162float(rv.y);
        }
        __syncthreads();
    }
    float inv = (deg > 0) ? 1.f / (float)deg : 0.f;
    __nv_bfloat162 o;
    o.x = __float2bfloat16(ax * inv);
    o.y = __float2bfloat16(ay * inv);
    *(__nv_bfloat162*)(g_aggb + (size_t)node * HC + 2 * c) = o;
}

// ---------------- GEMM fragment helpers ----------------
#define BGM 128
#define BGN 128
#define BGK 32
#define SSTR 40
#define XSTR 136

#define MMA_STEP(As_, Bs_, STRA, kbaseA, kk, cacc)                                   \
    {                                                                                 \
        uint32_t a[2][4], b[8][2];                                                    \
        _Pragma("unroll")                                                             \
        for (int mt = 0; mt < 2; mt++) {                                              \
            int row = wm * 32 + mt * 16 + (lane & 15);                                \
            int col = (kbaseA) + (kk) + ((lane >> 4) << 3);                           \
            uint32_t addr = (uint32_t)__cvta_generic_to_shared((As_) + row * (STRA) + col); \
            asm volatile("ldmatrix.sync.aligned.m8n8.x4.shared.b16 {%0,%1,%2,%3},[%4];" \
                         : "=r"(a[mt][0]), "=r"(a[mt][1]), "=r"(a[mt][2]), "=r"(a[mt][3]) \
                         : "r"(addr));                                                \
        }                                                                             \
        _Pragma("unroll")                                                             \
        for (int np = 0; np < 4; np++) {                                              \
            int nrow = wn * 64 + np * 16 + ((lane >> 4) << 3) + (lane & 7);           \
            int ncol = (kk) + (((lane >> 3) & 1) << 3);                               \
            uint32_t addr = (uint32_t)__cvta_generic_to_shared((Bs_) + nrow * SSTR + ncol); \
            asm volatile("ldmatrix.sync.aligned.m8n8.x4.shared.b16 {%0,%1,%2,%3},[%4];" \
                         : "=r"(b[2 * np][0]), "=r"(b[2 * np][1]),                    \
                           "=r"(b[2 * np + 1][0]), "=r"(b[2 * np + 1][1])             \
                         : "r"(addr));                                                \
        }                                                                             \
        _Pragma("unroll")                                                             \
        for (int mt = 0; mt < 2; mt++)                                                \
            _Pragma("unroll")                                                         \
            for (int nt = 0; nt < 8; nt++)                                            \
                asm volatile(                                                         \
                    "mma.sync.aligned.m16n8k16.row.col.f32.bf16.bf16.f32 "            \
                    "{%0,%1,%2,%3},{%4,%5,%6,%7},{%8,%9},{%0,%1,%2,%3};"              \
                    : "+f"(cacc[mt][nt][0]), "+f"(cacc[mt][nt][1]),                   \
                      "+f"(cacc[mt][nt][2]), "+f"(cacc[mt][nt][3])                    \
                    : "r"(a[mt][0]), "r"(a[mt][1]), "r"(a[mt][2]), "r"(a[mt][3]),     \
                      "r"(b[nt][0]), "r"(b[nt][1]));                                  \
    }

// ---------------- score GEMM ----------------
__global__ __launch_bounds__(256)
void k_score(const __nv_bfloat16* __restrict__ A, const __nv_bfloat16* __restrict__ B,
             float* __restrict__ Cf, const int* __restrict__ trip, double* acc,
             int M, int N) {
    __shared__ __nv_bfloat16 As[BGM * SSTR];
    __shared__ __nv_bfloat16 Bs[BGN * SSTR];
    int tid = threadIdx.x;
    int lane = tid & 31, wid = tid >> 5;
    int wm = wid & 3, wn = wid >> 2;
    int rowBase = blockIdx.y * BGM;
    int colBase = blockIdx.x * BGN;
    float c[2][8][4];
    #pragma unroll
    for (int i = 0; i < 2; i++)
        #pragma unroll
        for (int j = 0; j < 8; j++)
            #pragma unroll
            for (int q = 0; q < 4; q++) c[i][j][q] = 0.f;
    for (int k0 = 0; k0 < HC; k0 += BGK) {
        #pragma unroll
        for (int i = 0; i < 2; i++) {
            int idx = tid + i * 256;
            int r = idx >> 2, seg = idx & 3;
            *(uint4*)(As + r * SSTR + seg * 8) =
                *(const uint4*)(A + (size_t)(rowBase + r) * HC + k0 + seg * 8);
            uint4 vb = make_uint4(0, 0, 0, 0);
            int gn = colBase + r;
            if (gn < N) vb = *(const uint4*)(B + (size_t)gn * HC + k0 + seg * 8);
            *(uint4*)(Bs + r * SSTR + seg * 8) = vb;
        }
        __syncthreads();
        MMA_STEP(As, Bs, SSTR, 0, 0, c)
        MMA_STEP(As, Bs, SSTR, 0, 16, c)
        __syncthreads();
    }
    float lsp = 0.f, lxo = 0.f;
    #pragma unroll
    for (int mt = 0; mt < 2; mt++) {
        int r0 = rowBase + wm * 32 + mt * 16 + (lane >> 2);
        int ob0 = trip[r0 * 3 + 2];
        int ob1 = trip[(r0 + 8) * 3 + 2];
        #pragma unroll
        for (int nt = 0; nt < 8; nt++) {
            int col = colBase + wn * 64 + nt * 8 + ((lane & 3) << 1);
            if (col < N) {
                #pragma unroll
                for (int half = 0; half < 2; half++) {
                    int row = r0 + half * 8;
                    int ob = half ? ob1 : ob0;
                    float x0 = c[mt][nt][half * 2 + 0];
                    float x1 = c[mt][nt][half * 2 + 1];
                    float s0, p0, s1, p1;
                    sig_sp(x0, s0, p0);
                    sig_sp(x1, s1, p1);
                    *(float2*)(Cf + (size_t)row * N + col) = make_float2(s0, s1);
                    lsp += p0 + p1;
                    if (col == ob) lxo += x0;
                    if (col + 1 == ob) lxo += x1;
                }
            }
        }
    }
    float bs = blockReduceSum(lsp);
    float bx = blockReduceSum(lxo);
    if (tid == 0) {
        atomicAdd(&acc[0], (double)bs);
        atomicAdd(&acc[1], (double)bx);
    }
}

// ---------------- fused pre+aln ----------------
__global__ __launch_bounds__(256)
void k_prealn(const float* __restrict__ bal, const int* __restrict__ deg, int M) {
    extern __shared__ __nv_bfloat16 sm[];
    __nv_bfloat16* As = sm;
    __nv_bfloat16* Bs = sm + BGM * SSTR;
    __nv_bfloat16* Xs = sm + 2 * BGM * SSTR;
    int tid = threadIdx.x, lane = tid & 31, wid = tid >> 5;
    int wm = wid & 3, wn = wid >> 2;
    int rowBase = blockIdx.x * BGM;
    int lr[2]; bool lv[2], lm[2];
    #pragma unroll
    for (int i = 0; i < 2; i++) {
        int idx = tid + i * 256;
        lr[i] = idx >> 2;
        int gr = rowBase + lr[i];
        lv[i] = gr < M;
        lm[i] = lv[i] && (deg[lv[i] ? gr : 0] > 0);
    }
    float c[2][8][4];
    #pragma unroll
    for (int i = 0; i < 2; i++)
        #pragma unroll
        for (int j = 0; j < 8; j++)
            #pragma unroll
            for (int q = 0; q < 4; q++) c[i][j][q] = 0.f;
    for (int k0 = 0; k0 < KPRE; k0 += BGK) {
        #pragma unroll
        for (int i = 0; i < 2; i++) {
            int idx = tid + i * 256;
            int r = lr[i], seg = idx & 3;
            int gr = rowBase + r;
            int kc = k0 + seg * 8;
            uint4 va = make_uint4(0, 0, 0, 0);
            if (lv[i]) {
                if (k0 < 128) {
                    va = *(const uint4*)(g_aggb + (size_t)gr * HC + kc);
                } else if (k0 < 256) {
                    if (lm[i]) va = *(const uint4*)(g_entb + (size_t)gr * HC + kc - 128);
                } else {
                    if (!lm[i]) va = *(const uint4*)(g_entb + (size_t)gr * HC + kc - 256);
                }
            }
            *(uint4*)(As + r * SSTR + seg * 8) = va;
            *(uint4*)(Bs + r * SSTR + seg * 8) =
                *(const uint4*)(g_B3 + (size_t)r * KPRE + k0 + seg * 8);
        }
        __syncthreads();
        MMA_STEP(As, Bs, SSTR, 0, 0, c)
        MMA_STEP(As, Bs, SSTR, 0, 16, c)
        __syncthreads();
    }
    #pragma unroll
    for (int mt = 0; mt < 2; mt++) {
        #pragma unroll
        for (int nt = 0; nt < 8; nt++) {
            int colL = wn * 64 + nt * 8 + ((lane & 3) << 1);
            #pragma unroll
            for (int half = 0; half < 2; half++) {
                int rowL = wm * 32 + mt * 16 + (lane >> 2) + half * 8;
                float v0 = c[mt][nt][half * 2 + 0];
                float v1 = c[mt][nt][half * 2 + 1];
                v0 = (v0 >= 0.f) ? v0 : v0 * SLOPE;
                v1 = (v1 >= 0.f) ? v1 : v1 * SLOPE;
                __nv_bfloat162 bv(__float2bfloat16(v0), __float2bfloat16(v1));
                *(__nv_bfloat162*)(Xs + rowL * XSTR + colL) = bv;
                int grow = rowBase + rowL;
                if (grow < M)
                    *(__nv_bfloat162*)(g_prebf + (size_t)grow * HC + colL) = bv;
            }
        }
    }
    __syncthreads();
    float c2[2][8][4];
    #pragma unroll
    for (int i = 0; i < 2; i++)
        #pragma unroll
        for (int j = 0; j < 8; j++)
            #pragma unroll
            for (int q = 0; q < 4; q++) c2[i][j][q] = 0.f;
    for (int k0 = 0; k0 < HC; k0 += BGK) {
        #pragma unroll
        for (int i = 0; i < 2; i++) {
            int idx = tid + i * 256;
            int r = idx >> 2, seg = idx & 3;
            *(uint4*)(Bs + r * SSTR + seg * 8) =
                *(const uint4*)(g_walb + (size_t)r * HC + k0 + seg * 8);
        }
        __syncthreads();
        MMA_STEP(Xs, Bs, XSTR, k0, 0, c2)
        MMA_STEP(Xs, Bs, XSTR, k0, 16, c2)
        __syncthreads();
    }
    #pragma unroll
    for (int mt = 0; mt < 2; mt++) {
        #pragma unroll
        for (int nt = 0; nt < 8; nt++) {
            int colL = wn * 64 + nt * 8 + ((lane & 3) << 1);
            float b0 = bal[colL], b1 = bal[colL + 1];
            #pragma unroll
            for (int half = 0; half < 2; half++) {
                int grow = rowBase + wm * 32 + mt * 16 + (lane >> 2) + half * 8;
                if (grow < M) {
                    __nv_bfloat162 bv(__float2bfloat16(c2[mt][nt][half * 2 + 0] + b0),
                                      __float2bfloat16(c2[mt][nt][half * 2 + 1] + b1));
                    *(__nv_bfloat162*)(g_alnbf + (size_t)grow * HC + colL) = bv;
                }
            }
        }
    }
}

// ---------------- fused rpath+giall ----------------
__global__ __launch_bounds__(256)
void k_rpgi(const float* __restrict__ bih, float* __restrict__ giall) {
    extern __shared__ __nv_bfloat16 sm[];
    __nv_bfloat16* As = sm;
    __nv_bfloat16* Bs = sm + BGM * SSTR;
    __nv_bfloat16* Xs = sm + 2 * BGM * SSTR;
    int tid = threadIdx.x, lane = tid & 31, wid = tid >> 5;
    int wm = wid & 3, wn = wid >> 2;
    int rowBase = blockIdx.x * BGM;
    if (blockIdx.x < 64) {
        float c[2][8][4];
        #pragma unroll
        for (int i = 0; i < 2; i++)
            #pragma unroll
            for (int j = 0; j < 8; j++)
                #pragma unroll
                for (int q = 0; q < 4; q++) c[i][j][q] = 0.f;
        for (int k0 = 0; k0 < KPAD; k0 += BGK) {
            #pragma unroll
            for (int i = 0; i < 2; i++) {
                int idx = tid + i * 256;
                int r = idx >> 2, seg = idx & 3;
                *(uint4*)(As + r * SSTR + seg * 8) =
                    *(const uint4*)(g_attnb + (size_t)(rowBase + r) * KPAD + k0 + seg * 8);
                *(uint4*)(Bs + r * SSTR + seg * 8) =
                    *(const uint4*)(g_mrelTb + (size_t)r * KPAD + k0 + seg * 8);
            }
            __syncthreads();
            MMA_STEP(As, Bs, SSTR, 0, 0, c)
            MMA_STEP(As, Bs, SSTR, 0, 16, c)
            __syncthreads();
        }
        #pragma unroll
        for (int mt = 0; mt < 2; mt++)
            #pragma unroll
            for (int nt = 0; nt < 8; nt++) {
                int colL = wn * 64 + nt * 8 + ((lane & 3) << 1);
                #pragma unroll
                for (int half = 0; half < 2; half++) {
                    int rowL = wm * 32 + mt * 16 + (lane >> 2) + half * 8;
                    __nv_bfloat162 bv(__float2bfloat16(c[mt][nt][half * 2 + 0]),
                                      __float2bfloat16(c[mt][nt][half * 2 + 1]));
                    *(__nv_bfloat162*)(Xs + rowL * XSTR + colL) = bv;
                }
            }
    } else {
        for (int i = tid; i < BGM * (HC / 8); i += 256) {
            int r = i / (HC / 8), seg = i % (HC / 8);
            *(uint4*)(Xs + r * XSTR + seg * 8) =
                *(const uint4*)(g_Xb + (size_t)(rowBase + r) * HC + seg * 8);
        }
    }
    __syncthreads();
    for (int nb = 0; nb < 3; nb++) {
        float c2[2][8][4];
        #pragma unroll
        for (int i = 0; i < 2; i++)
            #pragma unroll
            for (int j = 0; j < 8; j++)
                #pragma unroll
                for (int q = 0; q < 4; q++) c2[i][j][q] = 0.f;
        for (int k0 = 0; k0 < HC; k0 += BGK) {
            #pragma unroll
            for (int i = 0; i < 2; i++) {
                int idx = tid + i * 256;
                int r = idx >> 2, seg = idx & 3;
                *(uint4*)(Bs + r * SSTR + seg * 8) =
                    *(const uint4*)(g_wihb + (size_t)(nb * 128 + r) * HC + k0 + seg * 8);
            }
            __syncthreads();
            MMA_STEP(Xs, Bs, XSTR, k0, 0, c2)
            MMA_STEP(Xs, Bs, XSTR, k0, 16, c2)
            __syncthreads();
        }
        #pragma unroll
        for (int mt = 0; mt < 2; mt++)
            #pragma unroll
            for (int nt = 0; nt < 8; nt++) {
                int colL = wn * 64 + nt * 8 + ((lane & 3) << 1);
                int col = nb * 128 + colL;
                float b0 = bih[col], b1 = bih[col + 1];
                #pragma unroll
                for (int half = 0; half < 2; half++) {
                    int row = rowBase + wm * 32 + mt * 16 + (lane >> 2) + half * 8;
                    *(float2*)(giall + (size_t)row * H3C + col) =
                        make_float2(c2[mt][nt][half * 2 + 0] + b0,
                                    c2[mt][nt][half * 2 + 1] + b1);
                }
            }
    }
}

// ---------------- fused mapped_rel ----------------
__global__ __launch_bounds__(256)
void k_mrel(const float* __restrict__ rel, const float* __restrict__ Wm1T,
            const float* __restrict__ Wm2T, const float* __restrict__ bm1,
            const float* __restrict__ bm2, float* __restrict__ mrel,
            float* __restrict__ mrelT) {
    __shared__ float rels[10][128];
    __shared__ float p1s[10][256];
    int tid = threadIdx.x;
    int r0 = blockIdx.x * 10;
    for (int i = tid; i < 10 * 128; i += 256)
        rels[i >> 7][i & 127] = rel[(r0 + (i >> 7)) * 128 + (i & 127)];
    __syncthreads();
    {
        int j2 = tid;
        float a[10];
        #pragma unroll
        for (int r = 0; r < 10; r++) a[r] = 0.f;
        for (int k = 0; k < 128; k++) {
            float w = Wm1T[k * 256 + j2];
            #pragma unroll
            for (int r = 0; r < 10; r++) a[r] = fmaf(rels[r][k], w, a[r]);
        }
        float b = bm1[j2];
        #pragma unroll
        for (int r = 0; r < 10; r++) p1s[r][j2] = a[r] + b;
    }
    __syncthreads();
    {
        int j = tid & 127, half = tid >> 7;
        float a[5];
        #pragma unroll
        for (int r = 0; r < 5; r++) a[r] = 0.f;
        for (int k = 0; k < 256; k++) {
            float w = Wm2T[k * 128 + j];
            #pragma unroll
            for (int r = 0; r < 5; r++) a[r] = fmaf(p1s[half * 5 + r][k], w, a[r]);
        }
        float b = bm2[j];
        #pragma unroll
        for (int r = 0; r < 5; r++) {
            int row = r0 + half * 5 + r;
            float v = a[r] + b;
            mrel[row * 128 + j] = v;
            mrelT[j * MT_STR + row] = v;
            g_mrelTb[j * KPAD + row] = __float2bfloat16(v);
        }
    }
}

__global__ __launch_bounds__(128)
void k_qa_amat(const float* __restrict__ mrel, const int* __restrict__ trip,
               const float* __restrict__ WatT, const float* __restrict__ bat,
               const float* __restrict__ mrelT, float* __restrict__ qrel,
               float* __restrict__ Amat) {
    __shared__ float q[4][128];
    __shared__ float qa[4][128];
    int j = threadIdx.x;
    int r0 = blockIdx.x * 4;
    #pragma unroll
    for (int r = 0; r < 4; r++) {
        float v = mrel[(size_t)trip[(r0 + r) * 3 + 1] * HC + j];
        q[r][j] = v;
        qrel[(r0 + r) * 128 + j] = v;
        g_Xb[(size_t)(NTC * NBC + r0 + r) * HC + j] = __float2bfloat16(v);
    }
    __syncthreads();
    {
        float a[4] = {0.f, 0.f, 0.f, 0.f};
        for (int k = 0; k < 128; k++) {
            float w = WatT[k * 128 + j];
            #pragma unroll
            for (int r = 0; r < 4; r++) a[r] = fmaf(q[r][k], w, a[r]);
        }
        float b = bat[j];
        #pragma unroll
        for (int r = 0; r < 4; r++) qa[r][j] = a[r] + b;
    }
    __syncthreads();
    #pragma unroll
    for (int r = 0; r < 4; r++) {
        float a[4] = {0.f, 0.f, 0.f, 0.f};
        for (int k = 0; k < 128; k++) {
            float qv = qa[r][k];
            #pragma unroll
            for (int t = 0; t < 4; t++)
                a[t] = fmaf(qv, mrelT[k * MT_STR + j + t * 128], a[t]);
        }
        #pragma unroll
        for (int t = 0; t < 4; t++) {
            int n = j + t * 128;
            if (n < NRELC) Amat[(size_t)(r0 + r) * NRELC + n] = a[t];
        }
    }
}

// warp-per-row masked softmax (no smem, shuffle-only)
__global__ __launch_bounds__(256)
void k_attn(const float* __restrict__ part, const float* __restrict__ Amat) {
    int warp = (blockIdx.x * 256 + threadIdx.x) >> 5;  // 8192 warps
    int lane = threadIdx.x & 31;
    int t = warp >> 10, b = warp & 1023;
    const float* prow = part + (size_t)b * (NTC * NRELC) + t * NRELC;
    const float* arow = Amat + (size_t)b * NRELC;
    float xv[15];
    float m = -3.402823e38f;
    #pragma unroll
    for (int i = 0; i < 15; i++) {
        int c = lane + i * 32;
        float x = -3.402823e38f;
        if (c < NRELC) {
            float val = prow[c] * arow[c];
            x = (val == 0.f) ? -1e9f : val;
        }
        xv[i] = x;
        m = fmaxf(m, x);
    }
    #pragma unroll
    for (int o = 16; o > 0; o >>= 1) m = fmaxf(m, __shfl_xor_sync(0xffffffffu, m, o));
    float s = 0.f;
    float ev[15];
    #pragma unroll
    for (int i = 0; i < 15; i++) {
        int c = lane + i * 32;
        float e = (c < NRELC) ? __expf(xv[i] - m) : 0.f;
        ev[i] = e;
        s += e;
    }
    #pragma unroll
    for (int o = 16; o > 0; o >>= 1) s += __shfl_xor_sync(0xffffffffu, s, o);
    float inv = 1.f / s;
    __nv_bfloat16* orow = g_attnb + (size_t)warp * KPAD;
    #pragma unroll
    for (int i = 0; i < 15; i++) {
        int c = lane + i * 32;
        if (c < NRELC) orow[c] = __float2bfloat16(ev[i] * inv);
    }
}

// ---------------- mega GRU kernel (whhT cached in dynamic smem) ----------------
__global__ __launch_bounds__(384)
void k_gru_all(const float* __restrict__ giall, const float* __restrict__ whhT,
               const float* __restrict__ bhh, const float* __restrict__ qrel,
               const float* __restrict__ Wh1T, const float* __restrict__ Wh2T,
               const float* __restrict__ bh1, const float* __restrict__ bh2,
               const int* __restrict__ trip, const float* __restrict__ WalT,
               const float* __restrict__ bal, double* acc) {
    extern __shared__ float swhh[];          // 128*384 fp32 = 192KB
    __shared__ float hs[8][128];
    __shared__ float asg[8][384];
    __shared__ float qs[8][128];
    __shared__ float ps[8][128];
    int tid = threadIdx.x;
    int j = tid & 127;
    int g = tid >> 7;
    int r0 = blockIdx.x * 8;

    for (int i = tid; i < HC * H3C; i += 384) swhh[i] = whhT[i];
    for (int i = tid; i < 8 * 128; i += 384) hs[i >> 7][i & 127] = 0.f;
    __syncthreads();

    for (int t = 0; t < NTC; t++) {
        {
            float a[8];
            #pragma unroll
            for (int r = 0; r < 8; r++) a[r] = 0.f;
            for (int k = 0; k < 128; k++) {
                float w = swhh[k * H3C + tid];
                #pragma unroll
                for (int r = 0; r < 8; r++) a[r] = fmaf(hs[r][k], w, a[r]);
            }
            #pragma unroll
            for (int r = 0; r < 8; r++) asg[r][tid] = a[r];
        }
        __syncthreads();
        if (tid < 128) {
            float br = bhh[j], bz = bhh[128 + j], bn = bhh[256 + j];
            const float* gi = giall + (size_t)t * NBC * H3C;
            #pragma unroll
            for (int r = 0; r < 8; r++) {
                size_t gx = (size_t)(r0 + r) * H3C;
                float rr = sigm(gi[gx + j] + asg[r][j] + br);
                float zz = sigm(gi[gx + 128 + j] + asg[r][128 + j] + bz);
                float nn = tanhf(gi[gx + 256 + j] + rr * (asg[r][256 + j] + bn));
                hs[r][j] = (1.f - zz) * nn + zz * hs[r][j];
            }
        }
        __syncthreads();
    }

    for (int i = tid; i < 8 * 128; i += 384)
        qs[i >> 7][i & 127] = qrel[(r0 + (i >> 7)) * 128 + (i & 127)];
    __syncthreads();

    for (int r = g; r < 8; r += 3) {
        float a = 0.f;
        for (int k = 0; k < 128; k++) a = fmaf(qs[r][k], Wh1T[k * 128 + j], a);
        ps[r][j] = a + bh1[j];
    }
    __syncthreads();
    float predv[3];
    int nmine = 0;
    for (int r = g; r < 8; r += 3) {
        float a = 0.f;
        for (int k = 0; k < 128; k++) a = fmaf(ps[r][k], Wh2T[k * 128 + j], a);
        predv[nmine++] = 0.1f * (a + bh2[j]) + qs[r][j];
    }
    __syncthreads();
    {
        int m = 0;
        for (int r = g; r < 8; r += 3) ps[r][j] = predv[m++];
    }
    __syncthreads();
    {
        float msum = 0.f;
        for (int r = g; r < 8; r += 3) {
            float d = ps[r][j] - hs[r][j];
            msum += d * d;
        }
        float bsum = blockReduceSum(msum);
        if (tid == 0) atomicAdd(&acc[2], (double)bsum);
    }
    __syncthreads();
    {
        float a[8];
        #pragma unroll
        for (int r = 0; r < 8; r++) a[r] = 0.f;
        for (int k = 0; k < 128; k++) {
            float w = swhh[k * H3C + tid];
            #pragma unroll
            for (int r = 0; r < 8; r++) a[r] = fmaf(ps[r][k], w, a[r]);
        }
        #pragma unroll
        for (int r = 0; r < 8; r++) asg[r][tid] = a[r];
    }
    __syncthreads();
    if (tid < 128) {
        float br = bhh[j], bz = bhh[128 + j], bn = bhh[256 + j];
        const float* gi = giall + (size_t)NTC * NBC * H3C;
        #pragma unroll
        for (int r = 0; r < 8; r++) {
            size_t gx = (size_t)(r0 + r) * H3C;
            float rr = sigm(gi[gx + j] + asg[r][j] + br);
            float zz = sigm(gi[gx + 128 + j] + asg[r][128 + j] + bz);
            float nn = tanhf(gi[gx + 256 + j] + rr * (asg[r][256 + j] + bn));
            hs[r][j] = (1.f - zz) * nn + zz * ps[r][j];
        }
    }
    __syncthreads();
    for (int i = tid; i < 8 * 128; i += 384) {
        int r = i >> 7, c = i & 127;
        int row = trip[(r0 + r) * 3 + 0];
        qs[r][c] = __bfloat162float(g_prebf[(size_t)row * HC + c]);
    }
    __syncthreads();
    for (int r = g; r < 8; r += 3) {
        float a = 0.f;
        for (int k = 0; k < 128; k++) a = fmaf(qs[r][k], WalT[k * 128 + j], a);
        float v = (a + bal[j]) * hs[r][j];
        g_svecb[(r0 + r) * 128 + j] = __float2bfloat16(v);
    }
}

__global__ void k_final(const double* __restrict__ acc, float* __restrict__ out) {
    if (threadIdx.x == 0) {
        out[(size_t)NBC * N_ENTC]     = (float)(acc[2] / (double)(NBC * HC));
        out[(size_t)NBC * N_ENTC + 1] = (float)((acc[0] - acc[1]) /
                                                ((double)NBC * (double)N_ENTC));
    }
}

// ---------------- host ----------------
extern "C" void kernel_launch(void* const* d_in, const int* in_sizes, int n_in,
                              void* d_out, int out_size) {
    const float* ent  = (const float*)d_in[0];
    const float* rel  = (const float*)d_in[1];
    const float* Wn   = (const float*)d_in[2];
    const float* Wl   = (const float*)d_in[3];
    const float* Wev  = (const float*)d_in[4];
    const float* wih  = (const float*)d_in[5];
    const float* whh  = (const float*)d_in[6];
    const float* bih  = (const float*)d_in[7];
    const float* bhh  = (const float*)d_in[8];
    const float* Wm1  = (const float*)d_in[9];
    const float* bm1  = (const float*)d_in[10];
    const float* Wm2  = (const float*)d_in[11];
    const float* bm2  = (const float*)d_in[12];
    const float* Wh1  = (const float*)d_in[13];
    const float* bh1  = (const float*)d_in[14];
    const float* Wh2  = (const float*)d_in[15];
    const float* bh2  = (const float*)d_in[16];
    const float* Wal  = (const float*)d_in[17];
    const float* bal  = (const float*)d_in[18];
    const float* Wat  = (const float*)d_in[19];
    const float* bat  = (const float*)d_in[20];
    const float* part = (const float*)d_in[21];
    const int* esrc = (const int*)d_in[22];
    const int* edst = (const int*)d_in[23];
    const int* etyp = (const int*)d_in[24];
    const int* trip = (const int*)d_in[25];
    float* out = (float*)d_out;

    void* basep = nullptr;
    cudaGetSymbolAddress(&basep, d_buf);
    float* F = (float*)basep;
    __nv_bfloat16 *pSvecb, *pAlnb;
    { void* p; cudaGetSymbolAddress(&p, g_svecb); pSvecb = (__nv_bfloat16*)p; }
    { void* p; cudaGetSymbolAddress(&p, g_alnbf); pAlnb  = (__nv_bfloat16*)p; }

    float* mrel   = F + O_MREL;
    float* mrelT  = F + O_MRELT;
    float* qrel   = F + O_QREL;
    float* Amat   = F + O_AMAT;
    float* giall  = F + O_GIALL;
    float* whhT   = F + O_WHHT;
    float* Wh1T   = F + O_WH1T;
    float* Wh2T   = F + O_WH2T;
    float* WatT   = F + O_WATT;
    float* WalT   = F + O_WALT;
    float* Wm1T   = F + O_WM1T;
    float* Wm2T   = F + O_WM2T;
    double* acc   = (double*)(F + O_ACC);
    int* deg      = (int*)(F + O_INT);
    int* rowptr   = deg + N_ENTC;
    int* cursor   = rowptr + N_ENTC + 1;
    int* csr      = cursor + N_ENTC;
    int* bsums    = csr + NEC;

    const int FUSED_SMEM = (2 * BGM * SSTR + BGM * XSTR) * 2;  // 55296 B
    const int GRU_SMEM = HC * H3C * 4;                          // 196608 B
    static bool s_init = false;
    static cudaStream_t sB = 0;
    static cudaEvent_t evF = 0, evB = 0;
    if (!s_init) {
        cudaFuncSetAttribute(k_prealn, cudaFuncAttributeMaxDynamicSharedMemorySize, FUSED_SMEM);
        cudaFuncSetAttribute(k_rpgi,   cudaFuncAttributeMaxDynamicSharedMemorySize, FUSED_SMEM);
        cudaFuncSetAttribute(k_gru_all, cudaFuncAttributeMaxDynamicSharedMemorySize, GRU_SMEM);
        cudaStreamCreateWithFlags(&sB, cudaStreamNonBlocking);
        cudaEventCreateWithFlags(&evF, cudaEventDisableTiming);
        cudaEventCreateWithFlags(&evB, cudaEventDisableTiming);
        s_init = true;
    }

    k_init<<<640, 256>>>(Wn, Wl, Wev, wih, whh, Wal, Wh1, Wh2, Wat, Wm1, Wm2, rel,
                         deg, cursor, acc, F);
    cudaEventRecord(evF, 0);
    cudaStreamWaitEvent(sB, evF, 0);

    // ---- chain B (relation path) on sB ----
    k_mrel<<<46, 256, 0, sB>>>(rel, Wm1T, Wm2T, bm1, bm2, mrel, mrelT);
    k_qa_amat<<<256, 128, 0, sB>>>(mrel, trip, WatT, bat, mrelT, qrel, Amat);
    k_attn<<<NTC * NBC / 8, 256, 0, sB>>>(part, Amat);
    k_rpgi<<<(NTC + 1) * NBC / BGM, 256, FUSED_SMEM, sB>>>(bih, giall);
    cudaEventRecord(evB, sB);

    // ---- chain A (entity path) on default stream ----
    k_count_entcvt<<<(N_ENTC * HC + 255) / 256, 256>>>(edst, deg, ent);
    k_scanA<<<(N_ENTC + 1023) / 1024, 1024>>>(deg, rowptr, bsums);
    k_scanB<<<1, 1024>>>(rowptr, bsums, (N_ENTC + 1023) / 1024);
    k_fill<<<(NEC + 255) / 256, 256>>>(edst, esrc, etyp, rowptr, cursor, csr);
    k_aggregate<<<N_ENTC, 64>>>(rowptr, csr);
    k_prealn<<<(N_ENTC + BGM - 1) / BGM, 256, FUSED_SMEM>>>(bal, deg, N_ENTC);

    // ---- join ----
    cudaStreamWaitEvent(0, evB, 0);
    k_gru_all<<<128, 384, GRU_SMEM>>>(giall, whhT, bhh, qrel, Wh1T, Wh2T, bh1, bh2,
                                      trip, WalT, bal, acc);
    {
        dim3 g((N_ENTC + BGN - 1) / BGN, NBC / BGM);
        k_score<<<g, 256>>>(pSvecb, pAlnb, out, trip, acc, NBC, N_ENTC);
    }
    if (out_size >= NBC * N_ENTC + 2) k_final<<<1, 32>>>(acc, out);
}

// round 12
// speedup vs baseline: 2.9863x; 1.0409x over previous
#include <cuda_runtime.h>
#include <cuda_bf16.h>
#include <stdint.h>
#include <math.h>

#define N_ENTC 20000
#define NRELC  460
#define HC     128
#define NEC    400000
#define NBC    1024
#define NTC    8
#define H3C    384
#define SLOPE  0.22916666666666666f
#define KPRE   384
#define KPAD   480
#define MT_STR 512

// ---------------- fp32 scratch ----------------
constexpr size_t O_MREL  = 0;
constexpr size_t O_MRELT = O_MREL + (size_t)NRELC * HC;
constexpr size_t O_QREL  = O_MRELT + (size_t)HC * MT_STR;
constexpr size_t O_AMAT  = O_QREL + (size_t)NBC * HC;
constexpr size_t O_GIALL = O_AMAT + (size_t)NBC * NRELC;
constexpr size_t O_WHHT  = O_GIALL + (size_t)(NTC + 1) * NBC * H3C;
constexpr size_t O_WH1T  = O_WHHT + 49152;
constexpr size_t O_WH2T  = O_WH1T + 16384;
constexpr size_t O_WATT  = O_WH2T + 16384;
constexpr size_t O_WALT  = O_WATT + 16384;
constexpr size_t O_WM1T  = O_WALT + 16384;
constexpr size_t O_WM2T  = O_WM1T + 32768;
constexpr size_t O_ACC_  = O_WM2T + 32768;
constexpr size_t O_ACC   = (O_ACC_ + 1) & ~(size_t)1;
constexpr size_t O_INT   = O_ACC + 8;
constexpr size_t N_INTS  = (size_t)N_ENTC + (N_ENTC + 1) + N_ENTC + NEC + 64;
constexpr size_t TOTALF  = O_INT + N_INTS;
__device__ __align__(16) float d_buf[TOTALF];

// ---------------- bf16 scratch ----------------
__device__ __align__(16) __nv_bfloat16 g_aggb[(size_t)N_ENTC * HC];
__device__ __align__(16) __nv_bfloat16 g_B3[HC * KPRE];
__device__ __align__(16) __nv_bfloat16 g_entb[(size_t)N_ENTC * HC];
__device__ __align__(16) __nv_bfloat16 g_relb[NRELC * HC];
__device__ __align__(16) __nv_bfloat16 g_prebf[(size_t)N_ENTC * HC];
__device__ __align__(16) __nv_bfloat16 g_alnbf[(size_t)N_ENTC * HC];
__device__ __align__(16) __nv_bfloat16 g_walb[HC * HC];
__device__ __align__(16) __nv_bfloat16 g_wihb[H3C * HC];
__device__ __align__(16) __nv_bfloat16 g_mrelTb[HC * KPAD];
__device__ __align__(16) __nv_bfloat16 g_Xb[(size_t)(NTC + 1) * NBC * HC];
__device__ __align__(16) __nv_bfloat16 g_attnb[(size_t)NTC * NBC * KPAD];
__device__ __align__(16) __nv_bfloat16 g_svecb[(size_t)NBC * HC];

// ---------------- reductions ----------------
__device__ __forceinline__ float blockReduceSum(float v) {
    __shared__ float sh[32];
    int tid = threadIdx.x;
    __syncthreads();
    #pragma unroll
    for (int o = 16; o > 0; o >>= 1) v += __shfl_xor_sync(0xffffffffu, v, o);
    if ((tid & 31) == 0) sh[tid >> 5] = v;
    __syncthreads();
    float r = 0.f;
    if (tid < 32) {
        int nw = (blockDim.x + 31) >> 5;
        r = (tid < nw) ? sh[tid] : 0.f;
        #pragma unroll
        for (int o = 16; o > 0; o >>= 1) r += __shfl_xor_sync(0xffffffffu, r, o);
    }
    return r;
}

__device__ __forceinline__ void sig_sp(float x, float& sig, float& sp) {
    float ax = fabsf(x);
    if (ax < 0.5f) {
        float x2 = x * x;
        sig = 0.5f + x * (0.25f + x2 * (-0.0208333333f + x2 * 0.0020833333f));
        sp  = 0.69314718f + 0.5f * x
            + x2 * (0.125f + x2 * (-0.0052083333f + x2 * 0.00034722222f));
    } else {
        float e = __expf(-ax);
        sig = (x >= 0.f) ? 1.f / (1.f + e) : e / (1.f + e);
        sp  = fmaxf(x, 0.f) + __logf(1.f + e);
    }
}
__device__ __forceinline__ float sigm(float x) { return 1.f / (1.f + __expf(-x)); }

// ---------------- init ----------------
__global__ void k_init(const float* __restrict__ Wn, const float* __restrict__ Wl,
                       const float* __restrict__ Wev, const float* __restrict__ wih,
                       const float* __restrict__ whh, const float* __restrict__ Wal,
                       const float* __restrict__ Wh1, const float* __restrict__ Wh2,
                       const float* __restrict__ Wat, const float* __restrict__ Wm1,
                       const float* __restrict__ Wm2, const float* __restrict__ rel,
                       int* deg, int* cursor, double* acc, int* done, float* F) {
    int i = blockIdx.x * blockDim.x + threadIdx.x;  // grid 640*256
    if (i < N_ENTC) { deg[i] = 0; cursor[i] = 0; }
    if (i == 0) { acc[0] = 0.0; acc[1] = 0.0; acc[2] = 0.0; done[0] = 0; }
    if (i < HC * KPRE) {
        int n = i / KPRE, k = i % KPRE;
        float v = (k < 128) ? Wn[k * 128 + n]
                : (k < 256) ? Wl[(k - 128) * 128 + n]
                            : Wev[(k - 256) * 128 + n];
        g_B3[i] = __float2bfloat16(v);
    }
    if (i < H3C * HC) g_wihb[i] = __float2bfloat16(wih[i]);
    if (i < HC * HC)  g_walb[i] = __float2bfloat16(Wal[i]);
    if (i < NRELC * HC) g_relb[i] = __float2bfloat16(rel[i]);
    if (i < HC * H3C) {
        int k = i / H3C, j = i % H3C;
        F[O_WHHT + i] = whh[j * 128 + k];
    }
    if (i < HC * HC) {
        int k = i / HC, j = i % HC;
        F[O_WH1T + i] = Wh1[j * HC + k];
        F[O_WH2T + i] = Wh2[j * HC + k];
        F[O_WATT + i] = Wat[j * HC + k];
        F[O_WALT + i] = Wal[j * HC + k];
    }
    if (i < 128 * 256) {
        int k = i / 256, j2 = i % 256;
        F[O_WM1T + i] = Wm1[j2 * 128 + k];
    }
    if (i < 256 * 128) {
        int k2 = i / 128, j = i % 128;
        F[O_WM2T + i] = Wm2[j * 256 + k2];
    }
    if (i < HC * (KPAD - NRELC)) {
        int j = i / (KPAD - NRELC), c = NRELC + i % (KPAD - NRELC);
        g_mrelTb[j * KPAD + c] = __float2bfloat16(0.f);
    }
    if (i < HC * (MT_STR - NRELC)) {
        int j = i / (MT_STR - NRELC), c = NRELC + i % (MT_STR - NRELC);
        F[O_MRELT + j * MT_STR + c] = 0.f;
    }
    if (i < NTC * NBC * (KPAD - NRELC)) {
        int row = i / (KPAD - NRELC), c = NRELC + i % (KPAD - NRELC);
        g_attnb[(size_t)row * KPAD + c] = __float2bfloat16(0.f);
    }
}

__global__ void k_count_entcvt(const int* __restrict__ dst, int* deg,
                               const float* __restrict__ ent) {
    int i = blockIdx.x * blockDim.x + threadIdx.x;
    if (i < NEC) atomicAdd(&deg[dst[i]], 1);
    if (i < N_ENTC * HC) g_entb[i] = __float2bfloat16(ent[i]);
}

__global__ void k_scanA(const int* __restrict__ deg, int* rowptr, int* bsums) {
    __shared__ int wsum[32];
    int tid = threadIdx.x, lane = tid & 31, wid = tid >> 5;
    int i = blockIdx.x * 1024 + tid;
    int v = (i < N_ENTC) ? deg[i] : 0;
    int x = v;
    #pragma unroll
    for (int o = 1; o < 32; o <<= 1) {
        int t = __shfl_up_sync(0xffffffffu, x, o);
        if (lane >= o) x += t;
    }
    if (lane == 31) wsum[wid] = x;
    __syncthreads();
    if (wid == 0) {
        int s = wsum[lane];
        #pragma unroll
        for (int o = 1; o < 32; o <<= 1) {
            int t = __shfl_up_sync(0xffffffffu, s, o);
            if (lane >= o) s += t;
        }
        wsum[lane] = s;
    }
    __syncthreads();
    int woff = (wid > 0) ? wsum[wid - 1] : 0;
    int incl = x + woff;
    if (i < N_ENTC) rowptr[i] = incl - v;
    if (tid == 1023) bsums[blockIdx.x] = incl;
}

__global__ void k_scanB(int* rowptr, const int* __restrict__ bsums, int nblk) {
    __shared__ int offs[32];
    __shared__ int total_s;
    int tid = threadIdx.x;
    if (tid < 32) {
        int v = (tid < nblk) ? bsums[tid] : 0;
        int x = v;
        #pragma unroll
        for (int o = 1; o < 32; o <<= 1) {
            int t = __shfl_up_sync(0xffffffffu, x, o);
            if (tid >= o) x += t;
        }
        offs[tid] = x - v;
        if (tid == 31) total_s = x;
    }
    __syncthreads();
    for (int i = tid; i < N_ENTC; i += blockDim.x)
        rowptr[i] += offs[i >> 10];
    if (tid == 0) rowptr[N_ENTC] = total_s;
}

__global__ void k_fill(const int* __restrict__ dst, const int* __restrict__ src,
                       const int* __restrict__ typ, const int* __restrict__ rowptr,
                       int* cursor, int* csr) {
    int e = blockIdx.x * blockDim.x + threadIdx.x;
    if (e < NEC) {
        int d = dst[e];
        int p = atomicAdd(&cursor[d], 1);
        csr[rowptr[d] + p] = src[e] | (typ[e] << 16);
    }
}

__global__ void k_aggregate(const int* __restrict__ rowptr, const int* __restrict__ csr) {
    int node = blockIdx.x;
    int c = threadIdx.x;  // 64
    __shared__ int s_src[256];
    __shared__ int s_typ[256];
    const __nv_bfloat162* entb = (const __nv_bfloat162*)g_entb;
    const __nv_bfloat162* relb = (const __nv_bfloat162*)g_relb;
    int beg = rowptr[node], end = rowptr[node + 1];
    int deg = end - beg;
    float ax = 0.f, ay = 0.f;
    for (int base = beg; base < end; base += 256) {
        int cnt = min(256, end - base);
        for (int i = c; i < cnt; i += 64) {
            int p = csr[base + i];
            s_src[i] = (p & 0xFFFF) << 6;
            s_typ[i] = ((unsigned)p >> 16) << 6;
        }
        __syncthreads();
        #pragma unroll 4
        for (int i = 0; i < cnt; i++) {
            __nv_bfloat162 ev = entb[s_src[i] + c];
            __nv_bfloat162 rv = relb[s_typ[i] + c];
            ax += __bfloat162float(ev.x) + __bfloat162float(rv.x);
            ay += __bfloat162float(ev.y) + __bfloat162float(rv.y);
        }
        __syncthreads();
    }
    float inv = (deg > 0) ? 1.f / (float)deg : 0.f;
    __nv_bfloat162 o;
    o.x = __float2bfloat16(ax * inv);
    o.y = __float2bfloat16(ay * inv);
    *(__nv_bfloat162*)(g_aggb + (size_t)node * HC + 2 * c) = o;
}

// ---------------- GEMM fragment helpers ----------------
#define BGM 128
#define BGN 128
#define BGK 32
#define SSTR 40
#define XSTR 136

#define MMA_STEP(As_, Bs_, STRA, kbaseA, kk, cacc)                                   \
    {                                                                                 \
        uint32_t a[2][4], b[8][2];                                                    \
        _Pragma("unroll")                                                             \
        for (int mt = 0; mt < 2; mt++) {                                              \
            int row = wm * 32 + mt * 16 + (lane & 15);                                \
            int col = (kbaseA) + (kk) + ((lane >> 4) << 3);                           \
            uint32_t addr = (uint32_t)__cvta_generic_to_shared((As_) + row * (STRA) + col); \
            asm volatile("ldmatrix.sync.aligned.m8n8.x4.shared.b16 {%0,%1,%2,%3},[%4];" \
                         : "=r"(a[mt][0]), "=r"(a[mt][1]), "=r"(a[mt][2]), "=r"(a[mt][3]) \
                         : "r"(addr));                                                \
        }                                                                             \
        _Pragma("unroll")                                                             \
        for (int np = 0; np < 4; np++) {                                              \
            int nrow = wn * 64 + np * 16 + ((lane >> 4) << 3) + (lane & 7);           \
            int ncol = (kk) + (((lane >> 3) & 1) << 3);                               \
            uint32_t addr = (uint32_t)__cvta_generic_to_shared((Bs_) + nrow * SSTR + ncol); \
            asm volatile("ldmatrix.sync.aligned.m8n8.x4.shared.b16 {%0,%1,%2,%3},[%4];" \
                         : "=r"(b[2 * np][0]), "=r"(b[2 * np][1]),                    \
                           "=r"(b[2 * np + 1][0]), "=r"(b[2 * np + 1][1])             \
                         : "r"(addr));                                                \
        }                                                                             \
        _Pragma("unroll")                                                             \
        for (int mt = 0; mt < 2; mt++)                                                \
            _Pragma("unroll")                                                         \
            for (int nt = 0; nt < 8; nt++)                                            \
                asm volatile(                                                         \
                    "mma.sync.aligned.m16n8k16.row.col.f32.bf16.bf16.f32 "            \
                    "{%0,%1,%2,%3},{%4,%5,%6,%7},{%8,%9},{%0,%1,%2,%3};"              \
                    : "+f"(cacc[mt][nt][0]), "+f"(cacc[mt][nt][1]),                   \
                      "+f"(cacc[mt][nt][2]), "+f"(cacc[mt][nt][3])                    \
                    : "r"(a[mt][0]), "r"(a[mt][1]), "r"(a[mt][2]), "r"(a[mt][3]),     \
                      "r"(b[nt][0]), "r"(b[nt][1]));                                  \
    }

// ---------------- score GEMM + fused final ----------------
__global__ __launch_bounds__(256)
void k_score(const __nv_bfloat16* __restrict__ A, const __nv_bfloat16* __restrict__ B,
             float* __restrict__ Cf, const int* __restrict__ trip, double* acc,
             int* done, int nblocks, int write_final, int M, int N) {
    __shared__ __nv_bfloat16 As[BGM * SSTR];
    __shared__ __nv_bfloat16 Bs[BGN * SSTR];
    int tid = threadIdx.x;
    int lane = tid & 31, wid = tid >> 5;
    int wm = wid & 3, wn = wid >> 2;
    int rowBase = blockIdx.y * BGM;
    int colBase = blockIdx.x * BGN;
    float c[2][8][4];
    #pragma unroll
    for (int i = 0; i < 2; i++)
        #pragma unroll
        for (int j = 0; j < 8; j++)
            #pragma unroll
            for (int q = 0; q < 4; q++) c[i][j][q] = 0.f;
    for (int k0 = 0; k0 < HC; k0 += BGK) {
        #pragma unroll
        for (int i = 0; i < 2; i++) {
            int idx = tid + i * 256;
            int r = idx >> 2, seg = idx & 3;
            *(uint4*)(As + r * SSTR + seg * 8) =
                *(const uint4*)(A + (size_t)(rowBase + r) * HC + k0 + seg * 8);
            uint4 vb = make_uint4(0, 0, 0, 0);
            int gn = colBase + r;
            if (gn < N) vb = *(const uint4*)(B + (size_t)gn * HC + k0 + seg * 8);
            *(uint4*)(Bs + r * SSTR + seg * 8) = vb;
        }
        __syncthreads();
        MMA_STEP(As, Bs, SSTR, 0, 0, c)
        MMA_STEP(As, Bs, SSTR, 0, 16, c)
        __syncthreads();
    }
    float lsp = 0.f, lxo = 0.f;
    #pragma unroll
    for (int mt = 0; mt < 2; mt++) {
        int r0 = rowBase + wm * 32 + mt * 16 + (lane >> 2);
        int ob0 = trip[r0 * 3 + 2];
        int ob1 = trip[(r0 + 8) * 3 + 2];
        #pragma unroll
        for (int nt = 0; nt < 8; nt++) {
            int col = colBase + wn * 64 + nt * 8 + ((lane & 3) << 1);
            if (col < N) {
                #pragma unroll
                for (int half = 0; half < 2; half++) {
                    int row = r0 + half * 8;
                    int ob = half ? ob1 : ob0;
                    float x0 = c[mt][nt][half * 2 + 0];
                    float x1 = c[mt][nt][half * 2 + 1];
                    float s0, p0, s1, p1;
                    sig_sp(x0, s0, p0);
                    sig_sp(x1, s1, p1);
                    *(float2*)(Cf + (size_t)row * N + col) = make_float2(s0, s1);
                    lsp += p0 + p1;
                    if (col == ob) lxo += x0;
                    if (col + 1 == ob) lxo += x1;
                }
            }
        }
    }
    float bs = blockReduceSum(lsp);
    float bx = blockReduceSum(lxo);
    if (tid == 0) {
        atomicAdd(&acc[0], (double)bs);
        atomicAdd(&acc[1], (double)bx);
        __threadfence();
        int old = atomicAdd(done, 1);
        if (old == nblocks - 1 && write_final) {
            double a0 = atomicAdd(&acc[0], 0.0);
            double a1 = atomicAdd(&acc[1], 0.0);
            double a2 = atomicAdd(&acc[2], 0.0);
            Cf[(size_t)NBC * N_ENTC]     = (float)(a2 / (double)(NBC * HC));
            Cf[(size_t)NBC * N_ENTC + 1] = (float)((a0 - a1) /
                                                   ((double)NBC * (double)N_ENTC));
        }
    }
}

// ---------------- fused pre+aln ----------------
__global__ __launch_bounds__(256)
void k_prealn(const float* __restrict__ bal, const int* __restrict__ deg, int M) {
    extern __shared__ __nv_bfloat16 sm[];
    __nv_bfloat16* As = sm;
    __nv_bfloat16* Bs = sm + BGM * SSTR;
    __nv_bfloat16* Xs = sm + 2 * BGM * SSTR;
    int tid = threadIdx.x, lane = tid & 31, wid = tid >> 5;
    int wm = wid & 3, wn = wid >> 2;
    int rowBase = blockIdx.x * BGM;
    int lr[2]; bool lv[2], lm[2];
    #pragma unroll
    for (int i = 0; i < 2; i++) {
        int idx = tid + i * 256;
        lr[i] = idx >> 2;
        int gr = rowBase + lr[i];
        lv[i] = gr < M;
        lm[i] = lv[i] && (deg[lv[i] ? gr : 0] > 0);
    }
    float c[2][8][4];
    #pragma unroll
    for (int i = 0; i < 2; i++)
        #pragma unroll
        for (int j = 0; j < 8; j++)
            #pragma unroll
            for (int q = 0; q < 4; q++) c[i][j][q] = 0.f;
    for (int k0 = 0; k0 < KPRE; k0 += BGK) {
        #pragma unroll
        for (int i = 0; i < 2; i++) {
            int idx = tid + i * 256;
            int r = lr[i], seg = idx & 3;
            int gr = rowBase + r;
            int kc = k0 + seg * 8;
            uint4 va = make_uint4(0, 0, 0, 0);
            if (lv[i]) {
                if (k0 < 128) {
                    va = *(const uint4*)(g_aggb + (size_t)gr * HC + kc);
                } else if (k0 < 256) {
                    if (lm[i]) va = *(const uint4*)(g_entb + (size_t)gr * HC + kc - 128);
                } else {
                    if (!lm[i]) va = *(const uint4*)(g_entb + (size_t)gr * HC + kc - 256);
                }
            }
            *(uint4*)(As + r * SSTR + seg * 8) = va;
            *(uint4*)(Bs + r * SSTR + seg * 8) =
                *(const uint4*)(g_B3 + (size_t)r * KPRE + k0 + seg * 8);
        }
        __syncthreads();
        MMA_STEP(As, Bs, SSTR, 0, 0, c)
        MMA_STEP(As, Bs, SSTR, 0, 16, c)
        __syncthreads();
    }
    #pragma unroll
    for (int mt = 0; mt < 2; mt++) {
        #pragma unroll
        for (int nt = 0; nt < 8; nt++) {
            int colL = wn * 64 + nt * 8 + ((lane & 3) << 1);
            #pragma unroll
            for (int half = 0; half < 2; half++) {
                int rowL = wm * 32 + mt * 16 + (lane >> 2) + half * 8;
                float v0 = c[mt][nt][half * 2 + 0];
                float v1 = c[mt][nt][half * 2 + 1];
                v0 = (v0 >= 0.f) ? v0 : v0 * SLOPE;
                v1 = (v1 >= 0.f) ? v1 : v1 * SLOPE;
                __nv_bfloat162 bv(__float2bfloat16(v0), __float2bfloat16(v1));
                *(__nv_bfloat162*)(Xs + rowL * XSTR + colL) = bv;
                int grow = rowBase + rowL;
                if (grow < M)
                    *(__nv_bfloat162*)(g_prebf + (size_t)grow * HC + colL) = bv;
            }
        }
    }
    __syncthreads();
    float c2[2][8][4];
    #pragma unroll
    for (int i = 0; i < 2; i++)
        #pragma unroll
        for (int j = 0; j < 8; j++)
            #pragma unroll
            for (int q = 0; q < 4; q++) c2[i][j][q] = 0.f;
    for (int k0 = 0; k0 < HC; k0 += BGK) {
        #pragma unroll
        for (int i = 0; i < 2; i++) {
            int idx = tid + i * 256;
            int r = idx >> 2, seg = idx & 3;
            *(uint4*)(Bs + r * SSTR + seg * 8) =
                *(const uint4*)(g_walb + (size_t)r * HC + k0 + seg * 8);
        }
        __syncthreads();
        MMA_STEP(Xs, Bs, XSTR, k0, 0, c2)
        MMA_STEP(Xs, Bs, XSTR, k0, 16, c2)
        __syncthreads();
    }
    #pragma unroll
    for (int mt = 0; mt < 2; mt++) {
        #pragma unroll
        for (int nt = 0; nt < 8; nt++) {
            int colL = wn * 64 + nt * 8 + ((lane & 3) << 1);
            float b0 = bal[colL], b1 = bal[colL + 1];
            #pragma unroll
            for (int half = 0; half < 2; half++) {
                int grow = rowBase + wm * 32 + mt * 16 + (lane >> 2) + half * 8;
                if (grow < M) {
                    __nv_bfloat162 bv(__float2bfloat16(c2[mt][nt][half * 2 + 0] + b0),
                                      __float2bfloat16(c2[mt][nt][half * 2 + 1] + b1));
                    *(__nv_bfloat162*)(g_alnbf + (size_t)grow * HC + colL) = bv;
                }
            }
        }
    }
}

// ---------------- fused softmax+rpath+giall ----------------
__global__ __launch_bounds__(256)
void k_rpgi(const float* __restrict__ part, const float* __restrict__ Amat,
            const float* __restrict__ bih, float* __restrict__ giall) {
    extern __shared__ __nv_bfloat16 sm[];
    __nv_bfloat16* As = sm;
    __nv_bfloat16* Bs = sm + BGM * SSTR;
    __nv_bfloat16* Xs = sm + 2 * BGM * SSTR;
    int tid = threadIdx.x, lane = tid & 31, wid = tid >> 5;
    int wm = wid & 3, wn = wid >> 2;
    int rowBase = blockIdx.x * BGM;
    if (blockIdx.x < 64) {
        for (int rr = wid; rr < BGM; rr += 8) {
            int grow = rowBase + rr;
            int t = grow >> 10, b = grow & 1023;
            const float* prow = part + (size_t)b * (NTC * NRELC) + t * NRELC;
            const float* arow = Amat + (size_t)b * NRELC;
            float xv[15];
            float m = -3.402823e38f;
            #pragma unroll
            for (int i = 0; i < 15; i++) {
                int cc = lane + i * 32;
                float x = -3.402823e38f;
                if (cc < NRELC) {
                    float val = prow[cc] * arow[cc];
                    x = (val == 0.f) ? -1e9f : val;
                }
                xv[i] = x;
                m = fmaxf(m, x);
            }
            #pragma unroll
            for (int o = 16; o > 0; o >>= 1) m = fmaxf(m, __shfl_xor_sync(0xffffffffu, m, o));
            float s = 0.f;
            float ev[15];
            #pragma unroll
            for (int i = 0; i < 15; i++) {
                int cc = lane + i * 32;
                float e = (cc < NRELC) ? __expf(xv[i] - m) : 0.f;
                ev[i] = e;
                s += e;
            }
            #pragma unroll
            for (int o = 16; o > 0; o >>= 1) s += __shfl_xor_sync(0xffffffffu, s, o);
            float inv = 1.f / s;
            __nv_bfloat16* orow = g_attnb + (size_t)grow * KPAD;
            #pragma unroll
            for (int i = 0; i < 15; i++) {
                int cc = lane + i * 32;
                if (cc < NRELC) orow[cc] = __float2bfloat16(ev[i] * inv);
            }
        }
        __syncthreads();
        float c[2][8][4];
        #pragma unroll
        for (int i = 0; i < 2; i++)
            #pragma unroll
            for (int j = 0; j < 8; j++)
                #pragma unroll
                for (int q = 0; q < 4; q++) c[i][j][q] = 0.f;
        for (int k0 = 0; k0 < KPAD; k0 += BGK) {
            #pragma unroll
            for (int i = 0; i < 2; i++) {
                int idx = tid + i * 256;
                int r = idx >> 2, seg = idx & 3;
                *(uint4*)(As + r * SSTR + seg * 8) =
                    *(const uint4*)(g_attnb + (size_t)(rowBase + r) * KPAD + k0 + seg * 8);
                *(uint4*)(Bs + r * SSTR + seg * 8) =
                    *(const uint4*)(g_mrelTb + (size_t)r * KPAD + k0 + seg * 8);
            }
            __syncthreads();
            MMA_STEP(As, Bs, SSTR, 0, 0, c)
            MMA_STEP(As, Bs, SSTR, 0, 16, c)
            __syncthreads();
        }
        #pragma unroll
        for (int mt = 0; mt < 2; mt++)
            #pragma unroll
            for (int nt = 0; nt < 8; nt++) {
                int colL = wn * 64 + nt * 8 + ((lane & 3) << 1);
                #pragma unroll
                for (int half = 0; half < 2; half++) {
                    int rowL = wm * 32 + mt * 16 + (lane >> 2) + half * 8;
                    __nv_bfloat162 bv(__float2bfloat16(c[mt][nt][half * 2 + 0]),
                                      __float2bfloat16(c[mt][nt][half * 2 + 1]));
                    *(__nv_bfloat162*)(Xs + rowL * XSTR + colL) = bv;
                }
            }
    } else {
        for (int i = tid; i < BGM * (HC / 8); i += 256) {
            int r = i / (HC / 8), seg = i % (HC / 8);
            *(uint4*)(Xs + r * XSTR + seg * 8) =
                *(const uint4*)(g_Xb + (size_t)(rowBase + r) * HC + seg * 8);
        }
    }
    __syncthreads();
    for (int nb = 0; nb < 3; nb++) {
        float c2[2][8][4];
        #pragma unroll
        for (int i = 0; i < 2; i++)
            #pragma unroll
            for (int j = 0; j < 8; j++)
                #pragma unroll
                for (int q = 0; q < 4; q++) c2[i][j][q] = 0.f;
        for (int k0 = 0; k0 < HC; k0 += BGK) {
            #pragma unroll
            for (int i = 0; i < 2; i++) {
                int idx = tid + i * 256;
                int r = idx >> 2, seg = idx & 3;
                *(uint4*)(Bs + r * SSTR + seg * 8) =
                    *(const uint4*)(g_wihb + (size_t)(nb * 128 + r) * HC + k0 + seg * 8);
            }
            __syncthreads();
            MMA_STEP(Xs, Bs, XSTR, k0, 0, c2)
            MMA_STEP(Xs, Bs, XSTR, k0, 16, c2)
            __syncthreads();
        }
        #pragma unroll
        for (int mt = 0; mt < 2; mt++)
            #pragma unroll
            for (int nt = 0; nt < 8; nt++) {
                int colL = wn * 64 + nt * 8 + ((lane & 3) << 1);
                int col = nb * 128 + colL;
                float b0 = bih[col], b1 = bih[col + 1];
                #pragma unroll
                for (int half = 0; half < 2; half++) {
                    int row = rowBase + wm * 32 + mt * 16 + (lane >> 2) + half * 8;
                    *(float2*)(giall + (size_t)row * H3C + col) =
                        make_float2(c2[mt][nt][half * 2 + 0] + b0,
                                    c2[mt][nt][half * 2 + 1] + b1);
                }
            }
    }
}

// ---------------- fused mapped_rel ----------------
__global__ __launch_bounds__(256)
void k_mrel(const float* __restrict__ rel, const float* __restrict__ Wm1T,
            const float* __restrict__ Wm2T, const float* __restrict__ bm1,
            const float* __restrict__ bm2, float* __restrict__ mrel,
            float* __restrict__ mrelT) {
    __shared__ float rels[10][128];
    __shared__ float p1s[10][256];
    int tid = threadIdx.x;
    int r0 = blockIdx.x * 10;
    for (int i = tid; i < 10 * 128; i += 256)
        rels[i >> 7][i & 127] = rel[(r0 + (i >> 7)) * 128 + (i & 127)];
    __syncthreads();
    {
        int j2 = tid;
        float a[10];
        #pragma unroll
        for (int r = 0; r < 10; r++) a[r] = 0.f;
        for (int k = 0; k < 128; k++) {
            float w = Wm1T[k * 256 + j2];
            #pragma unroll
            for (int r = 0; r < 10; r++) a[r] = fmaf(rels[r][k], w, a[r]);
        }
        float b = bm1[j2];
        #pragma unroll
        for (int r = 0; r < 10; r++) p1s[r][j2] = a[r] + b;
    }
    __syncthreads();
    {
        int j = tid & 127, half = tid >> 7;
        float a[5];
        #pragma unroll
        for (int r = 0; r < 5; r++) a[r] = 0.f;
        for (int k = 0; k < 256; k++) {
            float w = Wm2T[k * 128 + j];
            #pragma unroll
            for (int r = 0; r < 5; r++) a[r] = fmaf(p1s[half * 5 + r][k], w, a[r]);
        }
        float b = bm2[j];
        #pragma unroll
        for (int r = 0; r < 5; r++) {
            int row = r0 + half * 5 + r;
            float v = a[r] + b;
            mrel[row * 128 + j] = v;
            mrelT[j * MT_STR + row] = v;
            g_mrelTb[j * KPAD + row] = __float2bfloat16(v);
        }
    }
}

__global__ __launch_bounds__(128)
void k_qa_amat(const float* __restrict__ mrel, const int* __restrict__ trip,
               const float* __restrict__ WatT, const float* __restrict__ bat,
               const float* __restrict__ mrelT, float* __restrict__ qrel,
               float* __restrict__ Amat) {
    __shared__ float q[4][128];
    __shared__ float qa[4][128];
    int j = threadIdx.x;
    int r0 = blockIdx.x * 4;
    #pragma unroll
    for (int r = 0; r < 4; r++) {
        float v = mrel[(size_t)trip[(r0 + r) * 3 + 1] * HC + j];
        q[r][j] = v;
        qrel[(r0 + r) * 128 + j] = v;
        g_Xb[(size_t)(NTC * NBC + r0 + r) * HC + j] = __float2bfloat16(v);
    }
    __syncthreads();
    {
        float a[4] = {0.f, 0.f, 0.f, 0.f};
        for (int k = 0; k < 128; k++) {
            float w = WatT[k * 128 + j];
            #pragma unroll
            for (int r = 0; r < 4; r++) a[r] = fmaf(q[r][k], w, a[r]);
        }
        float b = bat[j];
        #pragma unroll
        for (int r = 0; r < 4; r++) qa[r][j] = a[r] + b;
    }
    __syncthreads();
    float a[4][4];
    #pragma unroll
    for (int r = 0; r < 4; r++)
        #pragma unroll
        for (int t = 0; t < 4; t++) a[r][t] = 0.f;
    for (int k = 0; k < 128; k++) {
        float m0 = mrelT[k * MT_STR + j];
        float m1 = mrelT[k * MT_STR + j + 128];
        float m2 = mrelT[k * MT_STR + j + 256];
        float m3 = mrelT[k * MT_STR + j + 384];
        #pragma unroll
        for (int r = 0; r < 4; r++) {
            float qv = qa[r][k];
            a[r][0] = fmaf(qv, m0, a[r][0]);
            a[r][1] = fmaf(qv, m1, a[r][1]);
            a[r][2] = fmaf(qv, m2, a[r][2]);
            a[r][3] = fmaf(qv, m3, a[r][3]);
        }
    }
    #pragma unroll
    for (int r = 0; r < 4; r++)
        #pragma unroll
        for (int t = 0; t < 4; t++) {
            int n = j + t * 128;
            if (n < NRELC) Amat[(size_t)(r0 + r) * NRELC + n] = a[r][t];
        }
}

// ---------------- mega GRU kernel ----------------
__global__ __launch_bounds__(384)
void k_gru_all(const float* __restrict__ giall, const float* __restrict__ whhT,
               const float* __restrict__ bhh, const float* __restrict__ qrel,
               const float* __restrict__ Wh1T, const float* __restrict__ Wh2T,
               const float* __restrict__ bh1, const float* __restrict__ bh2,
               const int* __restrict__ trip, const float* __restrict__ WalT,
               const float* __restrict__ bal, double* acc) {
    extern __shared__ float swhh[];
    __shared__ float hs[8][128];
    __shared__ float asg[8][384];
    __shared__ float qs[8][128];
    __shared__ float ps[8][128];
    int tid = threadIdx.x;
    int j = tid & 127;
    int g = tid >> 7;
    int r0 = blockIdx.x * 8;

    for (int i = tid; i < HC * H3C; i += 384) swhh[i] = whhT[i];
    for (int i = tid; i < 8 * 128; i += 384) hs[i >> 7][i & 127] = 0.f;
    __syncthreads();

    for (int t = 0; t < NTC; t++) {
        {
            float a[8];
            #pragma unroll
            for (int r = 0; r < 8; r++) a[r] = 0.f;
            for (int k = 0; k < 128; k++) {
                float w = swhh[k * H3C + tid];
                #pragma unroll
                for (int r = 0; r < 8; r++) a[r] = fmaf(hs[r][k], w, a[r]);
            }
            #pragma unroll
            for (int r = 0; r < 8; r++) asg[r][tid] = a[r];
        }
        __syncthreads();
        if (tid < 128) {
            float br = bhh[j], bz = bhh[128 + j], bn = bhh[256 + j];
            const float* gi = giall + (size_t)t * NBC * H3C;
            #pragma unroll
            for (int r = 0; r < 8; r++) {
                size_t gx = (size_t)(r0 + r) * H3C;
                float rr = sigm(gi[gx + j] + asg[r][j] + br);
                float zz = sigm(gi[gx + 128 + j] + asg[r][128 + j] + bz);
                float nn = tanhf(gi[gx + 256 + j] + rr * (asg[r][256 + j] + bn));
                hs[r][j] = (1.f - zz) * nn + zz * hs[r][j];
            }
        }
        __syncthreads();
    }

    for (int i = tid; i < 8 * 128; i += 384)
        qs[i >> 7][i & 127] = qrel[(r0 + (i >> 7)) * 128 + (i & 127)];
    __syncthreads();

    for (int r = g; r < 8; r += 3) {
        float a = 0.f;
        for (int k = 0; k < 128; k++) a = fmaf(qs[r][k], Wh1T[k * 128 + j], a);
        ps[r][j] = a + bh1[j];
    }
    __syncthreads();
    float predv[3];
    int nmine = 0;
    for (int r = g; r < 8; r += 3) {
        float a = 0.f;
        for (int k = 0; k < 128; k++) a = fmaf(ps[r][k], Wh2T[k * 128 + j], a);
        predv[nmine++] = 0.1f * (a + bh2[j]) + qs[r][j];
    }
    __syncthreads();
    {
        int m = 0;
        for (int r = g; r < 8; r += 3) ps[r][j] = predv[m++];
    }
    __syncthreads();
    {
        float msum = 0.f;
        for (int r = g; r < 8; r += 3) {
            float d = ps[r][j] - hs[r][j];
            msum += d * d;
        }
        float bsum = blockReduceSum(msum);
        if (tid == 0) atomicAdd(&acc[2], (double)bsum);
    }
    __syncthreads();
    {
        float a[8];
        #pragma unroll
        for (int r = 0; r < 8; r++) a[r] = 0.f;
        for (int k = 0; k < 128; k++) {
            float w = swhh[k * H3C + tid];
            #pragma unroll
            for (int r = 0; r < 8; r++) a[r] = fmaf(ps[r][k], w, a[r]);
        }
        #pragma unroll
        for (int r = 0; r < 8; r++) asg[r][tid] = a[r];
    }
    __syncthreads();
    if (tid < 128) {
        float br = bhh[j], bz = bhh[128 + j], bn = bhh[256 + j];
        const float* gi = giall + (size_t)NTC * NBC * H3C;
        #pragma unroll
        for (int r = 0; r < 8; r++) {
            size_t gx = (size_t)(r0 + r) * H3C;
            float rr = sigm(gi[gx + j] + asg[r][j] + br);
            float zz = sigm(gi[gx + 128 + j] + asg[r][128 + j] + bz);
            float nn = tanhf(gi[gx + 256 + j] + rr * (asg[r][256 + j] + bn));
            hs[r][j] = (1.f - zz) * nn + zz * ps[r][j];
        }
    }
    __syncthreads();
    for (int i = tid; i < 8 * 128; i += 384) {
        int r = i >> 7, c = i & 127;
        int row = trip[(r0 + r) * 3 + 0];
        qs[r][c] = __bfloat162float(g_prebf[(size_t)row * HC + c]);
    }
    __syncthreads();
    for (int r = g; r < 8; r += 3) {
        float a = 0.f;
        for (int k = 0; k < 128; k++) a = fmaf(qs[r][k], WalT[k * 128 + j], a);
        float v = (a + bal[j]) * hs[r][j];
        g_svecb[(r0 + r) * 128 + j] = __float2bfloat16(v);
    }
}

// ---------------- host ----------------
extern "C" void kernel_launch(void* const* d_in, const int* in_sizes, int n_in,
                              void* d_out, int out_size) {
    const float* ent  = (const float*)d_in[0];
    const float* rel  = (const float*)d_in[1];
    const float* Wn   = (const float*)d_in[2];
    const float* Wl   = (const float*)d_in[3];
    const float* Wev  = (const float*)d_in[4];
    const float* wih  = (const float*)d_in[5];
    const float* whh  = (const float*)d_in[6];
    const float* bih  = (const float*)d_in[7];
    const float* bhh  = (const float*)d_in[8];
    const float* Wm1  = (const float*)d_in[9];
    const float* bm1  = (const float*)d_in[10];
    const float* Wm2  = (const float*)d_in[11];
    const float* bm2  = (const float*)d_in[12];
    const float* Wh1  = (const float*)d_in[13];
    const float* bh1  = (const float*)d_in[14];
    const float* Wh2  = (const float*)d_in[15];
    const float* bh2  = (const float*)d_in[16];
    const float* Wal  = (const float*)d_in[17];
    const float* bal  = (const float*)d_in[18];
    const float* Wat  = (const float*)d_in[19];
    const float* bat  = (const float*)d_in[20];
    const float* part = (const float*)d_in[21];
    const int* esrc = (const int*)d_in[22];
    const int* edst = (const int*)d_in[23];
    const int* etyp = (const int*)d_in[24];
    const int* trip = (const int*)d_in[25];
    float* out = (float*)d_out;

    void* basep = nullptr;
    cudaGetSymbolAddress(&basep, d_buf);
    float* F = (float*)basep;
    __nv_bfloat16 *pSvecb, *pAlnb;
    { void* p; cudaGetSymbolAddress(&p, g_svecb); pSvecb = (__nv_bfloat16*)p; }
    { void* p; cudaGetSymbolAddress(&p, g_alnbf); pAlnb  = (__nv_bfloat16*)p; }

    float* mrel   = F + O_MREL;
    float* mrelT  = F + O_MRELT;
    float* qrel   = F + O_QREL;
    float* Amat   = F + O_AMAT;
    float* giall  = F + O_GIALL;
    float* whhT   = F + O_WHHT;
    float* Wh1T   = F + O_WH1T;
    float* Wh2T   = F + O_WH2T;
    float* WatT   = F + O_WATT;
    float* WalT   = F + O_WALT;
    float* Wm1T   = F + O_WM1T;
    float* Wm2T   = F + O_WM2T;
    double* acc   = (double*)(F + O_ACC);
    int* deg      = (int*)(F + O_INT);
    int* rowptr   = deg + N_ENTC;
    int* cursor   = rowptr + N_ENTC + 1;
    int* csr      = cursor + N_ENTC;
    int* bsums    = csr + NEC;
    int* done     = bsums + 32;

    const int FUSED_SMEM = (2 * BGM * SSTR + BGM * XSTR) * 2;  // 55296 B
    const int GRU_SMEM = HC * H3C * 4;                          // 196608 B
    static bool s_init = false;
    static cudaStream_t sB = 0;
    static cudaEvent_t evF = 0, evB = 0;
    if (!s_init) {
        cudaFuncSetAttribute(k_prealn, cudaFuncAttributeMaxDynamicSharedMemorySize, FUSED_SMEM);
        cudaFuncSetAttribute(k_rpgi,   cudaFuncAttributeMaxDynamicSharedMemorySize, FUSED_SMEM);
        cudaFuncSetAttribute(k_gru_all, cudaFuncAttributeMaxDynamicSharedMemorySize, GRU_SMEM);
        cudaStreamCreateWithFlags(&sB, cudaStreamNonBlocking);
        cudaEventCreateWithFlags(&evF, cudaEventDisableTiming);
        cudaEventCreateWithFlags(&evB, cudaEventDisableTiming);
        s_init = true;
    }

    k_init<<<640, 256>>>(Wn, Wl, Wev, wih, whh, Wal, Wh1, Wh2, Wat, Wm1, Wm2, rel,
                         deg, cursor, acc, done, F);
    cudaEventRecord(evF, 0);
    cudaStreamWaitEvent(sB, evF, 0);

    // ---- chain B (relation path) on sB ----
    k_mrel<<<46, 256, 0, sB>>>(rel, Wm1T, Wm2T, bm1, bm2, mrel, mrelT);
    k_qa_amat<<<256, 128, 0, sB>>>(mrel, trip, WatT, bat, mrelT, qrel, Amat);
    k_rpgi<<<(NTC + 1) * NBC / BGM, 256, FUSED_SMEM, sB>>>(part, Amat, bih, giall);
    cudaEventRecord(evB, sB);

    // ---- chain A (entity path) on default stream ----
    k_count_entcvt<<<(N_ENTC * HC + 255) / 256, 256>>>(edst, deg, ent);
    k_scanA<<<(N_ENTC + 1023) / 1024, 1024>>>(deg, rowptr, bsums);
    k_scanB<<<1, 1024>>>(rowptr, bsums, (N_ENTC + 1023) / 1024);
    k_fill<<<(NEC + 255) / 256, 256>>>(edst, esrc, etyp, rowptr, cursor, csr);
    k_aggregate<<<N_ENTC, 64>>>(rowptr, csr);
    k_prealn<<<(N_ENTC + BGM - 1) / BGM, 256, FUSED_SMEM>>>(bal, deg, N_ENTC);

    // ---- join ----
    cudaStreamWaitEvent(0, evB, 0);
    k_gru_all<<<128, 384, GRU_SMEM>>>(giall, whhT, bhh, qrel, Wh1T, Wh2T, bh1, bh2,
                                      trip, WalT, bal, acc);
    {
        dim3 g((N_ENTC + BGN - 1) / BGN, NBC / BGM);
        int nblocks = g.x * g.y;
        int wf = (out_size >= NBC * N_ENTC + 2) ? 1 : 0;
        k_score<<<g, 256>>>(pSvecb, pAlnb, out, trip, acc, done, nblocks, wf,
                            NBC, N_ENTC);
    }
}

// round 13
// speedup vs baseline: 3.1200x; 1.0448x over previous
#include <cuda_runtime.h>
#include <cuda_bf16.h>
#include <stdint.h>
#include <math.h>

#define N_ENTC 20000
#define NRELC  460
#define HC     128
#define NEC    400000
#define NBC    1024
#define NTC    8
#define H3C    384
#define SLOPE  0.22916666666666666f
#define KPRE   384
#define KPAD   480
#define MT_STR 512

// ---------------- fp32 scratch ----------------
constexpr size_t O_MREL  = 0;
constexpr size_t O_MRELT = O_MREL + (size_t)NRELC * HC;
constexpr size_t O_QREL  = O_MRELT + (size_t)HC * MT_STR;
constexpr size_t O_AMAT  = O_QREL + (size_t)NBC * HC;
constexpr size_t O_GIALL = O_AMAT + (size_t)NBC * NRELC;
constexpr size_t O_WHHT  = O_GIALL + (size_t)(NTC + 1) * NBC * H3C;
constexpr size_t O_WH1T  = O_WHHT + 49152;
constexpr size_t O_WH2T  = O_WH1T + 16384;
constexpr size_t O_WATT  = O_WH2T + 16384;
constexpr size_t O_WALT  = O_WATT + 16384;
constexpr size_t O_WM1T  = O_WALT + 16384;
constexpr size_t O_WM2T  = O_WM1T + 32768;
constexpr size_t O_ACC_  = O_WM2T + 32768;
constexpr size_t O_ACC   = (O_ACC_ + 1) & ~(size_t)1;
constexpr size_t O_INT   = O_ACC + 8;
constexpr size_t N_INTS  = (size_t)N_ENTC + (N_ENTC + 1) + N_ENTC + NEC + 64;
constexpr size_t TOTALF  = O_INT + N_INTS;
__device__ __align__(16) float d_buf[TOTALF];

// ---------------- bf16 scratch ----------------
__device__ __align__(16) __nv_bfloat16 g_aggb[(size_t)N_ENTC * HC];
__device__ __align__(16) __nv_bfloat16 g_B3[HC * KPRE];
__device__ __align__(16) __nv_bfloat16 g_entb[(size_t)N_ENTC * HC];
__device__ __align__(16) __nv_bfloat16 g_relb[NRELC * HC];
__device__ __align__(16) __nv_bfloat16 g_prebf[(size_t)N_ENTC * HC];
__device__ __align__(16) __nv_bfloat16 g_alnbf[(size_t)N_ENTC * HC];
__device__ __align__(16) __nv_bfloat16 g_walb[HC * HC];
__device__ __align__(16) __nv_bfloat16 g_wihb[H3C * HC];
__device__ __align__(16) __nv_bfloat16 g_mrelTb[HC * KPAD];
__device__ __align__(16) __nv_bfloat16 g_Xb[(size_t)(NTC + 1) * NBC * HC];
__device__ __align__(16) __nv_bfloat16 g_attnb[(size_t)NTC * NBC * KPAD];
__device__ __align__(16) __nv_bfloat16 g_svecb[(size_t)NBC * HC];

// ---------------- reductions ----------------
__device__ __forceinline__ float blockReduceSum(float v) {
    __shared__ float sh[32];
    int tid = threadIdx.x;
    __syncthreads();
    #pragma unroll
    for (int o = 16; o > 0; o >>= 1) v += __shfl_xor_sync(0xffffffffu, v, o);
    if ((tid & 31) == 0) sh[tid >> 5] = v;
    __syncthreads();
    float r = 0.f;
    if (tid < 32) {
        int nw = (blockDim.x + 31) >> 5;
        r = (tid < nw) ? sh[tid] : 0.f;
        #pragma unroll
        for (int o = 16; o > 0; o >>= 1) r += __shfl_xor_sync(0xffffffffu, r, o);
    }
    return r;
}

__device__ __forceinline__ void sig_sp(float x, float& sig, float& sp) {
    float ax = fabsf(x);
    if (ax < 0.5f) {
        float x2 = x * x;
        sig = 0.5f + x * (0.25f + x2 * (-0.0208333333f + x2 * 0.0020833333f));
        sp  = 0.69314718f + 0.5f * x
            + x2 * (0.125f + x2 * (-0.0052083333f + x2 * 0.00034722222f));
    } else {
        float e = __expf(-ax);
        sig = (x >= 0.f) ? 1.f / (1.f + e) : e / (1.f + e);
        sp  = fmaxf(x, 0.f) + __logf(1.f + e);
    }
}
__device__ __forceinline__ float sigm(float x) { return 1.f / (1.f + __expf(-x)); }

// ---------------- init ----------------
__global__ void k_init(const float* __restrict__ Wn, const float* __restrict__ Wl,
                       const float* __restrict__ Wev, const float* __restrict__ wih,
                       const float* __restrict__ whh, const float* __restrict__ Wal,
                       const float* __restrict__ Wh1, const float* __restrict__ Wh2,
                       const float* __restrict__ Wat, const float* __restrict__ Wm1,
                       const float* __restrict__ Wm2, const float* __restrict__ rel,
                       int* deg, int* cursor, double* acc, int* done, float* F) {
    int i = blockIdx.x * blockDim.x + threadIdx.x;  // grid 640*256
    if (i < N_ENTC) { deg[i] = 0; cursor[i] = 0; }
    if (i == 0) { acc[0] = 0.0; acc[1] = 0.0; acc[2] = 0.0; done[0] = 0; }
    if (i < HC * KPRE) {
        int n = i / KPRE, k = i % KPRE;
        float v = (k < 128) ? Wn[k * 128 + n]
                : (k < 256) ? Wl[(k - 128) * 128 + n]
                            : Wev[(k - 256) * 128 + n];
        g_B3[i] = __float2bfloat16(v);
    }
    if (i < H3C * HC) g_wihb[i] = __float2bfloat16(wih[i]);
    if (i < HC * HC)  g_walb[i] = __float2bfloat16(Wal[i]);
    if (i < NRELC * HC) g_relb[i] = __float2bfloat16(rel[i]);
    if (i < HC * H3C) {
        int k = i / H3C, j = i % H3C;
        F[O_WHHT + i] = whh[j * 128 + k];
    }
    if (i < HC * HC) {
        int k = i / HC, j = i % HC;
        F[O_WH1T + i] = Wh1[j * HC + k];
        F[O_WH2T + i] = Wh2[j * HC + k];
        F[O_WATT + i] = Wat[j * HC + k];
        F[O_WALT + i] = Wal[j * HC + k];
    }
    if (i < 128 * 256) {
        int k = i / 256, j2 = i % 256;
        F[O_WM1T + i] = Wm1[j2 * 128 + k];
    }
    if (i < 256 * 128) {
        int k2 = i / 128, j = i % 128;
        F[O_WM2T + i] = Wm2[j * 256 + k2];
    }
    if (i < HC * (KPAD - NRELC)) {
        int j = i / (KPAD - NRELC), c = NRELC + i % (KPAD - NRELC);
        g_mrelTb[j * KPAD + c] = __float2bfloat16(0.f);
    }
    if (i < HC * (MT_STR - NRELC)) {
        int j = i / (MT_STR - NRELC), c = NRELC + i % (MT_STR - NRELC);
        F[O_MRELT + j * MT_STR + c] = 0.f;
    }
    if (i < NTC * NBC * (KPAD - NRELC)) {
        int row = i / (KPAD - NRELC), c = NRELC + i % (KPAD - NRELC);
        g_attnb[(size_t)row * KPAD + c] = __float2bfloat16(0.f);
    }
}

__global__ void k_count_entcvt(const int* __restrict__ dst, int* deg,
                               const float* __restrict__ ent) {
    int i = blockIdx.x * blockDim.x + threadIdx.x;
    if (i < NEC) atomicAdd(&deg[dst[i]], 1);
    if (i < N_ENTC * HC) g_entb[i] = __float2bfloat16(ent[i]);
}

__global__ void k_scanA(const int* __restrict__ deg, int* rowptr, int* bsums) {
    __shared__ int wsum[32];
    int tid = threadIdx.x, lane = tid & 31, wid = tid >> 5;
    int i = blockIdx.x * 1024 + tid;
    int v = (i < N_ENTC) ? deg[i] : 0;
    int x = v;
    #pragma unroll
    for (int o = 1; o < 32; o <<= 1) {
        int t = __shfl_up_sync(0xffffffffu, x, o);
        if (lane >= o) x += t;
    }
    if (lane == 31) wsum[wid] = x;
    __syncthreads();
    if (wid == 0) {
        int s = wsum[lane];
        #pragma unroll
        for (int o = 1; o < 32; o <<= 1) {
            int t = __shfl_up_sync(0xffffffffu, s, o);
            if (lane >= o) s += t;
        }
        wsum[lane] = s;
    }
    __syncthreads();
    int woff = (wid > 0) ? wsum[wid - 1] : 0;
    int incl = x + woff;
    if (i < N_ENTC) rowptr[i] = incl - v;
    if (tid == 1023) bsums[blockIdx.x] = incl;
}

__global__ void k_scanB(int* rowptr, const int* __restrict__ bsums, int nblk) {
    __shared__ int offs[32];
    __shared__ int total_s;
    int tid = threadIdx.x;
    if (tid < 32) {
        int v = (tid < nblk) ? bsums[tid] : 0;
        int x = v;
        #pragma unroll
        for (int o = 1; o < 32; o <<= 1) {
            int t = __shfl_up_sync(0xffffffffu, x, o);
            if (tid >= o) x += t;
        }
        offs[tid] = x - v;
        if (tid == 31) total_s = x;
    }
    __syncthreads();
    for (int i = tid; i < N_ENTC; i += blockDim.x)
        rowptr[i] += offs[i >> 10];
    if (tid == 0) rowptr[N_ENTC] = total_s;
}

__global__ void k_fill(const int* __restrict__ dst, const int* __restrict__ src,
                       const int* __restrict__ typ, const int* __restrict__ rowptr,
                       int* cursor, int* csr) {
    int e = blockIdx.x * blockDim.x + threadIdx.x;
    if (e < NEC) {
        int d = dst[e];
        int p = atomicAdd(&cursor[d], 1);
        csr[rowptr[d] + p] = src[e] | (typ[e] << 16);
    }
}

__global__ void k_aggregate(const int* __restrict__ rowptr, const int* __restrict__ csr) {
    int node = blockIdx.x;
    int c = threadIdx.x;  // 64
    __shared__ int s_src[256];
    __shared__ int s_typ[256];
    const __nv_bfloat162* entb = (const __nv_bfloat162*)g_entb;
    const __nv_bfloat162* relb = (const __nv_bfloat162*)g_relb;
    int beg = rowptr[node], end = rowptr[node + 1];
    int deg = end - beg;
    float ax = 0.f, ay = 0.f;
    for (int base = beg; base < end; base += 256) {
        int cnt = min(256, end - base);
        for (int i = c; i < cnt; i += 64) {
            int p = csr[base + i];
            s_src[i] = (p & 0xFFFF) << 6;
            s_typ[i] = ((unsigned)p >> 16) << 6;
        }
        __syncthreads();
        #pragma unroll 8
        for (int i = 0; i < cnt; i++) {
            __nv_bfloat162 ev = entb[s_src[i] + c];
            __nv_bfloat162 rv = relb[s_typ[i] + c];
            ax += __bfloat162float(ev.x) + __bfloat162float(rv.x);
            ay += __bfloat162float(ev.y) + __bfloat162float(rv.y);
        }
        __syncthreads();
    }
    float inv = (deg > 0) ? 1.f / (float)deg : 0.f;
    __nv_bfloat162 o;
    o.x = __float2bfloat16(ax * inv);
    o.y = __float2bfloat16(ay * inv);
    *(__nv_bfloat162*)(g_aggb + (size_t)node * HC + 2 * c) = o;
}

// ---------------- GEMM fragment helpers ----------------
#define BGM 128
#define BGN 128
#define BGK 32
#define SSTR 40
#define XSTR 136

#define MMA_STEP(As_, Bs_, STRA, kbaseA, kk, cacc)                                   \
    {                                                                                 \
        uint32_t a[2][4], b[8][2];                                                    \
        _Pragma("unroll")                                                             \
        for (int mt = 0; mt < 2; mt++) {                                              \
            int row = wm * 32 + mt * 16 + (lane & 15);                                \
            int col = (kbaseA) + (kk) + ((lane >> 4) << 3);                           \
            uint32_t addr = (uint32_t)__cvta_generic_to_shared((As_) + row * (STRA) + col); \
            asm volatile("ldmatrix.sync.aligned.m8n8.x4.shared.b16 {%0,%1,%2,%3},[%4];" \
                         : "=r"(a[mt][0]), "=r"(a[mt][1]), "=r"(a[mt][2]), "=r"(a[mt][3]) \
                         : "r"(addr));                                                \
        }                                                                             \
        _Pragma("unroll")                                                             \
        for (int np = 0; np < 4; np++) {                                              \
            int nrow = wn * 64 + np * 16 + ((lane >> 4) << 3) + (lane & 7);           \
            int ncol = (kk) + (((lane >> 3) & 1) << 3);                               \
            uint32_t addr = (uint32_t)__cvta_generic_to_shared((Bs_) + nrow * SSTR + ncol); \
            asm volatile("ldmatrix.sync.aligned.m8n8.x4.shared.b16 {%0,%1,%2,%3},[%4];" \
                         : "=r"(b[2 * np][0]), "=r"(b[2 * np][1]),                    \
                           "=r"(b[2 * np + 1][0]), "=r"(b[2 * np + 1][1])             \
                         : "r"(addr));                                                \
        }                                                                             \
        _Pragma("unroll")                                                             \
        for (int mt = 0; mt < 2; mt++)                                                \
            _Pragma("unroll")                                                         \
            for (int nt = 0; nt < 8; nt++)                                            \
                asm volatile(                                                         \
                    "mma.sync.aligned.m16n8k16.row.col.f32.bf16.bf16.f32 "            \
                    "{%0,%1,%2,%3},{%4,%5,%6,%7},{%8,%9},{%0,%1,%2,%3};"              \
                    : "+f"(cacc[mt][nt][0]), "+f"(cacc[mt][nt][1]),                   \
                      "+f"(cacc[mt][nt][2]), "+f"(cacc[mt][nt][3])                    \
                    : "r"(a[mt][0]), "r"(a[mt][1]), "r"(a[mt][2]), "r"(a[mt][3]),     \
                      "r"(b[nt][0]), "r"(b[nt][1]));                                  \
    }

// ---------------- score GEMM + fused final (pipelined) ----------------
__global__ __launch_bounds__(256)
void k_score(const __nv_bfloat16* __restrict__ A, const __nv_bfloat16* __restrict__ B,
             float* __restrict__ Cf, const int* __restrict__ trip, double* acc,
             int* done, int nblocks, int write_final, int M, int N) {
    __shared__ __nv_bfloat16 As[BGM * SSTR];
    __shared__ __nv_bfloat16 Bs[BGN * SSTR];
    int tid = threadIdx.x;
    int lane = tid & 31, wid = tid >> 5;
    int wm = wid & 3, wn = wid >> 2;
    int rowBase = blockIdx.y * BGM;
    int colBase = blockIdx.x * BGN;
    float c[2][8][4];
    #pragma unroll
    for (int i = 0; i < 2; i++)
        #pragma unroll
        for (int j = 0; j < 8; j++)
            #pragma unroll
            for (int q = 0; q < 4; q++) c[i][j][q] = 0.f;
    uint4 pa[2], pb[2];
    #pragma unroll
    for (int i = 0; i < 2; i++) {
        int idx = tid + i * 256;
        int r = idx >> 2, seg = idx & 3;
        pa[i] = *(const uint4*)(A + (size_t)(rowBase + r) * HC + seg * 8);
        uint4 vb = make_uint4(0, 0, 0, 0);
        int gn = colBase + r;
        if (gn < N) vb = *(const uint4*)(B + (size_t)gn * HC + seg * 8);
        pb[i] = vb;
    }
    for (int k0 = 0; k0 < HC; k0 += BGK) {
        #pragma unroll
        for (int i = 0; i < 2; i++) {
            int idx = tid + i * 256;
            int r = idx >> 2, seg = idx & 3;
            *(uint4*)(As + r * SSTR + seg * 8) = pa[i];
            *(uint4*)(Bs + r * SSTR + seg * 8) = pb[i];
        }
        __syncthreads();
        if (k0 + BGK < HC) {
            #pragma unroll
            for (int i = 0; i < 2; i++) {
                int idx = tid + i * 256;
                int r = idx >> 2, seg = idx & 3;
                pa[i] = *(const uint4*)(A + (size_t)(rowBase + r) * HC + k0 + BGK + seg * 8);
                uint4 vb = make_uint4(0, 0, 0, 0);
                int gn = colBase + r;
                if (gn < N) vb = *(const uint4*)(B + (size_t)gn * HC + k0 + BGK + seg * 8);
                pb[i] = vb;
            }
        }
        MMA_STEP(As, Bs, SSTR, 0, 0, c)
        MMA_STEP(As, Bs, SSTR, 0, 16, c)
        __syncthreads();
    }
    float lsp = 0.f, lxo = 0.f;
    #pragma unroll
    for (int mt = 0; mt < 2; mt++) {
        int r0 = rowBase + wm * 32 + mt * 16 + (lane >> 2);
        int ob0 = trip[r0 * 3 + 2];
        int ob1 = trip[(r0 + 8) * 3 + 2];
        #pragma unroll
        for (int nt = 0; nt < 8; nt++) {
            int col = colBase + wn * 64 + nt * 8 + ((lane & 3) << 1);
            if (col < N) {
                #pragma unroll
                for (int half = 0; half < 2; half++) {
                    int row = r0 + half * 8;
                    int ob = half ? ob1 : ob0;
                    float x0 = c[mt][nt][half * 2 + 0];
                    float x1 = c[mt][nt][half * 2 + 1];
                    float s0, p0, s1, p1;
                    sig_sp(x0, s0, p0);
                    sig_sp(x1, s1, p1);
                    *(float2*)(Cf + (size_t)row * N + col) = make_float2(s0, s1);
                    lsp += p0 + p1;
                    if (col == ob) lxo += x0;
                    if (col + 1 == ob) lxo += x1;
                }
            }
        }
    }
    float bs = blockReduceSum(lsp);
    float bx = blockReduceSum(lxo);
    if (tid == 0) {
        atomicAdd(&acc[0], (double)bs);
        atomicAdd(&acc[1], (double)bx);
        __threadfence();
        int old = atomicAdd(done, 1);
        if (old == nblocks - 1 && write_final) {
            double a0 = atomicAdd(&acc[0], 0.0);
            double a1 = atomicAdd(&acc[1], 0.0);
            double a2 = atomicAdd(&acc[2], 0.0);
            Cf[(size_t)NBC * N_ENTC]     = (float)(a2 / (double)(NBC * HC));
            Cf[(size_t)NBC * N_ENTC + 1] = (float)((a0 - a1) /
                                                   ((double)NBC * (double)N_ENTC));
        }
    }
}

// ---------------- fused pre+aln (pipelined) ----------------
#define PREALN_LOAD(i, k0v, dst)                                                     \
    {                                                                                 \
        int idx = tid + (i) * 256;                                                    \
        int seg = idx & 3;                                                            \
        int gr = rowBase + lr[i];                                                     \
        int kc = (k0v) + seg * 8;                                                     \
        uint4 va = make_uint4(0, 0, 0, 0);                                            \
        if (lv[i]) {                                                                  \
            if ((k0v) < 128) {                                                        \
                va = *(const uint4*)(g_aggb + (size_t)gr * HC + kc);                  \
            } else if ((k0v) < 256) {                                                 \
                if (lm[i]) va = *(const uint4*)(g_entb + (size_t)gr * HC + kc - 128); \
            } else {                                                                  \
                if (!lm[i]) va = *(const uint4*)(g_entb + (size_t)gr * HC + kc - 256);\
            }                                                                         \
        }                                                                             \
        dst = va;                                                                     \
    }

__global__ __launch_bounds__(256)
void k_prealn(const float* __restrict__ bal, const int* __restrict__ deg, int M) {
    extern __shared__ __nv_bfloat16 sm[];
    __nv_bfloat16* As = sm;
    __nv_bfloat16* Bs = sm + BGM * SSTR;
    __nv_bfloat16* Xs = sm + 2 * BGM * SSTR;
    int tid = threadIdx.x, lane = tid & 31, wid = tid >> 5;
    int wm = wid & 3, wn = wid >> 2;
    int rowBase = blockIdx.x * BGM;
    int lr[2]; bool lv[2], lm[2];
    #pragma unroll
    for (int i = 0; i < 2; i++) {
        int idx = tid + i * 256;
        lr[i] = idx >> 2;
        int gr = rowBase + lr[i];
        lv[i] = gr < M;
        lm[i] = lv[i] && (deg[lv[i] ? gr : 0] > 0);
    }
    float c[2][8][4];
    #pragma unroll
    for (int i = 0; i < 2; i++)
        #pragma unroll
        for (int j = 0; j < 8; j++)
            #pragma unroll
            for (int q = 0; q < 4; q++) c[i][j][q] = 0.f;
    uint4 pa[2], pb[2];
    #pragma unroll
    for (int i = 0; i < 2; i++) {
        PREALN_LOAD(i, 0, pa[i])
        int idx = tid + i * 256;
        int r = idx >> 2, seg = idx & 3;
        pb[i] = *(const uint4*)(g_B3 + (size_t)r * KPRE + seg * 8);
    }
    for (int k0 = 0; k0 < KPRE; k0 += BGK) {
        #pragma unroll
        for (int i = 0; i < 2; i++) {
            int idx = tid + i * 256;
            int r = idx >> 2, seg = idx & 3;
            *(uint4*)(As + r * SSTR + seg * 8) = pa[i];
            *(uint4*)(Bs + r * SSTR + seg * 8) = pb[i];
        }
        __syncthreads();
        if (k0 + BGK < KPRE) {
            #pragma unroll
            for (int i = 0; i < 2; i++) {
                PREALN_LOAD(i, k0 + BGK, pa[i])
                int idx = tid + i * 256;
                int r = idx >> 2, seg = idx & 3;
                pb[i] = *(const uint4*)(g_B3 + (size_t)r * KPRE + k0 + BGK + seg * 8);
            }
        }
        MMA_STEP(As, Bs, SSTR, 0, 0, c)
        MMA_STEP(As, Bs, SSTR, 0, 16, c)
        __syncthreads();
    }
    #pragma unroll
    for (int mt = 0; mt < 2; mt++) {
        #pragma unroll
        for (int nt = 0; nt < 8; nt++) {
            int colL = wn * 64 + nt * 8 + ((lane & 3) << 1);
            #pragma unroll
            for (int half = 0; half < 2; half++) {
                int rowL = wm * 32 + mt * 16 + (lane >> 2) + half * 8;
                float v0 = c[mt][nt][half * 2 + 0];
                float v1 = c[mt][nt][half * 2 + 1];
                v0 = (v0 >= 0.f) ? v0 : v0 * SLOPE;
                v1 = (v1 >= 0.f) ? v1 : v1 * SLOPE;
                __nv_bfloat162 bv(__float2bfloat16(v0), __float2bfloat16(v1));
                *(__nv_bfloat162*)(Xs + rowL * XSTR + colL) = bv;
                int grow = rowBase + rowL;
                if (grow < M)
                    *(__nv_bfloat162*)(g_prebf + (size_t)grow * HC + colL) = bv;
            }
        }
    }
    __syncthreads();
    float c2[2][8][4];
    #pragma unroll
    for (int i = 0; i < 2; i++)
        #pragma unroll
        for (int j = 0; j < 8; j++)
            #pragma unroll
            for (int q = 0; q < 4; q++) c2[i][j][q] = 0.f;
    #pragma unroll
    for (int i = 0; i < 2; i++) {
        int idx = tid + i * 256;
        int r = idx >> 2, seg = idx & 3;
        pb[i] = *(const uint4*)(g_walb + (size_t)r * HC + seg * 8);
    }
    for (int k0 = 0; k0 < HC; k0 += BGK) {
        #pragma unroll
        for (int i = 0; i < 2; i++) {
            int idx = tid + i * 256;
            int r = idx >> 2, seg = idx & 3;
            *(uint4*)(Bs + r * SSTR + seg * 8) = pb[i];
        }
        __syncthreads();
        if (k0 + BGK < HC) {
            #pragma unroll
            for (int i = 0; i < 2; i++) {
                int idx = tid + i * 256;
                int r = idx >> 2, seg = idx & 3;
                pb[i] = *(const uint4*)(g_walb + (size_t)r * HC + k0 + BGK + seg * 8);
            }
        }
        MMA_STEP(Xs, Bs, XSTR, k0, 0, c2)
        MMA_STEP(Xs, Bs, XSTR, k0, 16, c2)
        __syncthreads();
    }
    #pragma unroll
    for (int mt = 0; mt < 2; mt++) {
        #pragma unroll
        for (int nt = 0; nt < 8; nt++) {
            int colL = wn * 64 + nt * 8 + ((lane & 3) << 1);
            float b0 = bal[colL], b1 = bal[colL + 1];
            #pragma unroll
            for (int half = 0; half < 2; half++) {
                int grow = rowBase + wm * 32 + mt * 16 + (lane >> 2) + half * 8;
                if (grow < M) {
                    __nv_bfloat162 bv(__float2bfloat16(c2[mt][nt][half * 2 + 0] + b0),
                                      __float2bfloat16(c2[mt][nt][half * 2 + 1] + b1));
                    *(__nv_bfloat162*)(g_alnbf + (size_t)grow * HC + colL) = bv;
                }
            }
        }
    }
}

// ---------------- fused softmax+rpath+giall (pipelined) ----------------
__global__ __launch_bounds__(256)
void k_rpgi(const float* __restrict__ part, const float* __restrict__ Amat,
            const float* __restrict__ bih, float* __restrict__ giall) {
    extern __shared__ __nv_bfloat16 sm[];
    __nv_bfloat16* As = sm;
    __nv_bfloat16* Bs = sm + BGM * SSTR;
    __nv_bfloat16* Xs = sm + 2 * BGM * SSTR;
    int tid = threadIdx.x, lane = tid & 31, wid = tid >> 5;
    int wm = wid & 3, wn = wid >> 2;
    int rowBase = blockIdx.x * BGM;
    uint4 pa[2], pb[2];
    if (blockIdx.x < 64) {
        for (int rr = wid; rr < BGM; rr += 8) {
            int grow = rowBase + rr;
            int t = grow >> 10, b = grow & 1023;
            const float* prow = part + (size_t)b * (NTC * NRELC) + t * NRELC;
            const float* arow = Amat + (size_t)b * NRELC;
            float xv[15];
            float m = -3.402823e38f;
            #pragma unroll
            for (int i = 0; i < 15; i++) {
                int cc = lane + i * 32;
                float x = -3.402823e38f;
                if (cc < NRELC) {
                    float val = prow[cc] * arow[cc];
                    x = (val == 0.f) ? -1e9f : val;
                }
                xv[i] = x;
                m = fmaxf(m, x);
            }
            #pragma unroll
            for (int o = 16; o > 0; o >>= 1) m = fmaxf(m, __shfl_xor_sync(0xffffffffu, m, o));
            float s = 0.f;
            float ev[15];
            #pragma unroll
            for (int i = 0; i < 15; i++) {
                int cc = lane + i * 32;
                float e = (cc < NRELC) ? __expf(xv[i] - m) : 0.f;
                ev[i] = e;
                s += e;
            }
            #pragma unroll
            for (int o = 16; o > 0; o >>= 1) s += __shfl_xor_sync(0xffffffffu, s, o);
            float inv = 1.f / s;
            __nv_bfloat16* orow = g_attnb + (size_t)grow * KPAD;
            #pragma unroll
            for (int i = 0; i < 15; i++) {
                int cc = lane + i * 32;
                if (cc < NRELC) orow[cc] = __float2bfloat16(ev[i] * inv);
            }
        }
        __syncthreads();
        float c[2][8][4];
        #pragma unroll
        for (int i = 0; i < 2; i++)
            #pragma unroll
            for (int j = 0; j < 8; j++)
                #pragma unroll
                for (int q = 0; q < 4; q++) c[i][j][q] = 0.f;
        #pragma unroll
        for (int i = 0; i < 2; i++) {
            int idx = tid + i * 256;
            int r = idx >> 2, seg = idx & 3;
            pa[i] = *(const uint4*)(g_attnb + (size_t)(rowBase + r) * KPAD + seg * 8);
            pb[i] = *(const uint4*)(g_mrelTb + (size_t)r * KPAD + seg * 8);
        }
        for (int k0 = 0; k0 < KPAD; k0 += BGK) {
            #pragma unroll
            for (int i = 0; i < 2; i++) {
                int idx = tid + i * 256;
                int r = idx >> 2, seg = idx & 3;
                *(uint4*)(As + r * SSTR + seg * 8) = pa[i];
                *(uint4*)(Bs + r * SSTR + seg * 8) = pb[i];
            }
            __syncthreads();
            if (k0 + BGK < KPAD) {
                #pragma unroll
                for (int i = 0; i < 2; i++) {
                    int idx = tid + i * 256;
                    int r = idx >> 2, seg = idx & 3;
                    pa[i] = *(const uint4*)(g_attnb + (size_t)(rowBase + r) * KPAD + k0 + BGK + seg * 8);
                    pb[i] = *(const uint4*)(g_mrelTb + (size_t)r * KPAD + k0 + BGK + seg * 8);
                }
            }
            MMA_STEP(As, Bs, SSTR, 0, 0, c)
            MMA_STEP(As, Bs, SSTR, 0, 16, c)
            __syncthreads();
        }
        #pragma unroll
        for (int mt = 0; mt < 2; mt++)
            #pragma unroll
            for (int nt = 0; nt < 8; nt++) {
                int colL = wn * 64 + nt * 8 + ((lane & 3) << 1);
                #pragma unroll
                for (int half = 0; half < 2; half++) {
                    int rowL = wm * 32 + mt * 16 + (lane >> 2) + half * 8;
                    __nv_bfloat162 bv(__float2bfloat16(c[mt][nt][half * 2 + 0]),
                                      __float2bfloat16(c[mt][nt][half * 2 + 1]));
                    *(__nv_bfloat162*)(Xs + rowL * XSTR + colL) = bv;
                }
            }
    } else {
        for (int i = tid; i < BGM * (HC / 8); i += 256) {
            int r = i / (HC / 8), seg = i % (HC / 8);
            *(uint4*)(Xs + r * XSTR + seg * 8) =
                *(const uint4*)(g_Xb + (size_t)(rowBase + r) * HC + seg * 8);
        }
    }
    __syncthreads();
    for (int nb = 0; nb < 3; nb++) {
        float c2[2][8][4];
        #pragma unroll
        for (int i = 0; i < 2; i++)
            #pragma unroll
            for (int j = 0; j < 8; j++)
                #pragma unroll
                for (int q = 0; q < 4; q++) c2[i][j][q] = 0.f;
        #pragma unroll
        for (int i = 0; i < 2; i++) {
            int idx = tid + i * 256;
            int r = idx >> 2, seg = idx & 3;
            pb[i] = *(const uint4*)(g_wihb + (size_t)(nb * 128 + r) * HC + seg * 8);
        }
        for (int k0 = 0; k0 < HC; k0 += BGK) {
            #pragma unroll
            for (int i = 0; i < 2; i++) {
                int idx = tid + i * 256;
                int r = idx >> 2, seg = idx & 3;
                *(uint4*)(Bs + r * SSTR + seg * 8) = pb[i];
            }
            __syncthreads();
            if (k0 + BGK < HC) {
                #pragma unroll
                for (int i = 0; i < 2; i++) {
                    int idx = tid + i * 256;
                    int r = idx >> 2, seg = idx & 3;
                    pb[i] = *(const uint4*)(g_wihb + (size_t)(nb * 128 + r) * HC + k0 + BGK + seg * 8);
                }
            }
            MMA_STEP(Xs, Bs, XSTR, k0, 0, c2)
            MMA_STEP(Xs, Bs, XSTR, k0, 16, c2)
            __syncthreads();
        }
        #pragma unroll
        for (int mt = 0; mt < 2; mt++)
            #pragma unroll
            for (int nt = 0; nt < 8; nt++) {
                int colL = wn * 64 + nt * 8 + ((lane & 3) << 1);
                int col = nb * 128 + colL;
                float b0 = bih[col], b1 = bih[col + 1];
                #pragma unroll
                for (int half = 0; half < 2; half++) {
                    int row = rowBase + wm * 32 + mt * 16 + (lane >> 2) + half * 8;
                    *(float2*)(giall + (size_t)row * H3C + col) =
                        make_float2(c2[mt][nt][half * 2 + 0] + b0,
                                    c2[mt][nt][half * 2 + 1] + b1);
                }
            }
    }
}

// ---------------- fused mapped_rel ----------------
__global__ __launch_bounds__(256)
void k_mrel(const float* __restrict__ rel, const float* __restrict__ Wm1T,
            const float* __restrict__ Wm2T, const float* __restrict__ bm1,
            const float* __restrict__ bm2, float* __restrict__ mrel,
            float* __restrict__ mrelT) {
    __shared__ float rels[10][128];
    __shared__ float p1s[10][256];
    int tid = threadIdx.x;
    int r0 = blockIdx.x * 10;
    for (int i = tid; i < 10 * 128; i += 256)
        rels[i >> 7][i & 127] = rel[(r0 + (i >> 7)) * 128 + (i & 127)];
    __syncthreads();
    {
        int j2 = tid;
        float a[10];
        #pragma unroll
        for (int r = 0; r < 10; r++) a[r] = 0.f;
        for (int k = 0; k < 128; k++) {
            float w = Wm1T[k * 256 + j2];
            #pragma unroll
            for (int r = 0; r < 10; r++) a[r] = fmaf(rels[r][k], w, a[r]);
        }
        float b = bm1[j2];
        #pragma unroll
        for (int r = 0; r < 10; r++) p1s[r][j2] = a[r] + b;
    }
    __syncthreads();
    {
        int j = tid & 127, half = tid >> 7;
        float a[5];
        #pragma unroll
        for (int r = 0; r < 5; r++) a[r] = 0.f;
        for (int k = 0; k < 256; k++) {
            float w = Wm2T[k * 128 + j];
            #pragma unroll
            for (int r = 0; r < 5; r++) a[r] = fmaf(p1s[half * 5 + r][k], w, a[r]);
        }
        float b = bm2[j];
        #pragma unroll
        for (int r = 0; r < 5; r++) {
            int row = r0 + half * 5 + r;
            float v = a[r] + b;
            mrel[row * 128 + j] = v;
            mrelT[j * MT_STR + row] = v;
            g_mrelTb[j * KPAD + row] = __float2bfloat16(v);
        }
    }
}

__global__ __launch_bounds__(128)
void k_qa_amat(const float* __restrict__ mrel, const int* __restrict__ trip,
               const float* __restrict__ WatT, const float* __restrict__ bat,
               const float* __restrict__ mrelT, float* __restrict__ qrel,
               float* __restrict__ Amat) {
    __shared__ float q[4][128];
    __shared__ float qa[4][128];
    int j = threadIdx.x;
    int r0 = blockIdx.x * 4;
    #pragma unroll
    for (int r = 0; r < 4; r++) {
        float v = mrel[(size_t)trip[(r0 + r) * 3 + 1] * HC + j];
        q[r][j] = v;
        qrel[(r0 + r) * 128 + j] = v;
        g_Xb[(size_t)(NTC * NBC + r0 + r) * HC + j] = __float2bfloat16(v);
    }
    __syncthreads();
    {
        float a[4] = {0.f, 0.f, 0.f, 0.f};
        for (int k = 0; k < 128; k++) {
            float w = WatT[k * 128 + j];
            #pragma unroll
            for (int r = 0; r < 4; r++) a[r] = fmaf(q[r][k], w, a[r]);
        }
        float b = bat[j];
        #pragma unroll
        for (int r = 0; r < 4; r++) qa[r][j] = a[r] + b;
    }
    __syncthreads();
    float a[4][4];
    #pragma unroll
    for (int r = 0; r < 4; r++)
        #pragma unroll
        for (int t = 0; t < 4; t++) a[r][t] = 0.f;
    for (int k = 0; k < 128; k++) {
        float m0 = mrelT[k * MT_STR + j];
        float m1 = mrelT[k * MT_STR + j + 128];
        float m2 = mrelT[k * MT_STR + j + 256];
        float m3 = mrelT[k * MT_STR + j + 384];
        #pragma unroll
        for (int r = 0; r < 4; r++) {
            float qv = qa[r][k];
            a[r][0] = fmaf(qv, m0, a[r][0]);
            a[r][1] = fmaf(qv, m1, a[r][1]);
            a[r][2] = fmaf(qv, m2, a[r][2]);
            a[r][3] = fmaf(qv, m3, a[r][3]);
        }
    }
    #pragma unroll
    for (int r = 0; r < 4; r++)
        #pragma unroll
        for (int t = 0; t < 4; t++) {
            int n = j + t * 128;
            if (n < NRELC) Amat[(size_t)(r0 + r) * NRELC + n] = a[r][t];
        }
}

// ---------------- mega GRU kernel ----------------
__global__ __launch_bounds__(384)
void k_gru_all(const float* __restrict__ giall, const float* __restrict__ whhT,
               const float* __restrict__ bhh, const float* __restrict__ qrel,
               const float* __restrict__ Wh1T, const float* __restrict__ Wh2T,
               const float* __restrict__ bh1, const float* __restrict__ bh2,
               const int* __restrict__ trip, const float* __restrict__ WalT,
               const float* __restrict__ bal, double* acc) {
    extern __shared__ float swhh[];
    __shared__ float hs[8][128];
    __shared__ float asg[8][384];
    __shared__ float qs[8][128];
    __shared__ float ps[8][128];
    int tid = threadIdx.x;
    int j = tid & 127;
    int g = tid >> 7;
    int r0 = blockIdx.x * 8;

    for (int i = tid; i < HC * H3C; i += 384) swhh[i] = whhT[i];
    for (int i = tid; i < 8 * 128; i += 384) hs[i >> 7][i & 127] = 0.f;
    __syncthreads();

    for (int t = 0; t < NTC; t++) {
        {
            float a[8];
            #pragma unroll
            for (int r = 0; r < 8; r++) a[r] = 0.f;
            for (int k = 0; k < 128; k++) {
                float w = swhh[k * H3C + tid];
                #pragma unroll
                for (int r = 0; r < 8; r++) a[r] = fmaf(hs[r][k], w, a[r]);
            }
            #pragma unroll
            for (int r = 0; r < 8; r++) asg[r][tid] = a[r];
        }
        __syncthreads();
        if (tid < 128) {
            float br = bhh[j], bz = bhh[128 + j], bn = bhh[256 + j];
            const float* gi = giall + (size_t)t * NBC * H3C;
            #pragma unroll
            for (int r = 0; r < 8; r++) {
                size_t gx = (size_t)(r0 + r) * H3C;
                float rr = sigm(gi[gx + j] + asg[r][j] + br);
                float zz = sigm(gi[gx + 128 + j] + asg[r][128 + j] + bz);
                float nn = tanhf(gi[gx + 256 + j] + rr * (asg[r][256 + j] + bn));
                hs[r][j] = (1.f - zz) * nn + zz * hs[r][j];
            }
        }
        __syncthreads();
    }

    for (int i = tid; i < 8 * 128; i += 384)
        qs[i >> 7][i & 127] = qrel[(r0 + (i >> 7)) * 128 + (i & 127)];
    __syncthreads();

    for (int r = g; r < 8; r += 3) {
        float a = 0.f;
        for (int k = 0; k < 128; k++) a = fmaf(qs[r][k], Wh1T[k * 128 + j], a);
        ps[r][j] = a + bh1[j];
    }
    __syncthreads();
    float predv[3];
    int nmine = 0;
    for (int r = g; r < 8; r += 3) {
        float a = 0.f;
        for (int k = 0; k < 128; k++) a = fmaf(ps[r][k], Wh2T[k * 128 + j], a);
        predv[nmine++] = 0.1f * (a + bh2[j]) + qs[r][j];
    }
    __syncthreads();
    {
        int m = 0;
        for (int r = g; r < 8; r += 3) ps[r][j] = predv[m++];
    }
    __syncthreads();
    {
        float msum = 0.f;
        for (int r = g; r < 8; r += 3) {
            float d = ps[r][j] - hs[r][j];
            msum += d * d;
        }
        float bsum = blockReduceSum(msum);
        if (tid == 0) atomicAdd(&acc[2], (double)bsum);
    }
    __syncthreads();
    {
        float a[8];
        #pragma unroll
        for (int r = 0; r < 8; r++) a[r] = 0.f;
        for (int k = 0; k < 128; k++) {
            float w = swhh[k * H3C + tid];
            #pragma unroll
            for (int r = 0; r < 8; r++) a[r] = fmaf(ps[r][k], w, a[r]);
        }
        #pragma unroll
        for (int r = 0; r < 8; r++) asg[r][tid] = a[r];
    }
    __syncthreads();
    if (tid < 128) {
        float br = bhh[j], bz = bhh[128 + j], bn = bhh[256 + j];
        const float* gi = giall + (size_t)NTC * NBC * H3C;
        #pragma unroll
        for (int r = 0; r < 8; r++) {
            size_t gx = (size_t)(r0 + r) * H3C;
            float rr = sigm(gi[gx + j] + asg[r][j] + br);
            float zz = sigm(gi[gx + 128 + j] + asg[r][128 + j] + bz);
            float nn = tanhf(gi[gx + 256 + j] + rr * (asg[r][256 + j] + bn));
            hs[r][j] = (1.f - zz) * nn + zz * ps[r][j];
        }
    }
    __syncthreads();
    for (int i = tid; i < 8 * 128; i += 384) {
        int r = i >> 7, c = i & 127;
        int row = trip[(r0 + r) * 3 + 0];
        qs[r][c] = __bfloat162float(g_prebf[(size_t)row * HC + c]);
    }
    __syncthreads();
    for (int r = g; r < 8; r += 3) {
        float a = 0.f;
        for (int k = 0; k < 128; k++) a = fmaf(qs[r][k], WalT[k * 128 + j], a);
        float v = (a + bal[j]) * hs[r][j];
        g_svecb[(r0 + r) * 128 + j] = __float2bfloat16(v);
    }
}

// ---------------- host ----------------
extern "C" void kernel_launch(void* const* d_in, const int* in_sizes, int n_in,
                              void* d_out, int out_size) {
    const float* ent  = (const float*)d_in[0];
    const float* rel  = (const float*)d_in[1];
    const float* Wn   = (const float*)d_in[2];
    const float* Wl   = (const float*)d_in[3];
    const float* Wev  = (const float*)d_in[4];
    const float* wih  = (const float*)d_in[5];
    const float* whh  = (const float*)d_in[6];
    const float* bih  = (const float*)d_in[7];
    const float* bhh  = (const float*)d_in[8];
    const float* Wm1  = (const float*)d_in[9];
    const float* bm1  = (const float*)d_in[10];
    const float* Wm2  = (const float*)d_in[11];
    const float* bm2  = (const float*)d_in[12];
    const float* Wh1  = (const float*)d_in[13];
    const float* bh1  = (const float*)d_in[14];
    const float* Wh2  = (const float*)d_in[15];
    const float* bh2  = (const float*)d_in[16];
    const float* Wal  = (const float*)d_in[17];
    const float* bal  = (const float*)d_in[18];
    const float* Wat  = (const float*)d_in[19];
    const float* bat  = (const float*)d_in[20];
    const float* part = (const float*)d_in[21];
    const int* esrc = (const int*)d_in[22];
    const int* edst = (const int*)d_in[23];
    const int* etyp = (const int*)d_in[24];
    const int* trip = (const int*)d_in[25];
    float* out = (float*)d_out;

    void* basep = nullptr;
    cudaGetSymbolAddress(&basep, d_buf);
    float* F = (float*)basep;
    __nv_bfloat16 *pSvecb, *pAlnb;
    { void* p; cudaGetSymbolAddress(&p, g_svecb); pSvecb = (__nv_bfloat16*)p; }
    { void* p; cudaGetSymbolAddress(&p, g_alnbf); pAlnb  = (__nv_bfloat16*)p; }

    float* mrel   = F + O_MREL;
    float* mrelT  = F + O_MRELT;
    float* qrel   = F + O_QREL;
    float* Amat   = F + O_AMAT;
    float* giall  = F + O_GIALL;
    float* whhT   = F + O_WHHT;
    float* Wh1T   = F + O_WH1T;
    float* Wh2T   = F + O_WH2T;
    float* WatT   = F + O_WATT;
    float* WalT   = F + O_WALT;
    float* Wm1T   = F + O_WM1T;
    float* Wm2T   = F + O_WM2T;
    double* acc   = (double*)(F + O_ACC);
    int* deg      = (int*)(F + O_INT);
    int* rowptr   = deg + N_ENTC;
    int* cursor   = rowptr + N_ENTC + 1;
    int* csr      = cursor + N_ENTC;
    int* bsums    = csr + NEC;
    int* done     = bsums + 32;

    const int FUSED_SMEM = (2 * BGM * SSTR + BGM * XSTR) * 2;  // 55296 B
    const int GRU_SMEM = HC * H3C * 4;                          // 196608 B
    static bool s_init = false;
    static cudaStream_t sB = 0;
    static cudaEvent_t evF = 0, evB = 0;
    if (!s_init) {
        cudaFuncSetAttribute(k_prealn, cudaFuncAttributeMaxDynamicSharedMemorySize, FUSED_SMEM);
        cudaFuncSetAttribute(k_rpgi,   cudaFuncAttributeMaxDynamicSharedMemorySize, FUSED_SMEM);
        cudaFuncSetAttribute(k_gru_all, cudaFuncAttributeMaxDynamicSharedMemorySize, GRU_SMEM);
        cudaStreamCreateWithFlags(&sB, cudaStreamNonBlocking);
        cudaEventCreateWithFlags(&evF, cudaEventDisableTiming);
        cudaEventCreateWithFlags(&evB, cudaEventDisableTiming);
        s_init = true;
    }

    k_init<<<640, 256>>>(Wn, Wl, Wev, wih, whh, Wal, Wh1, Wh2, Wat, Wm1, Wm2, rel,
                         deg, cursor, acc, done, F);
    cudaEventRecord(evF, 0);
    cudaStreamWaitEvent(sB, evF, 0);

    // ---- chain B (relation path) on sB ----
    k_mrel<<<46, 256, 0, sB>>>(rel, Wm1T, Wm2T, bm1, bm2, mrel, mrelT);
    k_qa_amat<<<256, 128, 0, sB>>>(mrel, trip, WatT, bat, mrelT, qrel, Amat);
    k_rpgi<<<(NTC + 1) * NBC / BGM, 256, FUSED_SMEM, sB>>>(part, Amat, bih, giall);
    cudaEventRecord(evB, sB);

    // ---- chain A (entity path) on default stream ----
    k_count_entcvt<<<(N_ENTC * HC + 255) / 256, 256>>>(edst, deg, ent);
    k_scanA<<<(N_ENTC + 1023) / 1024, 1024>>>(deg, rowptr, bsums);
    k_scanB<<<1, 1024>>>(rowptr, bsums, (N_ENTC + 1023) / 1024);
    k_fill<<<(NEC + 255) / 256, 256>>>(edst, esrc, etyp, rowptr, cursor, csr);
    k_aggregate<<<N_ENTC, 64>>>(rowptr, csr);
    k_prealn<<<(N_ENTC + BGM - 1) / BGM, 256, FUSED_SMEM>>>(bal, deg, N_ENTC);

    // ---- join ----
    cudaStreamWaitEvent(0, evB, 0);
    k_gru_all<<<128, 384, GRU_SMEM>>>(giall, whhT, bhh, qrel, Wh1T, Wh2T, bh1, bh2,
                                      trip, WalT, bal, acc);
    {
        dim3 g((N_ENTC + BGN - 1) / BGN, NBC / BGM);
        int nblocks = g.x * g.y;
        int wf = (out_size >= NBC * N_ENTC + 2) ? 1 : 0;
        k_score<<<g, 256>>>(pSvecb, pAlnb, out, trip, acc, done, nblocks, wf,
                            NBC, N_ENTC);
    }
}